// round 4
// baseline (speedup 1.0000x reference)
#include <cuda_runtime.h>
#include <cstdint>

#define B_   1024
#define T_   200
#define H_   128
#define G_   384
#define ROWS 8
#define NCTA 128
#define NTHR 384

typedef unsigned long long ull;

// Weight scratch: 4 mv matrices [m][k4][j]float4 + h2o [k4][oi]float4
#define NW4  (4*32*384)            // 49152 float4
#define HO4  NW4
__device__ float4 g_W4[NW4 + 32*128];

// ---- packed f32x2 helpers ----
__device__ __forceinline__ ull pack2(float a, float b) {
    ull r; asm("mov.b64 %0,{%1,%2};" : "=l"(r) : "f"(a), "f"(b)); return r;
}
__device__ __forceinline__ void fma2(ull& c, ull a, ull b) {
    asm("fma.rn.f32x2 %0,%1,%2,%0;" : "+l"(c) : "l"(a), "l"(b));
}
__device__ __forceinline__ float2 unpack2(ull v) {
    float lo, hi; asm("mov.b64 {%0,%1},%2;" : "=f"(lo), "=f"(hi) : "l"(v));
    return make_float2(lo, hi);
}
__device__ __forceinline__ void ldg2u64(const void* p, ull& a, ull& b) {
    asm("ld.global.nc.v2.u64 {%0,%1},[%2];" : "=l"(a), "=l"(b) : "l"(p));
}

__device__ __forceinline__ float sigmoid_fast(float x) {
    return 1.0f / (1.0f + __expf(-x));
}
__device__ __forceinline__ float tanh_fast(float x) {
    float ax = fabsf(x);
    float e  = __expf(-2.0f * ax);
    float t  = __fdividef(1.0f - e, 1.0f + e);
    return copysignf(t, x);
}

// One-time weight re-layout.
// m: 0=Wih l0, 1=Whh l0, 2=Wih l1, 3=Whh l1
__global__ void prep_kernel(const float* __restrict__ Wih,
                            const float* __restrict__ Whh,
                            const float* __restrict__ h2o_w)
{
    int idx = blockIdx.x * blockDim.x + threadIdx.x;
    if (idx < NW4) {
        int j    = idx % G_;
        int rest = idx / G_;
        int k4   = rest % 32;
        int m    = rest / 32;
        int l    = m >> 1;
        const float* src = ((m & 1) == 0) ? Wih : Whh;
        const float* row = src + ((size_t)l * G_ + j) * H_ + 4 * k4;
        g_W4[idx] = make_float4(row[0], row[1], row[2], row[3]);
    } else if (idx < NW4 + 32 * 128) {
        int i2 = idx - NW4;
        int oi = i2 % H_;
        int k4 = i2 / H_;
        const float* row = h2o_w + oi * H_ + 4 * k4;
        g_W4[idx] = make_float4(row[0], row[1], row[2], row[3]);
    }
}

// Activation pair buffers: ull element = (val_k, val_{k+1}) for one row.
// Index: [k2*10 + r], k2 in 0..63, r in 0..7 (stride 10 for bank spread).
#define SU 10
#define NPBUF (64*SU)
// float-view index for unit u (0..127), row r:
#define PIDX(u, r) (((u) >> 1) * (2*SU) + 2*(r) + ((u) & 1))

// Dual matvec: gi[r] = bi + Wih[j,:]·x[r,:] ; gh[r] = bh + Whh[j,:]·h[r,:]
__device__ __forceinline__ void dualmv(const ull* __restrict__ xp,
                                       const ull* __restrict__ hp,
                                       const float4* __restrict__ wi,
                                       const float4* __restrict__ wh,
                                       float bi, float bh,
                                       float* gi, float* gh)
{
    ull ai[ROWS], ah[ROWS];
#pragma unroll
    for (int r = 0; r < ROWS; r++) { ai[r] = pack2(bi, 0.0f); ah[r] = pack2(bh, 0.0f); }
#pragma unroll 4
    for (int k4 = 0; k4 < 32; k4++) {
        ull wiA, wiB, whA, whB;
        ldg2u64(wi + k4 * G_, wiA, wiB);      // (w_k0,w_k1),(w_k2,w_k3) — coalesced LDG.128
        ldg2u64(wh + k4 * G_, whA, whB);
        const ull* xa = xp + (2 * k4) * SU;
        const ull* ha = hp + (2 * k4) * SU;
#pragma unroll
        for (int p = 0; p < 4; p++) {
            ulonglong2 xv = *(const ulonglong2*)(xa + 2 * p);
            fma2(ai[2*p],   wiA, xv.x);
            fma2(ai[2*p+1], wiA, xv.y);
        }
#pragma unroll
        for (int p = 0; p < 4; p++) {
            ulonglong2 xv = *(const ulonglong2*)(xa + SU + 2 * p);
            fma2(ai[2*p],   wiB, xv.x);
            fma2(ai[2*p+1], wiB, xv.y);
        }
#pragma unroll
        for (int p = 0; p < 4; p++) {
            ulonglong2 hv = *(const ulonglong2*)(ha + 2 * p);
            fma2(ah[2*p],   whA, hv.x);
            fma2(ah[2*p+1], whA, hv.y);
        }
#pragma unroll
        for (int p = 0; p < 4; p++) {
            ulonglong2 hv = *(const ulonglong2*)(ha + SU + 2 * p);
            fma2(ah[2*p],   whB, hv.x);
            fma2(ah[2*p+1], whB, hv.y);
        }
    }
#pragma unroll
    for (int r = 0; r < ROWS; r++) {
        float2 a = unpack2(ai[r]); gi[r] = a.x + a.y;
        float2 b = unpack2(ah[r]); gh[r] = b.x + b.y;
    }
}

__global__ void __launch_bounds__(NTHR, 1)
gru_kernel(const int* __restrict__ il,
           const float* __restrict__ mask,
           const float* __restrict__ emb,
           const float* __restrict__ bih,
           const float* __restrict__ bhh,
           const float* __restrict__ h2o_b,
           float* __restrict__ out1,     // (B,199,H)
           float* __restrict__ out4)     // (B,200,2H)
{
    __shared__ __align__(16) ull xp [NPBUF];   // x input / layer1 output (pairs)
    __shared__ __align__(16) ull bp [NPBUF];   // layer0 output (pairs)
    __shared__ __align__(16) ull h0p[NPBUF];
    __shared__ __align__(16) ull h1p[NPBUF];
    __shared__ __align__(16) float sg [ROWS * G_];
    __shared__ __align__(16) float shn[ROWS * H_];
    __shared__ float skeep[ROWS];

    const int j  = threadIdx.x;
    const int b0 = blockIdx.x * ROWS;

    for (int i = j; i < NPBUF; i += NTHR) { h0p[i] = 0ull; h1p[i] = 0ull; }

    const float bi0 = bih[j],      bh0 = bhh[j];
    const float bi1 = bih[G_ + j], bh1 = bhh[G_ + j];
    const float4* wi0 = g_W4 + (0*32)*G_ + j;
    const float4* wh0 = g_W4 + (1*32)*G_ + j;
    const float4* wi1 = g_W4 + (2*32)*G_ + j;
    const float4* wh1 = g_W4 + (3*32)*G_ + j;

    const int   oi   = j & (H_ - 1);
    const int   half = (j >> 7) & 1;
    const float ob   = (j < 256) ? h2o_b[oi] : 0.0f;
    const float4* wo = g_W4 + HO4 + oi;

    const int lr  = j & 7;       // loader: row
    const int lk4 = j >> 3;      // loader: k-quad

    float* xpf  = (float*)xp;
    float* bpf  = (float*)bp;
    float* h0pf = (float*)h0p;
    float* h1pf = (float*)h1p;

    __syncthreads();

    for (int t = 0; t < T_; t++) {
        // ---- load x into pair layout + write out4 low half ----
        if (j < 256) {
            int tok = il[(b0 + lr) * T_ + t];
            float4 v = __ldg((const float4*)emb + (size_t)tok * 32 + lk4);
            xpf[PIDX(4*lk4 + 0, lr)] = v.x;
            xpf[PIDX(4*lk4 + 1, lr)] = v.y;
            xpf[PIDX(4*lk4 + 2, lr)] = v.z;
            xpf[PIDX(4*lk4 + 3, lr)] = v.w;
            ((float4*)(out4 + ((size_t)(b0 + lr) * T_ + t) * 256))[lk4] = v;
        }
        if (j < ROWS) {
            float m = mask[(b0 + j) * T_ + t];
            skeep[j] = (m != 0.0f) ? 1.0f : 0.0f;
        }
        __syncthreads();

        // ================= layer 0 =================
        {
            float gi[ROWS], gh[ROWS];
            dualmv(xp, h0p, wi0, wh0, bi0, bh0, gi, gh);
            if (j < 2 * H_) {
#pragma unroll
                for (int r = 0; r < ROWS; r++)
                    sg[r * G_ + j] = sigmoid_fast(gi[r] + gh[r]);
            } else {
#pragma unroll
                for (int r = 0; r < ROWS; r++) {
                    sg [r * G_ + j]         = gi[r];
                    shn[r * H_ + (j - 256)] = gh[r];
                }
            }
            __syncthreads();
            if (j < H_) {
#pragma unroll
                for (int r = 0; r < ROWS; r++) {
                    float rv  = sg[r * G_ + j];
                    float zv  = sg[r * G_ + H_ + j];
                    float inn = sg[r * G_ + 2 * H_ + j];
                    float hn  = shn[r * H_ + j];
                    float nv  = tanh_fast(fmaf(rv, hn, inn));
                    float ho  = h0pf[PIDX(j, r)];
                    float hw  = fmaf(zv, ho - nv, nv);
                    bpf [PIDX(j, r)] = hw;
                    h0pf[PIDX(j, r)] = hw * skeep[r];
                }
            }
            __syncthreads();
        }

        // ================= layer 1 =================
        {
            float gi[ROWS], gh[ROWS];
            dualmv(bp, h1p, wi1, wh1, bi1, bh1, gi, gh);
            if (j < 2 * H_) {
#pragma unroll
                for (int r = 0; r < ROWS; r++)
                    sg[r * G_ + j] = sigmoid_fast(gi[r] + gh[r]);
            } else {
#pragma unroll
                for (int r = 0; r < ROWS; r++) {
                    sg [r * G_ + j]         = gi[r];
                    shn[r * H_ + (j - 256)] = gh[r];
                }
            }
            __syncthreads();
            if (j < H_) {
#pragma unroll
                for (int r = 0; r < ROWS; r++) {
                    float rv  = sg[r * G_ + j];
                    float zv  = sg[r * G_ + H_ + j];
                    float inn = sg[r * G_ + 2 * H_ + j];
                    float hn  = shn[r * H_ + j];
                    float nv  = tanh_fast(fmaf(rv, hn, inn));
                    float ho  = h1pf[PIDX(j, r)];
                    float hw  = fmaf(zv, ho - nv, nv);
                    xpf [PIDX(j, r)] = hw;          // h2o input (unmasked)
                    h1pf[PIDX(j, r)] = hw * skeep[r];
                }
            }
            __syncthreads();
        }

        // ================= h2o: out = tanh(h1 @ h2o_w.T + b) =================
        if (j < 256) {
            ull acc[4];
#pragma unroll
            for (int p = 0; p < 4; p++) acc[p] = pack2(ob, 0.0f);
            const int r0 = 4 * half;
#pragma unroll 4
            for (int k4 = 0; k4 < 32; k4++) {
                ull wA, wB;
                ldg2u64(wo + k4 * H_, wA, wB);
                const ull* xa = xp + (2 * k4) * SU + r0;
                ulonglong2 x0 = *(const ulonglong2*)(xa);
                ulonglong2 x1 = *(const ulonglong2*)(xa + 2);
                fma2(acc[0], wA, x0.x); fma2(acc[1], wA, x0.y);
                fma2(acc[2], wA, x1.x); fma2(acc[3], wA, x1.y);
                ulonglong2 y0 = *(const ulonglong2*)(xa + SU);
                ulonglong2 y1 = *(const ulonglong2*)(xa + SU + 2);
                fma2(acc[0], wB, y0.x); fma2(acc[1], wB, y0.y);
                fma2(acc[2], wB, y1.x); fma2(acc[3], wB, y1.y);
            }
#pragma unroll
            for (int rr = 0; rr < 4; rr++) {
                float2 s = unpack2(acc[rr]);
                float o  = tanh_fast(s.x + s.y);
                size_t gb = (size_t)(b0 + r0 + rr);
                out4[(gb * T_ + t) * 256 + H_ + oi] = o;
                if (t < T_ - 1)
                    out1[(gb * (T_ - 1) + t) * H_ + oi] = o;
            }
        }
        __syncthreads();   // protect xp before next step's loader
    }
}

// out2[b,t,:] = emb[il[b,t+1]];  out3[b,t,:] = emb[neg[b,t]]
__global__ void gather_kernel(const int* __restrict__ il,
                              const int* __restrict__ neg,
                              const float4* __restrict__ emb4,
                              float4* __restrict__ out2,
                              float4* __restrict__ out3)
{
    int idx = blockIdx.x * blockDim.x + threadIdx.x;
    const int n4 = B_ * (T_ - 1) * (H_ / 4);
    if (idx >= n4) return;
    int k4 = idx & 31;
    int bt = idx >> 5;
    int b  = bt / (T_ - 1);
    int t  = bt - b * (T_ - 1);
    int p  = il [b * T_ + t + 1];
    int q  = neg[b * T_ + t];
    out2[idx] = __ldg(emb4 + (size_t)p * 32 + k4);
    out3[idx] = __ldg(emb4 + (size_t)q * 32 + k4);
}

extern "C" void kernel_launch(void* const* d_in, const int* in_sizes, int n_in,
                              void* d_out, int out_size)
{
    const int*   il    = (const int*)  d_in[0];
    const float* mask  = (const float*)d_in[1];
    const int*   neg   = (const int*)  d_in[2];
    const float* emb   = (const float*)d_in[3];
    const float* Wih   = (const float*)d_in[4];
    const float* Whh   = (const float*)d_in[5];
    const float* bih   = (const float*)d_in[6];
    const float* bhh   = (const float*)d_in[7];
    const float* h2o_w = (const float*)d_in[8];
    const float* h2o_b = (const float*)d_in[9];

    float* out  = (float*)d_out;
    float* out1 = out;
    float* out2 = out1 + (size_t)B_ * (T_ - 1) * H_;
    float* out3 = out2 + (size_t)B_ * (T_ - 1) * H_;
    float* out4 = out3 + (size_t)B_ * (T_ - 1) * H_;

    const int nprep = NW4 + 32 * 128;
    prep_kernel<<<(nprep + 255) / 256, 256>>>(Wih, Whh, h2o_w);

    const int n4 = B_ * (T_ - 1) * (H_ / 4);
    gather_kernel<<<(n4 + 255) / 256, 256>>>(il, neg, (const float4*)emb,
                                             (float4*)out2, (float4*)out3);

    gru_kernel<<<NCTA, NTHR>>>(il, mask, emb, bih, bhh, h2o_b, out1, out4);
}

// round 5
// speedup vs baseline: 1.0924x; 1.0924x over previous
#include <cuda_runtime.h>
#include <cuda_fp16.h>
#include <cstdint>

#define B_   1024
#define T_   200
#define H_   128
#define G_   384
#define ROWS 8
#define NCTA 128
#define NTHR 384

typedef unsigned long long ull;

// fp16 weight scratch: 4 mv matrices [m][k4][j] (ull = 4 halves) + h2o [k4][oi]
#define NWH (4*32*384)
#define HOH NWH
__device__ ull g_Wh[NWH + 32*128];

// ---- packed f32x2 helpers ----
__device__ __forceinline__ ull pack2(float a, float b) {
    ull r; asm("mov.b64 %0,{%1,%2};" : "=l"(r) : "f"(a), "f"(b)); return r;
}
__device__ __forceinline__ void fma2(ull& c, ull a, ull b) {
    asm("fma.rn.f32x2 %0,%1,%2,%0;" : "+l"(c) : "l"(a), "l"(b));
}
__device__ __forceinline__ float2 unpack2(ull v) {
    float lo, hi; asm("mov.b64 {%0,%1},%2;" : "=f"(lo), "=f"(hi) : "l"(v));
    return make_float2(lo, hi);
}
// 4 fp16 weights (in one ull) -> two f32x2 pairs
__device__ __forceinline__ void cvt4(ull w, ull& A, ull& B) {
    uint32_t lo = (uint32_t)w, hi = (uint32_t)(w >> 32);
    __half2 h0 = *reinterpret_cast<__half2*>(&lo);
    __half2 h1 = *reinterpret_cast<__half2*>(&hi);
    float2 f0 = __half22float2(h0);
    float2 f1 = __half22float2(h1);
    A = pack2(f0.x, f0.y);
    B = pack2(f1.x, f1.y);
}

__device__ __forceinline__ float sigmoid_fast(float x) {
    return 1.0f / (1.0f + __expf(-x));
}
__device__ __forceinline__ float tanh_fast(float x) {
    float ax = fabsf(x);
    float e  = __expf(-2.0f * ax);
    float t  = __fdividef(1.0f - e, 1.0f + e);
    return copysignf(t, x);
}

__device__ __forceinline__ ull pack4h(const float* row) {
    ull a = (ull)__half_as_ushort(__float2half_rn(row[0]));
    ull b = (ull)__half_as_ushort(__float2half_rn(row[1]));
    ull c = (ull)__half_as_ushort(__float2half_rn(row[2]));
    ull d = (ull)__half_as_ushort(__float2half_rn(row[3]));
    return a | (b << 16) | (c << 32) | (d << 48);
}

// One-time weight re-layout + fp16 conversion.
// m: 0=Wih l0, 1=Whh l0, 2=Wih l1, 3=Whh l1
__global__ void prep_kernel(const float* __restrict__ Wih,
                            const float* __restrict__ Whh,
                            const float* __restrict__ h2o_w)
{
    int idx = blockIdx.x * blockDim.x + threadIdx.x;
    if (idx < NWH) {
        int j    = idx % G_;
        int rest = idx / G_;
        int k4   = rest % 32;
        int m    = rest / 32;
        int l    = m >> 1;
        const float* src = ((m & 1) == 0) ? Wih : Whh;
        g_Wh[idx] = pack4h(src + ((size_t)l * G_ + j) * H_ + 4 * k4);
    } else if (idx < NWH + 32 * 128) {
        int i2 = idx - NWH;
        int oi = i2 % H_;
        int k4 = i2 / H_;
        g_Wh[idx] = pack4h(h2o_w + oi * H_ + 4 * k4);
    }
}

// Activation pair buffers: ull element = (val_k, val_{k+1}) for one row.
#define SU 10
#define NPBUF (64*SU)
#define PIDX(u, r) (((u) >> 1) * (2*SU) + 2*(r) + ((u) & 1))

// Dual matvec: gi[r] = bi + Wih[j,:]·x[r,:] ; gh[r] = bh + Whh[j,:]·h[r,:]
__device__ __forceinline__ void dualmv(const ull* __restrict__ xp,
                                       const ull* __restrict__ hp,
                                       const ull* __restrict__ wi,
                                       const ull* __restrict__ wh,
                                       float bi, float bh,
                                       float* gi, float* gh)
{
    ull ai[ROWS], ah[ROWS];
#pragma unroll
    for (int r = 0; r < ROWS; r++) { ai[r] = pack2(bi, 0.0f); ah[r] = pack2(bh, 0.0f); }
#pragma unroll 4
    for (int k4 = 0; k4 < 32; k4++) {
        ull wiw = __ldg(wi + k4 * G_);          // 4 fp16, coalesced across j
        ull whw = __ldg(wh + k4 * G_);
        ull wiA, wiB, whA, whB;
        cvt4(wiw, wiA, wiB);
        cvt4(whw, whA, whB);
        const ull* xa = xp + (2 * k4) * SU;
        const ull* ha = hp + (2 * k4) * SU;
#pragma unroll
        for (int p = 0; p < 4; p++) {
            ulonglong2 xv = *(const ulonglong2*)(xa + 2 * p);
            fma2(ai[2*p],   wiA, xv.x);
            fma2(ai[2*p+1], wiA, xv.y);
        }
#pragma unroll
        for (int p = 0; p < 4; p++) {
            ulonglong2 xv = *(const ulonglong2*)(xa + SU + 2 * p);
            fma2(ai[2*p],   wiB, xv.x);
            fma2(ai[2*p+1], wiB, xv.y);
        }
#pragma unroll
        for (int p = 0; p < 4; p++) {
            ulonglong2 hv = *(const ulonglong2*)(ha + 2 * p);
            fma2(ah[2*p],   whA, hv.x);
            fma2(ah[2*p+1], whA, hv.y);
        }
#pragma unroll
        for (int p = 0; p < 4; p++) {
            ulonglong2 hv = *(const ulonglong2*)(ha + SU + 2 * p);
            fma2(ah[2*p],   whB, hv.x);
            fma2(ah[2*p+1], whB, hv.y);
        }
    }
#pragma unroll
    for (int r = 0; r < ROWS; r++) {
        float2 a = unpack2(ai[r]); gi[r] = a.x + a.y;
        float2 b = unpack2(ah[r]); gh[r] = b.x + b.y;
    }
}

__global__ void __launch_bounds__(NTHR, 1)
gru_kernel(const int* __restrict__ il,
           const float* __restrict__ mask,
           const float* __restrict__ emb,
           const float* __restrict__ bih,
           const float* __restrict__ bhh,
           const float* __restrict__ h2o_b,
           float* __restrict__ out1,     // (B,199,H)
           float* __restrict__ out4)     // (B,200,2H)
{
    __shared__ __align__(16) ull xp [NPBUF];
    __shared__ __align__(16) ull bp [NPBUF];
    __shared__ __align__(16) ull h0p[NPBUF];
    __shared__ __align__(16) ull h1p[NPBUF];
    __shared__ __align__(16) float sg [ROWS * G_];
    __shared__ __align__(16) float shn[ROWS * H_];
    __shared__ float skeep[ROWS];

    const int j  = threadIdx.x;
    const int b0 = blockIdx.x * ROWS;

    for (int i = j; i < NPBUF; i += NTHR) { h0p[i] = 0ull; h1p[i] = 0ull; }

    const float bi0 = bih[j],      bh0 = bhh[j];
    const float bi1 = bih[G_ + j], bh1 = bhh[G_ + j];
    const ull* wi0 = g_Wh + (0*32)*G_ + j;
    const ull* wh0 = g_Wh + (1*32)*G_ + j;
    const ull* wi1 = g_Wh + (2*32)*G_ + j;
    const ull* wh1 = g_Wh + (3*32)*G_ + j;

    const int   oi   = j & (H_ - 1);
    const int   half = (j >> 7) & 1;
    const float ob   = (j < 256) ? h2o_b[oi] : 0.0f;
    const ull*  wo   = g_Wh + HOH + oi;

    const int lr  = j & 7;
    const int lk4 = j >> 3;

    float* xpf  = (float*)xp;
    float* bpf  = (float*)bp;
    float* h0pf = (float*)h0p;
    float* h1pf = (float*)h1p;

    __syncthreads();

    for (int t = 0; t < T_; t++) {
        if (j < 256) {
            int tok = il[(b0 + lr) * T_ + t];
            float4 v = __ldg((const float4*)emb + (size_t)tok * 32 + lk4);
            xpf[PIDX(4*lk4 + 0, lr)] = v.x;
            xpf[PIDX(4*lk4 + 1, lr)] = v.y;
            xpf[PIDX(4*lk4 + 2, lr)] = v.z;
            xpf[PIDX(4*lk4 + 3, lr)] = v.w;
            ((float4*)(out4 + ((size_t)(b0 + lr) * T_ + t) * 256))[lk4] = v;
        }
        if (j < ROWS) {
            float m = mask[(b0 + j) * T_ + t];
            skeep[j] = (m != 0.0f) ? 1.0f : 0.0f;
        }
        __syncthreads();

        // ================= layer 0 =================
        {
            float gi[ROWS], gh[ROWS];
            dualmv(xp, h0p, wi0, wh0, bi0, bh0, gi, gh);
            if (j < 2 * H_) {
#pragma unroll
                for (int r = 0; r < ROWS; r++)
                    sg[r * G_ + j] = sigmoid_fast(gi[r] + gh[r]);
            } else {
#pragma unroll
                for (int r = 0; r < ROWS; r++) {
                    sg [r * G_ + j]         = gi[r];
                    shn[r * H_ + (j - 256)] = gh[r];
                }
            }
            __syncthreads();
            if (j < H_) {
#pragma unroll
                for (int r = 0; r < ROWS; r++) {
                    float rv  = sg[r * G_ + j];
                    float zv  = sg[r * G_ + H_ + j];
                    float inn = sg[r * G_ + 2 * H_ + j];
                    float hn  = shn[r * H_ + j];
                    float nv  = tanh_fast(fmaf(rv, hn, inn));
                    float ho  = h0pf[PIDX(j, r)];
                    float hw  = fmaf(zv, ho - nv, nv);
                    bpf [PIDX(j, r)] = hw;
                    h0pf[PIDX(j, r)] = hw * skeep[r];
                }
            }
            __syncthreads();
        }

        // ================= layer 1 =================
        {
            float gi[ROWS], gh[ROWS];
            dualmv(bp, h1p, wi1, wh1, bi1, bh1, gi, gh);
            if (j < 2 * H_) {
#pragma unroll
                for (int r = 0; r < ROWS; r++)
                    sg[r * G_ + j] = sigmoid_fast(gi[r] + gh[r]);
            } else {
#pragma unroll
                for (int r = 0; r < ROWS; r++) {
                    sg [r * G_ + j]         = gi[r];
                    shn[r * H_ + (j - 256)] = gh[r];
                }
            }
            __syncthreads();
            if (j < H_) {
#pragma unroll
                for (int r = 0; r < ROWS; r++) {
                    float rv  = sg[r * G_ + j];
                    float zv  = sg[r * G_ + H_ + j];
                    float inn = sg[r * G_ + 2 * H_ + j];
                    float hn  = shn[r * H_ + j];
                    float nv  = tanh_fast(fmaf(rv, hn, inn));
                    float ho  = h1pf[PIDX(j, r)];
                    float hw  = fmaf(zv, ho - nv, nv);
                    xpf [PIDX(j, r)] = hw;
                    h1pf[PIDX(j, r)] = hw * skeep[r];
                }
            }
            __syncthreads();
        }

        // ================= h2o =================
        if (j < 256) {
            ull acc[4];
#pragma unroll
            for (int p = 0; p < 4; p++) acc[p] = pack2(ob, 0.0f);
            const int r0 = 4 * half;
#pragma unroll 4
            for (int k4 = 0; k4 < 32; k4++) {
                ull ww = __ldg(wo + k4 * H_);
                ull wA, wB;
                cvt4(ww, wA, wB);
                const ull* xa = xp + (2 * k4) * SU + r0;
                ulonglong2 x0 = *(const ulonglong2*)(xa);
                ulonglong2 x1 = *(const ulonglong2*)(xa + 2);
                fma2(acc[0], wA, x0.x); fma2(acc[1], wA, x0.y);
                fma2(acc[2], wA, x1.x); fma2(acc[3], wA, x1.y);
                ulonglong2 y0 = *(const ulonglong2*)(xa + SU);
                ulonglong2 y1 = *(const ulonglong2*)(xa + SU + 2);
                fma2(acc[0], wB, y0.x); fma2(acc[1], wB, y0.y);
                fma2(acc[2], wB, y1.x); fma2(acc[3], wB, y1.y);
            }
#pragma unroll
            for (int rr = 0; rr < 4; rr++) {
                float2 s = unpack2(acc[rr]);
                float o  = tanh_fast(s.x + s.y);
                size_t gb = (size_t)(b0 + r0 + rr);
                out4[(gb * T_ + t) * 256 + H_ + oi] = o;
                if (t < T_ - 1)
                    out1[(gb * (T_ - 1) + t) * H_ + oi] = o;
            }
        }
        __syncthreads();
    }
}

// out2[b,t,:] = emb[il[b,t+1]];  out3[b,t,:] = emb[neg[b,t]]
__global__ void gather_kernel(const int* __restrict__ il,
                              const int* __restrict__ neg,
                              const float4* __restrict__ emb4,
                              float4* __restrict__ out2,
                              float4* __restrict__ out3)
{
    int idx = blockIdx.x * blockDim.x + threadIdx.x;
    const int n4 = B_ * (T_ - 1) * (H_ / 4);
    if (idx >= n4) return;
    int k4 = idx & 31;
    int bt = idx >> 5;
    int b  = bt / (T_ - 1);
    int t  = bt - b * (T_ - 1);
    int p  = il [b * T_ + t + 1];
    int q  = neg[b * T_ + t];
    out2[idx] = __ldg(emb4 + (size_t)p * 32 + k4);
    out3[idx] = __ldg(emb4 + (size_t)q * 32 + k4);
}

extern "C" void kernel_launch(void* const* d_in, const int* in_sizes, int n_in,
                              void* d_out, int out_size)
{
    const int*   il    = (const int*)  d_in[0];
    const float* mask  = (const float*)d_in[1];
    const int*   neg   = (const int*)  d_in[2];
    const float* emb   = (const float*)d_in[3];
    const float* Wih   = (const float*)d_in[4];
    const float* Whh   = (const float*)d_in[5];
    const float* bih   = (const float*)d_in[6];
    const float* bhh   = (const float*)d_in[7];
    const float* h2o_w = (const float*)d_in[8];
    const float* h2o_b = (const float*)d_in[9];

    float* out  = (float*)d_out;
    float* out1 = out;
    float* out2 = out1 + (size_t)B_ * (T_ - 1) * H_;
    float* out3 = out2 + (size_t)B_ * (T_ - 1) * H_;
    float* out4 = out3 + (size_t)B_ * (T_ - 1) * H_;

    const int nprep = NWH + 32 * 128;
    prep_kernel<<<(nprep + 255) / 256, 256>>>(Wih, Whh, h2o_w);

    const int n4 = B_ * (T_ - 1) * (H_ / 4);
    gather_kernel<<<(n4 + 255) / 256, 256>>>(il, neg, (const float4*)emb,
                                             (float4*)out2, (float4*)out3);

    gru_kernel<<<NCTA, NTHR>>>(il, mask, emb, bih, bhh, h2o_b, out1, out4);
}

// round 6
// speedup vs baseline: 1.0937x; 1.0012x over previous
#include <cuda_runtime.h>
#include <cuda_fp16.h>
#include <cstdint>

#define B_   1024
#define T_   200
#define H_   128
#define G_   384
#define ROWS 8
#define NCTA 128
#define NTHR 384

typedef unsigned long long ull;

// fp16 weight scratch: 4 mv matrices [m][k4][j] (ull = 4 halves) + h2o [k4][oi]
#define NWH (4*32*384)
#define HOH NWH
__device__ ull g_Wh[NWH + 32*128];

// ---- packed f32x2 helpers ----
__device__ __forceinline__ ull pack2(float a, float b) {
    ull r; asm("mov.b64 %0,{%1,%2};" : "=l"(r) : "f"(a), "f"(b)); return r;
}
__device__ __forceinline__ void fma2(ull& c, ull a, ull b) {
    asm("fma.rn.f32x2 %0,%1,%2,%0;" : "+l"(c) : "l"(a), "l"(b));
}
__device__ __forceinline__ float2 unpack2(ull v) {
    float lo, hi; asm("mov.b64 {%0,%1},%2;" : "=f"(lo), "=f"(hi) : "l"(v));
    return make_float2(lo, hi);
}
// 4 fp16 weights (in one ull) -> two f32x2 pairs
__device__ __forceinline__ void cvt4(ull w, ull& A, ull& B) {
    uint32_t lo = (uint32_t)w, hi = (uint32_t)(w >> 32);
    __half2 h0 = *reinterpret_cast<__half2*>(&lo);
    __half2 h1 = *reinterpret_cast<__half2*>(&hi);
    float2 f0 = __half22float2(h0);
    float2 f1 = __half22float2(h1);
    A = pack2(f0.x, f0.y);
    B = pack2(f1.x, f1.y);
}

__device__ __forceinline__ float sigmoid_fast(float x) {
    return 1.0f / (1.0f + __expf(-x));
}
__device__ __forceinline__ float tanh_fast(float x) {
    float ax = fabsf(x);
    float e  = __expf(-2.0f * ax);
    float t  = __fdividef(1.0f - e, 1.0f + e);
    return copysignf(t, x);
}

__device__ __forceinline__ ull pack4h(const float* row) {
    ull a = (ull)__half_as_ushort(__float2half_rn(row[0]));
    ull b = (ull)__half_as_ushort(__float2half_rn(row[1]));
    ull c = (ull)__half_as_ushort(__float2half_rn(row[2]));
    ull d = (ull)__half_as_ushort(__float2half_rn(row[3]));
    return a | (b << 16) | (c << 32) | (d << 48);
}

// One-time weight re-layout + fp16 conversion.
// m: 0=Wih l0, 1=Whh l0, 2=Wih l1, 3=Whh l1
__global__ void prep_kernel(const float* __restrict__ Wih,
                            const float* __restrict__ Whh,
                            const float* __restrict__ h2o_w)
{
    int idx = blockIdx.x * blockDim.x + threadIdx.x;
    if (idx < NWH) {
        int j    = idx % G_;
        int rest = idx / G_;
        int k4   = rest % 32;
        int m    = rest / 32;
        int l    = m >> 1;
        const float* src = ((m & 1) == 0) ? Wih : Whh;
        g_Wh[idx] = pack4h(src + ((size_t)l * G_ + j) * H_ + 4 * k4);
    } else if (idx < NWH + 32 * 128) {
        int i2 = idx - NWH;
        int oi = i2 % H_;
        int k4 = i2 / H_;
        g_Wh[idx] = pack4h(h2o_w + oi * H_ + 4 * k4);
    }
}

// Activation pair buffers: ull element = (val_k, val_{k+1}) for one row.
#define SU 10
#define NPBUF (64*SU)
#define PIDX(u, r) (((u) >> 1) * (2*SU) + 2*(r) + ((u) & 1))

// Dual matvec: gi[r] = bi + Wih[j,:]·x[r,:] ; gh[r] = bh + Whh[j,:]·h[r,:]
__device__ __forceinline__ void dualmv(const ull* __restrict__ xp,
                                       const ull* __restrict__ hp,
                                       const ull* __restrict__ wi,
                                       const ull* __restrict__ wh,
                                       float bi, float bh,
                                       float* gi, float* gh)
{
    ull ai[ROWS], ah[ROWS];
#pragma unroll
    for (int r = 0; r < ROWS; r++) { ai[r] = pack2(bi, 0.0f); ah[r] = pack2(bh, 0.0f); }
#pragma unroll 4
    for (int k4 = 0; k4 < 32; k4++) {
        ull wiw = __ldg(wi + k4 * G_);          // 4 fp16, coalesced across j
        ull whw = __ldg(wh + k4 * G_);
        ull wiA, wiB, whA, whB;
        cvt4(wiw, wiA, wiB);
        cvt4(whw, whA, whB);
        const ull* xa = xp + (2 * k4) * SU;
        const ull* ha = hp + (2 * k4) * SU;
#pragma unroll
        for (int p = 0; p < 4; p++) {
            ulonglong2 xv = *(const ulonglong2*)(xa + 2 * p);
            fma2(ai[2*p],   wiA, xv.x);
            fma2(ai[2*p+1], wiA, xv.y);
        }
#pragma unroll
        for (int p = 0; p < 4; p++) {
            ulonglong2 xv = *(const ulonglong2*)(xa + SU + 2 * p);
            fma2(ai[2*p],   wiB, xv.x);
            fma2(ai[2*p+1], wiB, xv.y);
        }
#pragma unroll
        for (int p = 0; p < 4; p++) {
            ulonglong2 hv = *(const ulonglong2*)(ha + 2 * p);
            fma2(ah[2*p],   whA, hv.x);
            fma2(ah[2*p+1], whA, hv.y);
        }
#pragma unroll
        for (int p = 0; p < 4; p++) {
            ulonglong2 hv = *(const ulonglong2*)(ha + SU + 2 * p);
            fma2(ah[2*p],   whB, hv.x);
            fma2(ah[2*p+1], whB, hv.y);
        }
    }
#pragma unroll
    for (int r = 0; r < ROWS; r++) {
        float2 a = unpack2(ai[r]); gi[r] = a.x + a.y;
        float2 b = unpack2(ah[r]); gh[r] = b.x + b.y;
    }
}

__global__ void __launch_bounds__(NTHR, 1)
gru_kernel(const int* __restrict__ il,
           const float* __restrict__ mask,
           const float* __restrict__ emb,
           const float* __restrict__ bih,
           const float* __restrict__ bhh,
           const float* __restrict__ h2o_b,
           float* __restrict__ out1,     // (B,199,H)
           float* __restrict__ out4)     // (B,200,2H)
{
    __shared__ __align__(16) ull xp [NPBUF];
    __shared__ __align__(16) ull bp [NPBUF];
    __shared__ __align__(16) ull h0p[NPBUF];
    __shared__ __align__(16) ull h1p[NPBUF];
    __shared__ __align__(16) float sg [ROWS * G_];
    __shared__ __align__(16) float shn[ROWS * H_];
    __shared__ float skeep[ROWS];

    const int j  = threadIdx.x;
    const int b0 = blockIdx.x * ROWS;

    for (int i = j; i < NPBUF; i += NTHR) { h0p[i] = 0ull; h1p[i] = 0ull; }

    const float bi0 = bih[j],      bh0 = bhh[j];
    const float bi1 = bih[G_ + j], bh1 = bhh[G_ + j];
    const ull* wi0 = g_Wh + (0*32)*G_ + j;
    const ull* wh0 = g_Wh + (1*32)*G_ + j;
    const ull* wi1 = g_Wh + (2*32)*G_ + j;
    const ull* wh1 = g_Wh + (3*32)*G_ + j;

    const int   oi   = j & (H_ - 1);
    const int   half = (j >> 7) & 1;
    const float ob   = (j < 256) ? h2o_b[oi] : 0.0f;
    const ull*  wo   = g_Wh + HOH + oi;

    const int lr  = j & 7;
    const int lk4 = j >> 3;

    float* xpf  = (float*)xp;
    float* bpf  = (float*)bp;
    float* h0pf = (float*)h0p;
    float* h1pf = (float*)h1p;

    __syncthreads();

    for (int t = 0; t < T_; t++) {
        if (j < 256) {
            int tok = il[(b0 + lr) * T_ + t];
            float4 v = __ldg((const float4*)emb + (size_t)tok * 32 + lk4);
            xpf[PIDX(4*lk4 + 0, lr)] = v.x;
            xpf[PIDX(4*lk4 + 1, lr)] = v.y;
            xpf[PIDX(4*lk4 + 2, lr)] = v.z;
            xpf[PIDX(4*lk4 + 3, lr)] = v.w;
            ((float4*)(out4 + ((size_t)(b0 + lr) * T_ + t) * 256))[lk4] = v;
        }
        if (j < ROWS) {
            float m = mask[(b0 + j) * T_ + t];
            skeep[j] = (m != 0.0f) ? 1.0f : 0.0f;
        }
        __syncthreads();

        // ================= layer 0 =================
        {
            float gi[ROWS], gh[ROWS];
            dualmv(xp, h0p, wi0, wh0, bi0, bh0, gi, gh);
            if (j < 2 * H_) {
#pragma unroll
                for (int r = 0; r < ROWS; r++)
                    sg[r * G_ + j] = sigmoid_fast(gi[r] + gh[r]);
            } else {
#pragma unroll
                for (int r = 0; r < ROWS; r++) {
                    sg [r * G_ + j]         = gi[r];
                    shn[r * H_ + (j - 256)] = gh[r];
                }
            }
            __syncthreads();
            if (j < H_) {
#pragma unroll
                for (int r = 0; r < ROWS; r++) {
                    float rv  = sg[r * G_ + j];
                    float zv  = sg[r * G_ + H_ + j];
                    float inn = sg[r * G_ + 2 * H_ + j];
                    float hn  = shn[r * H_ + j];
                    float nv  = tanh_fast(fmaf(rv, hn, inn));
                    float ho  = h0pf[PIDX(j, r)];
                    float hw  = fmaf(zv, ho - nv, nv);
                    bpf [PIDX(j, r)] = hw;
                    h0pf[PIDX(j, r)] = hw * skeep[r];
                }
            }
            __syncthreads();
        }

        // ================= layer 1 =================
        {
            float gi[ROWS], gh[ROWS];
            dualmv(bp, h1p, wi1, wh1, bi1, bh1, gi, gh);
            if (j < 2 * H_) {
#pragma unroll
                for (int r = 0; r < ROWS; r++)
                    sg[r * G_ + j] = sigmoid_fast(gi[r] + gh[r]);
            } else {
#pragma unroll
                for (int r = 0; r < ROWS; r++) {
                    sg [r * G_ + j]         = gi[r];
                    shn[r * H_ + (j - 256)] = gh[r];
                }
            }
            __syncthreads();
            if (j < H_) {
#pragma unroll
                for (int r = 0; r < ROWS; r++) {
                    float rv  = sg[r * G_ + j];
                    float zv  = sg[r * G_ + H_ + j];
                    float inn = sg[r * G_ + 2 * H_ + j];
                    float hn  = shn[r * H_ + j];
                    float nv  = tanh_fast(fmaf(rv, hn, inn));
                    float ho  = h1pf[PIDX(j, r)];
                    float hw  = fmaf(zv, ho - nv, nv);
                    xpf [PIDX(j, r)] = hw;
                    h1pf[PIDX(j, r)] = hw * skeep[r];
                }
            }
            __syncthreads();
        }

        // ================= h2o =================
        if (j < 256) {
            ull acc[4];
#pragma unroll
            for (int p = 0; p < 4; p++) acc[p] = pack2(ob, 0.0f);
            const int r0 = 4 * half;
#pragma unroll 4
            for (int k4 = 0; k4 < 32; k4++) {
                ull ww = __ldg(wo + k4 * H_);
                ull wA, wB;
                cvt4(ww, wA, wB);
                const ull* xa = xp + (2 * k4) * SU + r0;
                ulonglong2 x0 = *(const ulonglong2*)(xa);
                ulonglong2 x1 = *(const ulonglong2*)(xa + 2);
                fma2(acc[0], wA, x0.x); fma2(acc[1], wA, x0.y);
                fma2(acc[2], wA, x1.x); fma2(acc[3], wA, x1.y);
                ulonglong2 y0 = *(const ulonglong2*)(xa + SU);
                ulonglong2 y1 = *(const ulonglong2*)(xa + SU + 2);
                fma2(acc[0], wB, y0.x); fma2(acc[1], wB, y0.y);
                fma2(acc[2], wB, y1.x); fma2(acc[3], wB, y1.y);
            }
#pragma unroll
            for (int rr = 0; rr < 4; rr++) {
                float2 s = unpack2(acc[rr]);
                float o  = tanh_fast(s.x + s.y);
                size_t gb = (size_t)(b0 + r0 + rr);
                out4[(gb * T_ + t) * 256 + H_ + oi] = o;
                if (t < T_ - 1)
                    out1[(gb * (T_ - 1) + t) * H_ + oi] = o;
            }
        }
        __syncthreads();
    }
}

// out2[b,t,:] = emb[il[b,t+1]];  out3[b,t,:] = emb[neg[b,t]]
__global__ void gather_kernel(const int* __restrict__ il,
                              const int* __restrict__ neg,
                              const float4* __restrict__ emb4,
                              float4* __restrict__ out2,
                              float4* __restrict__ out3)
{
    int idx = blockIdx.x * blockDim.x + threadIdx.x;
    const int n4 = B_ * (T_ - 1) * (H_ / 4);
    if (idx >= n4) return;
    int k4 = idx & 31;
    int bt = idx >> 5;
    int b  = bt / (T_ - 1);
    int t  = bt - b * (T_ - 1);
    int p  = il [b * T_ + t + 1];
    int q  = neg[b * T_ + t];
    out2[idx] = __ldg(emb4 + (size_t)p * 32 + k4);
    out3[idx] = __ldg(emb4 + (size_t)q * 32 + k4);
}

extern "C" void kernel_launch(void* const* d_in, const int* in_sizes, int n_in,
                              void* d_out, int out_size)
{
    const int*   il    = (const int*)  d_in[0];
    const float* mask  = (const float*)d_in[1];
    const int*   neg   = (const int*)  d_in[2];
    const float* emb   = (const float*)d_in[3];
    const float* Wih   = (const float*)d_in[4];
    const float* Whh   = (const float*)d_in[5];
    const float* bih   = (const float*)d_in[6];
    const float* bhh   = (const float*)d_in[7];
    const float* h2o_w = (const float*)d_in[8];
    const float* h2o_b = (const float*)d_in[9];

    float* out  = (float*)d_out;
    float* out1 = out;
    float* out2 = out1 + (size_t)B_ * (T_ - 1) * H_;
    float* out3 = out2 + (size_t)B_ * (T_ - 1) * H_;
    float* out4 = out3 + (size_t)B_ * (T_ - 1) * H_;

    const int nprep = NWH + 32 * 128;
    prep_kernel<<<(nprep + 255) / 256, 256>>>(Wih, Whh, h2o_w);

    const int n4 = B_ * (T_ - 1) * (H_ / 4);
    gather_kernel<<<(n4 + 255) / 256, 256>>>(il, neg, (const float4*)emb,
                                             (float4*)out2, (float4*)out3);

    gru_kernel<<<NCTA, NTHR>>>(il, mask, emb, bih, bhh, h2o_b, out1, out4);
}

// round 7
// speedup vs baseline: 1.1772x; 1.0764x over previous
#include <cuda_runtime.h>
#include <cuda_fp16.h>
#include <cstdint>

#define B_   1024
#define T_   200
#define H_   128
#define G_   384
#define ROWS 8
#define NCTA 128          // B_/ROWS
#define NTHR 768          // 2 k-halves x 384 gate threads
#define NBT  (B_*T_)

typedef unsigned long long ull;

// fp16 weight scratch: m=0 Wih0, 1 Whh0, 2 Wih1, 3 Whh1, then h2o
#define NWH (4*32*384)
#define HOH NWH
__device__ ull   g_Wh[NWH + 32*128];
__device__ float g_gi0[(size_t)NBT * G_];   // precomputed layer-0 input gates (+bias)
__device__ float g_h1 [(size_t)NBT * H_];   // raw layer-1 hidden outputs (unmasked)

// ---- packed f32x2 helpers ----
__device__ __forceinline__ ull pack2(float a, float b) {
    ull r; asm("mov.b64 %0,{%1,%2};" : "=l"(r) : "f"(a), "f"(b)); return r;
}
__device__ __forceinline__ void fma2(ull& c, ull a, ull b) {
    asm("fma.rn.f32x2 %0,%1,%2,%0;" : "+l"(c) : "l"(a), "l"(b));
}
__device__ __forceinline__ float2 unpack2(ull v) {
    float lo, hi; asm("mov.b64 {%0,%1},%2;" : "=f"(lo), "=f"(hi) : "l"(v));
    return make_float2(lo, hi);
}
__device__ __forceinline__ void cvt4(ull w, ull& A, ull& B) {
    uint32_t lo = (uint32_t)w, hi = (uint32_t)(w >> 32);
    __half2 h0 = *reinterpret_cast<__half2*>(&lo);
    __half2 h1 = *reinterpret_cast<__half2*>(&hi);
    float2 f0 = __half22float2(h0);
    float2 f1 = __half22float2(h1);
    A = pack2(f0.x, f0.y);
    B = pack2(f1.x, f1.y);
}
__device__ __forceinline__ float sigmoid_fast(float x) {
    return 1.0f / (1.0f + __expf(-x));
}
__device__ __forceinline__ float tanh_fast(float x) {
    float ax = fabsf(x);
    float e  = __expf(-2.0f * ax);
    float t  = __fdividef(1.0f - e, 1.0f + e);
    return copysignf(t, x);
}
__device__ __forceinline__ ull pack4h(const float* row) {
    ull a = (ull)__half_as_ushort(__float2half_rn(row[0]));
    ull b = (ull)__half_as_ushort(__float2half_rn(row[1]));
    ull c = (ull)__half_as_ushort(__float2half_rn(row[2]));
    ull d = (ull)__half_as_ushort(__float2half_rn(row[3]));
    return a | (b << 16) | (c << 32) | (d << 48);
}

__global__ void prep_kernel(const float* __restrict__ Wih,
                            const float* __restrict__ Whh,
                            const float* __restrict__ h2o_w)
{
    int idx = blockIdx.x * blockDim.x + threadIdx.x;
    if (idx < NWH) {
        int j    = idx % G_;
        int rest = idx / G_;
        int k4   = rest % 32;
        int m    = rest / 32;
        int l    = m >> 1;
        const float* src = ((m & 1) == 0) ? Wih : Whh;
        g_Wh[idx] = pack4h(src + ((size_t)l * G_ + j) * H_ + 4 * k4);
    } else if (idx < NWH + 32 * 128) {
        int i2 = idx - NWH;
        int oi = i2 % H_;
        int k4 = i2 / H_;
        g_Wh[idx] = pack4h(h2o_w + oi * H_ + 4 * k4);
    }
}

// Activation pair layout: ull = (val_k, val_{k+1}) for one row.
#define SU 10
#define NPBUF (64*SU)
#define PIDX(u, r) (((u) >> 1) * (2*SU) + 2*(r) + ((u) & 1))

// ===================== pre-kernel: gi0 + out4-low =====================
__global__ void __launch_bounds__(384)
pre_kernel(const int* __restrict__ il,
           const float* __restrict__ emb,
           const float* __restrict__ bih,
           float* __restrict__ out4)
{
    __shared__ __align__(16) ull xp[NPBUF];
    const int j   = threadIdx.x;
    const int bt0 = blockIdx.x * ROWS;
    float* xpf = (float*)xp;

    if (j < 256) {
        int lr = j & 7, lk4 = j >> 3;
        int tok = il[bt0 + lr];
        float4 v = __ldg((const float4*)emb + (size_t)tok * 32 + lk4);
        xpf[PIDX(4*lk4 + 0, lr)] = v.x;
        xpf[PIDX(4*lk4 + 1, lr)] = v.y;
        xpf[PIDX(4*lk4 + 2, lr)] = v.z;
        xpf[PIDX(4*lk4 + 3, lr)] = v.w;
        ((float4*)(out4 + (size_t)(bt0 + lr) * 256))[lk4] = v;
    }
    __syncthreads();

    const ull* w = g_Wh + j;     // m=0 (Wih l0)
    float bi = bih[j];
    ull acc[ROWS];
#pragma unroll
    for (int r = 0; r < ROWS; r++) acc[r] = pack2(bi, 0.0f);
#pragma unroll 4
    for (int k4 = 0; k4 < 32; k4++) {
        ull wA, wB; cvt4(__ldg(w + k4 * G_), wA, wB);
        const ull* xa = xp + (2 * k4) * SU;
#pragma unroll
        for (int p = 0; p < 4; p++) {
            ulonglong2 xv = *(const ulonglong2*)(xa + 2 * p);
            fma2(acc[2*p],   wA, xv.x);
            fma2(acc[2*p+1], wA, xv.y);
        }
#pragma unroll
        for (int p = 0; p < 4; p++) {
            ulonglong2 xv = *(const ulonglong2*)(xa + SU + 2 * p);
            fma2(acc[2*p],   wB, xv.x);
            fma2(acc[2*p+1], wB, xv.y);
        }
    }
#pragma unroll
    for (int r = 0; r < ROWS; r++) {
        float2 s = unpack2(acc[r]);
        g_gi0[(size_t)(bt0 + r) * G_ + j] = s.x + s.y;
    }
}

// ===================== post-kernel: h2o GEMM + tanh =====================
__global__ void __launch_bounds__(128)
post_kernel(const float* __restrict__ h2o_b,
            float* __restrict__ out1,
            float* __restrict__ out4)
{
    __shared__ __align__(16) ull xp[NPBUF];
    const int j   = threadIdx.x;       // output index oi
    const int bt0 = blockIdx.x * ROWS;
    float* xpf = (float*)xp;

#pragma unroll
    for (int r = 0; r < ROWS; r++)
        xpf[PIDX(j, r)] = g_h1[(size_t)(bt0 + r) * H_ + j];
    __syncthreads();

    const ull* w = g_Wh + HOH + j;
    float ob = h2o_b[j];
    ull acc[ROWS];
#pragma unroll
    for (int r = 0; r < ROWS; r++) acc[r] = pack2(ob, 0.0f);
#pragma unroll 4
    for (int k4 = 0; k4 < 32; k4++) {
        ull wA, wB; cvt4(__ldg(w + k4 * H_), wA, wB);
        const ull* xa = xp + (2 * k4) * SU;
#pragma unroll
        for (int p = 0; p < 4; p++) {
            ulonglong2 xv = *(const ulonglong2*)(xa + 2 * p);
            fma2(acc[2*p],   wA, xv.x);
            fma2(acc[2*p+1], wA, xv.y);
        }
#pragma unroll
        for (int p = 0; p < 4; p++) {
            ulonglong2 xv = *(const ulonglong2*)(xa + SU + 2 * p);
            fma2(acc[2*p],   wB, xv.x);
            fma2(acc[2*p+1], wB, xv.y);
        }
    }
#pragma unroll
    for (int r = 0; r < ROWS; r++) {
        float2 s = unpack2(acc[r]);
        float o  = tanh_fast(s.x + s.y);
        int bt = bt0 + r;
        int b  = bt / T_;
        int t  = bt - b * T_;
        out4[(size_t)bt * 256 + H_ + j] = o;
        if (t < T_ - 1)
            out1[((size_t)b * (T_ - 1) + t) * H_ + j] = o;
    }
}

// ===================== recurrence loop =====================
// mvhalf: partial gh over 16 k4's (one k-half) of one matrix.
__device__ __forceinline__ void mvhalf(const ull* __restrict__ hp,
                                       const ull* __restrict__ w,
                                       float bh, float* gh)
{
    ull ah[ROWS];
#pragma unroll
    for (int r = 0; r < ROWS; r++) ah[r] = pack2(bh, 0.0f);
#pragma unroll 2
    for (int k4 = 0; k4 < 16; k4++) {
        ull wA, wB; cvt4(__ldg(w + k4 * G_), wA, wB);
        const ull* ha = hp + (2 * k4) * SU;
#pragma unroll
        for (int p = 0; p < 4; p++) {
            ulonglong2 hv = *(const ulonglong2*)(ha + 2 * p);
            fma2(ah[2*p],   wA, hv.x);
            fma2(ah[2*p+1], wA, hv.y);
        }
#pragma unroll
        for (int p = 0; p < 4; p++) {
            ulonglong2 hv = *(const ulonglong2*)(ha + SU + 2 * p);
            fma2(ah[2*p],   wB, hv.x);
            fma2(ah[2*p+1], wB, hv.y);
        }
    }
#pragma unroll
    for (int r = 0; r < ROWS; r++) {
        float2 s = unpack2(ah[r]); gh[r] = s.x + s.y;
    }
}

// mvfull: partial gi+gh over 16 k4's of two matrices.
__device__ __forceinline__ void mvfull(const ull* __restrict__ xpb,
                                       const ull* __restrict__ hp,
                                       const ull* __restrict__ wi,
                                       const ull* __restrict__ wh,
                                       float bi, float bh,
                                       float* gi, float* gh)
{
    ull ai[ROWS], ah[ROWS];
#pragma unroll
    for (int r = 0; r < ROWS; r++) { ai[r] = pack2(bi, 0.0f); ah[r] = pack2(bh, 0.0f); }
#pragma unroll 2
    for (int k4 = 0; k4 < 16; k4++) {
        ull wiA, wiB, whA, whB;
        cvt4(__ldg(wi + k4 * G_), wiA, wiB);
        cvt4(__ldg(wh + k4 * G_), whA, whB);
        const ull* xa = xpb + (2 * k4) * SU;
        const ull* ha = hp  + (2 * k4) * SU;
#pragma unroll
        for (int p = 0; p < 4; p++) {
            ulonglong2 xv = *(const ulonglong2*)(xa + 2 * p);
            fma2(ai[2*p],   wiA, xv.x);
            fma2(ai[2*p+1], wiA, xv.y);
        }
#pragma unroll
        for (int p = 0; p < 4; p++) {
            ulonglong2 xv = *(const ulonglong2*)(xa + SU + 2 * p);
            fma2(ai[2*p],   wiB, xv.x);
            fma2(ai[2*p+1], wiB, xv.y);
        }
#pragma unroll
        for (int p = 0; p < 4; p++) {
            ulonglong2 hv = *(const ulonglong2*)(ha + 2 * p);
            fma2(ah[2*p],   whA, hv.x);
            fma2(ah[2*p+1], whA, hv.y);
        }
#pragma unroll
        for (int p = 0; p < 4; p++) {
            ulonglong2 hv = *(const ulonglong2*)(ha + SU + 2 * p);
            fma2(ah[2*p],   whB, hv.x);
            fma2(ah[2*p+1], whB, hv.y);
        }
    }
#pragma unroll
    for (int r = 0; r < ROWS; r++) {
        float2 a = unpack2(ai[r]); gi[r] = a.x + a.y;
        float2 b = unpack2(ah[r]); gh[r] = b.x + b.y;
    }
}

__global__ void __launch_bounds__(NTHR, 1)
gru_loop(const float* __restrict__ mask,
         const float* __restrict__ bih,
         const float* __restrict__ bhh)
{
    __shared__ __align__(16) ull bp [NPBUF];    // layer0 output pairs
    __shared__ __align__(16) ull h0p[NPBUF];
    __shared__ __align__(16) ull h1p[NPBUF];
    __shared__ __align__(16) float sgi[ROWS * G_];   // psum-gi ALIAS gate buffer
    __shared__ __align__(16) float psh[ROWS * G_];   // psum-gh
    __shared__ __align__(16) float shn[ROWS * H_];
    __shared__ float skeep[ROWS];

    const int tid = threadIdx.x;
    const int kh  = tid / 384;          // k-half 0/1
    const int j   = tid - kh * 384;     // gate index
    const int b0  = blockIdx.x * ROWS;

    for (int i = tid; i < NPBUF; i += NTHR) { h0p[i] = 0ull; h1p[i] = 0ull; }

    const ull* wh0 = g_Wh + (1*32 + kh*16) * G_ + j;
    const ull* wi1 = g_Wh + (2*32 + kh*16) * G_ + j;
    const ull* wh1 = g_Wh + (3*32 + kh*16) * G_ + j;
    const float bh0 = kh ? 0.0f : bhh[j];
    const float bi1 = kh ? 0.0f : bih[G_ + j];
    const float bh1 = kh ? 0.0f : bhh[G_ + j];

    const ull* h0k = h0p + (kh * 32) * SU;   // this half's k-range base
    const ull* h1k = h1p + (kh * 32) * SU;
    const ull* bpk = bp  + (kh * 32) * SU;

    float* h0pf = (float*)h0p;
    float* h1pf = (float*)h1p;
    float* bpf  = (float*)bp;

    __syncthreads();

    for (int t = 0; t < T_; t++) {
        // prefetch gi0 (kh=0 only) and mask
        float gi0r[ROWS];
        if (!kh) {
#pragma unroll
            for (int r = 0; r < ROWS; r++)
                gi0r[r] = __ldg(g_gi0 + ((size_t)(b0 + r) * T_ + t) * G_ + j);
        } else if (j < ROWS) {
            float m = mask[(b0 + j) * T_ + t];
            skeep[j] = (m != 0.0f) ? 1.0f : 0.0f;
        }

        // ---------- layer 0: gh partial ----------
        {
            float gh[ROWS];
            mvhalf(h0k, wh0, bh0, gh);
            if (kh) {
#pragma unroll
                for (int r = 0; r < ROWS; r++) psh[r * G_ + j] = gh[r];
            }
            __syncthreads();
            if (!kh) {
#pragma unroll
                for (int r = 0; r < ROWS; r++) gh[r] += psh[r * G_ + j];
                if (j < 2 * H_) {
#pragma unroll
                    for (int r = 0; r < ROWS; r++)
                        sgi[r * G_ + j] = sigmoid_fast(gi0r[r] + gh[r]);
                } else {
#pragma unroll
                    for (int r = 0; r < ROWS; r++) {
                        sgi[r * G_ + j]         = gi0r[r];
                        shn[r * H_ + (j - 256)] = gh[r];
                    }
                }
            }
            __syncthreads();
            if (!kh && j < H_) {
#pragma unroll
                for (int r = 0; r < ROWS; r++) {
                    float rv  = sgi[r * G_ + j];
                    float zv  = sgi[r * G_ + H_ + j];
                    float inn = sgi[r * G_ + 2 * H_ + j];
                    float hn  = shn[r * H_ + j];
                    float nv  = tanh_fast(fmaf(rv, hn, inn));
                    float ho  = h0pf[PIDX(j, r)];
                    float hw  = fmaf(zv, ho - nv, nv);
                    bpf [PIDX(j, r)] = hw;
                    h0pf[PIDX(j, r)] = hw * skeep[r];
                }
            }
            __syncthreads();
        }

        // ---------- layer 1: gi + gh partial ----------
        {
            float gi[ROWS], gh[ROWS];
            mvfull(bpk, h1k, wi1, wh1, bi1, bh1, gi, gh);
            if (kh) {
#pragma unroll
                for (int r = 0; r < ROWS; r++) {
                    sgi[r * G_ + j] = gi[r];
                    psh[r * G_ + j] = gh[r];
                }
            }
            __syncthreads();
            if (!kh) {
#pragma unroll
                for (int r = 0; r < ROWS; r++) {
                    gi[r] += sgi[r * G_ + j];
                    gh[r] += psh[r * G_ + j];
                }
                if (j < 2 * H_) {
#pragma unroll
                    for (int r = 0; r < ROWS; r++)
                        sgi[r * G_ + j] = sigmoid_fast(gi[r] + gh[r]);
                } else {
#pragma unroll
                    for (int r = 0; r < ROWS; r++) {
                        sgi[r * G_ + j]         = gi[r];
                        shn[r * H_ + (j - 256)] = gh[r];
                    }
                }
            }
            __syncthreads();
            if (!kh && j < H_) {
#pragma unroll
                for (int r = 0; r < ROWS; r++) {
                    float rv  = sgi[r * G_ + j];
                    float zv  = sgi[r * G_ + H_ + j];
                    float inn = sgi[r * G_ + 2 * H_ + j];
                    float hn  = shn[r * H_ + j];
                    float nv  = tanh_fast(fmaf(rv, hn, inn));
                    float ho  = h1pf[PIDX(j, r)];
                    float hw  = fmaf(zv, ho - nv, nv);
                    g_h1[(size_t)((b0 + r) * T_ + t) * H_ + j] = hw;   // raw h1
                    h1pf[PIDX(j, r)] = hw * skeep[r];
                }
            }
            __syncthreads();
        }
    }
}

// out2/out3 gathers
__global__ void gather_kernel(const int* __restrict__ il,
                              const int* __restrict__ neg,
                              const float4* __restrict__ emb4,
                              float4* __restrict__ out2,
                              float4* __restrict__ out3)
{
    int idx = blockIdx.x * blockDim.x + threadIdx.x;
    const int n4 = B_ * (T_ - 1) * (H_ / 4);
    if (idx >= n4) return;
    int k4 = idx & 31;
    int bt = idx >> 5;
    int b  = bt / (T_ - 1);
    int t  = bt - b * (T_ - 1);
    int p  = il [b * T_ + t + 1];
    int q  = neg[b * T_ + t];
    out2[idx] = __ldg(emb4 + (size_t)p * 32 + k4);
    out3[idx] = __ldg(emb4 + (size_t)q * 32 + k4);
}

extern "C" void kernel_launch(void* const* d_in, const int* in_sizes, int n_in,
                              void* d_out, int out_size)
{
    const int*   il    = (const int*)  d_in[0];
    const float* mask  = (const float*)d_in[1];
    const int*   neg   = (const int*)  d_in[2];
    const float* emb   = (const float*)d_in[3];
    const float* Wih   = (const float*)d_in[4];
    const float* Whh   = (const float*)d_in[5];
    const float* bih   = (const float*)d_in[6];
    const float* bhh   = (const float*)d_in[7];
    const float* h2o_w = (const float*)d_in[8];
    const float* h2o_b = (const float*)d_in[9];

    float* out  = (float*)d_out;
    float* out1 = out;
    float* out2 = out1 + (size_t)B_ * (T_ - 1) * H_;
    float* out3 = out2 + (size_t)B_ * (T_ - 1) * H_;
    float* out4 = out3 + (size_t)B_ * (T_ - 1) * H_;

    const int nprep = NWH + 32 * 128;
    prep_kernel<<<(nprep + 255) / 256, 256>>>(Wih, Whh, h2o_w);

    const int n4 = B_ * (T_ - 1) * (H_ / 4);
    gather_kernel<<<(n4 + 255) / 256, 256>>>(il, neg, (const float4*)emb,
                                             (float4*)out2, (float4*)out3);

    pre_kernel<<<NBT / ROWS, 384>>>(il, emb, bih, out4);

    gru_loop<<<NCTA, NTHR>>>(mask, bih, bhh);

    post_kernel<<<NBT / ROWS, 128>>>(h2o_b, out1, out4);
}

// round 8
// speedup vs baseline: 1.2940x; 1.0992x over previous
#include <cuda_runtime.h>
#include <cuda_fp16.h>
#include <cstdint>

#define B_   1024
#define T_   200
#define H_   128
#define G_   384
#define ROWS 8
#define NCTA 128
#define NTHR 768
#define NBT  (B_*T_)

#define SU 10
#define NPBUF (64*SU)
#define PIDX(u,r) (((u)>>1)*(2*SU) + 2*(r) + ((u)&1))
#define PSQ (384*9)          // floats per k-quarter psum slice

typedef unsigned long long ull;

#define NWP (4*32*192)
__device__ ulonglong2 g_Wp[NWP];          // paired fp16 weights: [m][k4][jp] -> {j, j+192}
__device__ ull        g_Wo[32*128];       // h2o fp16 [k4][oi]
__device__ float g_gi0[(size_t)NBT * G_]; // precomputed layer-0 input gates (+bias)
__device__ float g_h1 [(size_t)NBT * H_]; // raw layer-1 hidden outputs

// ---- packed f32x2 helpers ----
__device__ __forceinline__ ull pack2(float a, float b) {
    ull r; asm("mov.b64 %0,{%1,%2};" : "=l"(r) : "f"(a), "f"(b)); return r;
}
__device__ __forceinline__ void fma2(ull& c, ull a, ull b) {
    asm("fma.rn.f32x2 %0,%1,%2,%0;" : "+l"(c) : "l"(a), "l"(b));
}
__device__ __forceinline__ float2 unpack2(ull v) {
    float lo, hi; asm("mov.b64 {%0,%1},%2;" : "=f"(lo), "=f"(hi) : "l"(v));
    return make_float2(lo, hi);
}
__device__ __forceinline__ void cvt4(ull w, ull& A, ull& B) {
    uint32_t lo = (uint32_t)w, hi = (uint32_t)(w >> 32);
    __half2 h0 = *reinterpret_cast<__half2*>(&lo);
    __half2 h1 = *reinterpret_cast<__half2*>(&hi);
    float2 f0 = __half22float2(h0);
    float2 f1 = __half22float2(h1);
    A = pack2(f0.x, f0.y);
    B = pack2(f1.x, f1.y);
}
__device__ __forceinline__ ulonglong2 ldg128(const ulonglong2* p) {
    ulonglong2 v;
    asm("ld.global.nc.v2.u64 {%0,%1},[%2];" : "=l"(v.x), "=l"(v.y) : "l"(p));
    return v;
}
__device__ __forceinline__ float sigmoid_fast(float x) {
    return 1.0f / (1.0f + __expf(-x));
}
__device__ __forceinline__ float tanh_fast(float x) {
    float ax = fabsf(x);
    float e  = __expf(-2.0f * ax);
    float t  = __fdividef(1.0f - e, 1.0f + e);
    return copysignf(t, x);
}
__device__ __forceinline__ ull pack4h(const float* row) {
    ull a = (ull)__half_as_ushort(__float2half_rn(row[0]));
    ull b = (ull)__half_as_ushort(__float2half_rn(row[1]));
    ull c = (ull)__half_as_ushort(__float2half_rn(row[2]));
    ull d = (ull)__half_as_ushort(__float2half_rn(row[3]));
    return a | (b << 16) | (c << 32) | (d << 48);
}
__device__ __forceinline__ void cpasync16(uint32_t dst, const void* src) {
    asm volatile("cp.async.ca.shared.global [%0],[%1],16;" :: "r"(dst), "l"(src));
}

// One-time weight re-layout (fp16 pairs).  m: 0=Wih0, 1=Whh0, 2=Wih1, 3=Whh1
__global__ void prep_kernel(const float* __restrict__ Wih,
                            const float* __restrict__ Whh,
                            const float* __restrict__ h2o_w)
{
    int idx = blockIdx.x * blockDim.x + threadIdx.x;
    if (idx < NWP) {
        int jp = idx % 192;
        int k4 = (idx / 192) % 32;
        int m  = idx / (192 * 32);
        int l  = m >> 1;
        const float* src = ((m & 1) == 0) ? Wih : Whh;
        ulonglong2 v;
        v.x = pack4h(src + ((size_t)l * G_ + jp      ) * H_ + 4 * k4);
        v.y = pack4h(src + ((size_t)l * G_ + jp + 192) * H_ + 4 * k4);
        g_Wp[idx] = v;
    } else if (idx < NWP + 32 * 128) {
        int i2 = idx - NWP;
        int oi = i2 % H_;
        int k4 = i2 / H_;
        g_Wo[i2] = pack4h(h2o_w + oi * H_ + 4 * k4);
    }
}

// 2j matvec partial: out[jj][r] = b_jj + sum over NK4 k-quads of W[j_jj,:]·act[r,:]
template<int NK4>
__device__ __forceinline__ void mv2j(const ull* __restrict__ act,
                                     const ulonglong2* __restrict__ w,
                                     float out[2][8], float b0, float b1)
{
    ull acc[2][8];
#pragma unroll
    for (int r = 0; r < 8; r++) { acc[0][r] = pack2(b0, 0.f); acc[1][r] = pack2(b1, 0.f); }
#pragma unroll 8
    for (int k4 = 0; k4 < NK4; k4++) {
        ulonglong2 ww = ldg128(w + k4 * 192);
        ull w0A, w0B, w1A, w1B;
        cvt4(ww.x, w0A, w0B);
        cvt4(ww.y, w1A, w1B);
        const ull* xa = act + 2 * k4 * SU;
#pragma unroll
        for (int p = 0; p < 4; p++) {
            ulonglong2 xv = *(const ulonglong2*)(xa + 2 * p);
            fma2(acc[0][2*p],   w0A, xv.x);
            fma2(acc[0][2*p+1], w0A, xv.y);
            fma2(acc[1][2*p],   w1A, xv.x);
            fma2(acc[1][2*p+1], w1A, xv.y);
        }
#pragma unroll
        for (int p = 0; p < 4; p++) {
            ulonglong2 xv = *(const ulonglong2*)(xa + SU + 2 * p);
            fma2(acc[0][2*p],   w0B, xv.x);
            fma2(acc[0][2*p+1], w0B, xv.y);
            fma2(acc[1][2*p],   w1B, xv.x);
            fma2(acc[1][2*p+1], w1B, xv.y);
        }
    }
#pragma unroll
    for (int jj = 0; jj < 2; jj++)
#pragma unroll
        for (int r = 0; r < 8; r++) {
            float2 s = unpack2(acc[jj][r]);
            out[jj][r] = s.x + s.y;
        }
}

// ===================== pre-kernel: gi0 + out4-low (32 rows / block) =====================
__global__ void __launch_bounds__(768)
pre_kernel(const int* __restrict__ il,
           const float* __restrict__ emb,
           const float* __restrict__ bih,
           float* __restrict__ out4)
{
    __shared__ __align__(16) ull xq[4 * NPBUF];
    const int tid = threadIdx.x;
    const int bt0 = blockIdx.x * 32;

    for (int i = tid; i < 1024; i += 768) {
        int row = i >> 5, k4 = i & 31;
        int tok = il[bt0 + row];
        float4 v = __ldg((const float4*)emb + (size_t)tok * 32 + k4);
        float* base = (float*)(xq + (row >> 3) * NPBUF);
        int r = row & 7;
        base[PIDX(4*k4 + 0, r)] = v.x;
        base[PIDX(4*k4 + 1, r)] = v.y;
        base[PIDX(4*k4 + 2, r)] = v.z;
        base[PIDX(4*k4 + 3, r)] = v.w;
        ((float4*)(out4 + (size_t)(bt0 + row) * 256))[k4] = v;
    }
    __syncthreads();

    const int rg = tid / 192, jp = tid - rg * 192;
    float out[2][8];
    mv2j<32>(xq + rg * NPBUF, g_Wp + jp, out, bih[jp], bih[jp + 192]);
#pragma unroll
    for (int jj = 0; jj < 2; jj++)
#pragma unroll
        for (int r = 0; r < 8; r++)
            g_gi0[(size_t)(bt0 + rg * 8 + r) * G_ + jp + jj * 192] = out[jj][r];
}

// ===================== post-kernel: h2o GEMM + tanh =====================
__global__ void __launch_bounds__(128)
post_kernel(const float* __restrict__ h2o_b,
            float* __restrict__ out1,
            float* __restrict__ out4)
{
    __shared__ __align__(16) ull xp[NPBUF];
    const int j   = threadIdx.x;
    const int bt0 = blockIdx.x * ROWS;
    float* xpf = (float*)xp;

#pragma unroll
    for (int r = 0; r < ROWS; r++)
        xpf[PIDX(j, r)] = g_h1[(size_t)(bt0 + r) * H_ + j];
    __syncthreads();

    const ull* w = g_Wo + j;
    float ob = h2o_b[j];
    ull acc[ROWS];
#pragma unroll
    for (int r = 0; r < ROWS; r++) acc[r] = pack2(ob, 0.0f);
#pragma unroll 4
    for (int k4 = 0; k4 < 32; k4++) {
        ull wA, wB; cvt4(__ldg(w + k4 * H_), wA, wB);
        const ull* xa = xp + (2 * k4) * SU;
#pragma unroll
        for (int p = 0; p < 4; p++) {
            ulonglong2 xv = *(const ulonglong2*)(xa + 2 * p);
            fma2(acc[2*p],   wA, xv.x);
            fma2(acc[2*p+1], wA, xv.y);
        }
#pragma unroll
        for (int p = 0; p < 4; p++) {
            ulonglong2 xv = *(const ulonglong2*)(xa + SU + 2 * p);
            fma2(acc[2*p],   wB, xv.x);
            fma2(acc[2*p+1], wB, xv.y);
        }
    }
#pragma unroll
    for (int r = 0; r < ROWS; r++) {
        float2 s = unpack2(acc[r]);
        float o  = tanh_fast(s.x + s.y);
        int bt = bt0 + r;
        int b  = bt / T_;
        int t  = bt - b * T_;
        out4[(size_t)bt * 256 + H_ + j] = o;
        if (t < T_ - 1)
            out1[((size_t)b * (T_ - 1) + t) * H_ + j] = o;
    }
}

// ===================== recurrence loop =====================
__global__ void __launch_bounds__(NTHR, 1)
gru_loop(const float* __restrict__ mask,
         const float* __restrict__ bih,
         const float* __restrict__ bhh)
{
    extern __shared__ __align__(16) char dsm[];
    ull*   bp    = (ull*)dsm;                         // layer0 out pairs
    ull*   h0p   = bp  + NPBUF;
    ull*   h1p   = h0p + NPBUF;
    float* sgi   = (float*)(h1p + NPBUF);             // gi0 / gates [r][j]
    float* shn   = sgi + ROWS * G_;                   // hn slice [r][j-256]
    float* psA   = shn + ROWS * H_;                   // 3*PSQ
    float* psB   = psA + 3 * PSQ;                     // 3*PSQ
    float* skeep = psB + 3 * PSQ;                     // 8

    const int tid = threadIdx.x;
    const int q   = tid / 192;       // k-quarter
    const int jp  = tid - q * 192;   // gate pair index
    const int b0  = blockIdx.x * ROWS;

    for (int i = tid; i < NPBUF; i += NTHR) { h0p[i] = 0ull; h1p[i] = 0ull; }

    const ulonglong2* wh0 = g_Wp + (1*32 + q*8) * 192 + jp;
    const ulonglong2* wi1 = g_Wp + (2*32 + q*8) * 192 + jp;
    const ulonglong2* wh1 = g_Wp + (3*32 + q*8) * 192 + jp;
    float bh0a = 0.f, bh0b = 0.f, bi1a = 0.f, bi1b = 0.f, bh1a = 0.f, bh1b = 0.f;
    if (q == 0) {
        bh0a = bhh[jp];        bh0b = bhh[jp + 192];
        bi1a = bih[G_ + jp];   bi1b = bih[G_ + jp + 192];
        bh1a = bhh[G_ + jp];   bh1b = bhh[G_ + jp + 192];
    }
    const ull* h0q = h0p + q * 16 * SU;
    const ull* h1q = h1p + q * 16 * SU;
    const ull* bpq = bp  + q * 16 * SU;

    float* h0pf = (float*)h0p;
    float* h1pf = (float*)h1p;
    float* bpf  = (float*)bp;

    // cp.async mapping: 768 thr = 8 rows x 96 float4 columns
    const int cr = tid / 96;
    const int cl = tid - cr * 96;
    uint32_t sgi_dst = (uint32_t)__cvta_generic_to_shared(sgi + cr * G_ + 4 * cl);
    const float* gi0src = g_gi0 + ((size_t)(b0 + cr) * T_) * G_ + 4 * cl;

    __syncthreads();

    for (int t = 0; t < T_; t++) {
        // async-load gi0 row (bias included) straight into gate buffer
        cpasync16(sgi_dst, gi0src);
        asm volatile("cp.async.commit_group;" ::: "memory");
        gi0src += G_;
        if (tid >= 704 && tid < 712) {
            float m = mask[(b0 + tid - 704) * T_ + t];
            skeep[tid - 704] = (m != 0.0f) ? 1.0f : 0.0f;
        }

        // ---------- layer 0: gh ----------
        float gh0[2][8];
        mv2j<8>(h0q, wh0, gh0, bh0a, bh0b);
        if (q) {
#pragma unroll
            for (int jj = 0; jj < 2; jj++)
#pragma unroll
                for (int r = 0; r < 8; r++)
                    psA[(q-1)*PSQ + (jj*192 + jp)*9 + r] = gh0[jj][r];
        }
        asm volatile("cp.async.wait_group 0;" ::: "memory");
        __syncthreads();                                          // B1

        if (q == 0) {
#pragma unroll
            for (int jj = 0; jj < 2; jj++) {
                int j = jp + jj * 192;
#pragma unroll
                for (int r = 0; r < 8; r++) {
                    int pidx = (jj*192 + jp)*9 + r;
                    float ghT = gh0[jj][r] + psA[pidx] + psA[PSQ + pidx] + psA[2*PSQ + pidx];
                    if (j < 256)
                        sgi[r * G_ + j] = sigmoid_fast(sgi[r * G_ + j] + ghT);
                    else
                        shn[r * H_ + (j - 256)] = ghT;            // sgi keeps gi0 (= inn)
                }
            }
        }
        __syncthreads();                                          // B2

        if (tid < 512) {
            int j  = tid & 127;
            int r0 = (tid >> 7) * 2;
#pragma unroll
            for (int rr = 0; rr < 2; rr++) {
                int r = r0 + rr;
                float rv  = sgi[r * G_ + j];
                float zv  = sgi[r * G_ + H_ + j];
                float inn = sgi[r * G_ + 2 * H_ + j];
                float hn  = shn[r * H_ + j];
                float nv  = tanh_fast(fmaf(rv, hn, inn));
                float ho  = h0pf[PIDX(j, r)];
                float hw  = fmaf(zv, ho - nv, nv);
                bpf [PIDX(j, r)] = hw;
                h0pf[PIDX(j, r)] = hw * skeep[r];
            }
        }
        __syncthreads();                                          // B3

        // ---------- layer 1: gi then gh ----------
        float gi1[2][8];
        mv2j<8>(bpq, wi1, gi1, bi1a, bi1b);
        if (q) {
#pragma unroll
            for (int jj = 0; jj < 2; jj++)
#pragma unroll
                for (int r = 0; r < 8; r++)
                    psA[(q-1)*PSQ + (jj*192 + jp)*9 + r] = gi1[jj][r];
        }
        float gh1[2][8];
        mv2j<8>(h1q, wh1, gh1, bh1a, bh1b);
        if (q) {
#pragma unroll
            for (int jj = 0; jj < 2; jj++)
#pragma unroll
                for (int r = 0; r < 8; r++)
                    psB[(q-1)*PSQ + (jj*192 + jp)*9 + r] = gh1[jj][r];
        }
        __syncthreads();                                          // B4

        if (q == 0) {
#pragma unroll
            for (int jj = 0; jj < 2; jj++) {
                int j = jp + jj * 192;
#pragma unroll
                for (int r = 0; r < 8; r++) {
                    int pidx = (jj*192 + jp)*9 + r;
                    float giT = gi1[jj][r] + psA[pidx] + psA[PSQ + pidx] + psA[2*PSQ + pidx];
                    float ghT = gh1[jj][r] + psB[pidx] + psB[PSQ + pidx] + psB[2*PSQ + pidx];
                    if (j < 256) {
                        sgi[r * G_ + j] = sigmoid_fast(giT + ghT);
                    } else {
                        sgi[r * G_ + j]         = giT;
                        shn[r * H_ + (j - 256)] = ghT;
                    }
                }
            }
        }
        __syncthreads();                                          // B5

        if (tid < 512) {
            int j  = tid & 127;
            int r0 = (tid >> 7) * 2;
#pragma unroll
            for (int rr = 0; rr < 2; rr++) {
                int r = r0 + rr;
                float rv  = sgi[r * G_ + j];
                float zv  = sgi[r * G_ + H_ + j];
                float inn = sgi[r * G_ + 2 * H_ + j];
                float hn  = shn[r * H_ + j];
                float nv  = tanh_fast(fmaf(rv, hn, inn));
                float ho  = h1pf[PIDX(j, r)];
                float hw  = fmaf(zv, ho - nv, nv);
                g_h1[((size_t)(b0 + r) * T_ + t) * H_ + j] = hw;
                h1pf[PIDX(j, r)] = hw * skeep[r];
            }
        }
        __syncthreads();                                          // B6
    }
}

// out2/out3 gathers
__global__ void gather_kernel(const int* __restrict__ il,
                              const int* __restrict__ neg,
                              const float4* __restrict__ emb4,
                              float4* __restrict__ out2,
                              float4* __restrict__ out3)
{
    int idx = blockIdx.x * blockDim.x + threadIdx.x;
    const int n4 = B_ * (T_ - 1) * (H_ / 4);
    if (idx >= n4) return;
    int k4 = idx & 31;
    int bt = idx >> 5;
    int b  = bt / (T_ - 1);
    int t  = bt - b * (T_ - 1);
    int p  = il [b * T_ + t + 1];
    int qd = neg[b * T_ + t];
    out2[idx] = __ldg(emb4 + (size_t)p  * 32 + k4);
    out3[idx] = __ldg(emb4 + (size_t)qd * 32 + k4);
}

#define LOOP_SMEM (3*NPBUF*8 + (ROWS*G_ + ROWS*H_ + 6*PSQ + 8)*4 + 32)

extern "C" void kernel_launch(void* const* d_in, const int* in_sizes, int n_in,
                              void* d_out, int out_size)
{
    const int*   il    = (const int*)  d_in[0];
    const float* mask  = (const float*)d_in[1];
    const int*   neg   = (const int*)  d_in[2];
    const float* emb   = (const float*)d_in[3];
    const float* Wih   = (const float*)d_in[4];
    const float* Whh   = (const float*)d_in[5];
    const float* bih   = (const float*)d_in[6];
    const float* bhh   = (const float*)d_in[7];
    const float* h2o_w = (const float*)d_in[8];
    const float* h2o_b = (const float*)d_in[9];

    float* out  = (float*)d_out;
    float* out1 = out;
    float* out2 = out1 + (size_t)B_ * (T_ - 1) * H_;
    float* out3 = out2 + (size_t)B_ * (T_ - 1) * H_;
    float* out4 = out3 + (size_t)B_ * (T_ - 1) * H_;

    cudaFuncSetAttribute(gru_loop, cudaFuncAttributeMaxDynamicSharedMemorySize, LOOP_SMEM);

    const int nprep = NWP + 32 * 128;
    prep_kernel<<<(nprep + 255) / 256, 256>>>(Wih, Whh, h2o_w);

    const int n4 = B_ * (T_ - 1) * (H_ / 4);
    gather_kernel<<<(n4 + 255) / 256, 256>>>(il, neg, (const float4*)emb,
                                             (float4*)out2, (float4*)out3);

    pre_kernel<<<NBT / 32, 768>>>(il, emb, bih, out4);

    gru_loop<<<NCTA, NTHR, LOOP_SMEM>>>(mask, bih, bhh);

    post_kernel<<<NBT / ROWS, 128>>>(h2o_b, out1, out4);
}

// round 9
// speedup vs baseline: 1.4949x; 1.1552x over previous
#include <cuda_runtime.h>
#include <cuda_fp16.h>
#include <cstdint>

#define B_   1024
#define T_   200
#define H_   128
#define G_   384
#define ROWS 8
#define NCTA 128
#define NTHR 768
#define NBT  (B_*T_)

#define SU 10
#define NPBUF (64*SU)
#define PIDX(u,r) (((u)>>1)*(2*SU) + 2*(r) + ((u)&1))
#define PSQ (384*9)          // floats per k-quarter psum slice

typedef unsigned long long ull;

#define NWP (4*32*192)
__device__ ulonglong2 g_Wp[NWP];          // paired fp16 weights: [m][k4][jp] -> {j, j+192}
__device__ ull        g_Wo[32*128];       // h2o fp16 [k4][oi]
__device__ float g_gi0[(size_t)NBT * G_]; // precomputed layer-0 input gates (+bias)
__device__ float g_h1 [(size_t)NBT * H_]; // raw layer-1 hidden outputs

// ---- packed f32x2 helpers ----
__device__ __forceinline__ ull pack2(float a, float b) {
    ull r; asm("mov.b64 %0,{%1,%2};" : "=l"(r) : "f"(a), "f"(b)); return r;
}
__device__ __forceinline__ void fma2(ull& c, ull a, ull b) {
    asm("fma.rn.f32x2 %0,%1,%2,%0;" : "+l"(c) : "l"(a), "l"(b));
}
__device__ __forceinline__ float2 unpack2(ull v) {
    float lo, hi; asm("mov.b64 {%0,%1},%2;" : "=f"(lo), "=f"(hi) : "l"(v));
    return make_float2(lo, hi);
}
__device__ __forceinline__ void cvt4(ull w, ull& A, ull& B) {
    uint32_t lo = (uint32_t)w, hi = (uint32_t)(w >> 32);
    __half2 h0 = *reinterpret_cast<__half2*>(&lo);
    __half2 h1 = *reinterpret_cast<__half2*>(&hi);
    float2 f0 = __half22float2(h0);
    float2 f1 = __half22float2(h1);
    A = pack2(f0.x, f0.y);
    B = pack2(f1.x, f1.y);
}
__device__ __forceinline__ ulonglong2 ldg128(const ulonglong2* p) {
    ulonglong2 v;
    asm("ld.global.nc.v2.u64 {%0,%1},[%2];" : "=l"(v.x), "=l"(v.y) : "l"(p));
    return v;
}
__device__ __forceinline__ float sigmoid_fast(float x) {
    return 1.0f / (1.0f + __expf(-x));
}
__device__ __forceinline__ float tanh_fast(float x) {
    float ax = fabsf(x);
    float e  = __expf(-2.0f * ax);
    float t  = __fdividef(1.0f - e, 1.0f + e);
    return copysignf(t, x);
}
__device__ __forceinline__ ull pack4h(const float* row) {
    ull a = (ull)__half_as_ushort(__float2half_rn(row[0]));
    ull b = (ull)__half_as_ushort(__float2half_rn(row[1]));
    ull c = (ull)__half_as_ushort(__float2half_rn(row[2]));
    ull d = (ull)__half_as_ushort(__float2half_rn(row[3]));
    return a | (b << 16) | (c << 32) | (d << 48);
}
__device__ __forceinline__ void cpasync16(uint32_t dst, const void* src) {
    asm volatile("cp.async.ca.shared.global [%0],[%1],16;" :: "r"(dst), "l"(src));
}

// One-time weight re-layout (fp16 pairs).  m: 0=Wih0, 1=Whh0, 2=Wih1, 3=Whh1
__global__ void prep_kernel(const float* __restrict__ Wih,
                            const float* __restrict__ Whh,
                            const float* __restrict__ h2o_w)
{
    int idx = blockIdx.x * blockDim.x + threadIdx.x;
    if (idx < NWP) {
        int jp = idx % 192;
        int k4 = (idx / 192) % 32;
        int m  = idx / (192 * 32);
        int l  = m >> 1;
        const float* src = ((m & 1) == 0) ? Wih : Whh;
        ulonglong2 v;
        v.x = pack4h(src + ((size_t)l * G_ + jp      ) * H_ + 4 * k4);
        v.y = pack4h(src + ((size_t)l * G_ + jp + 192) * H_ + 4 * k4);
        g_Wp[idx] = v;
    } else if (idx < NWP + 32 * 128) {
        int i2 = idx - NWP;
        int oi = i2 % H_;
        int k4 = i2 / H_;
        g_Wo[i2] = pack4h(h2o_w + oi * H_ + 4 * k4);
    }
}

// 2j matvec partial
template<int NK4>
__device__ __forceinline__ void mv2j(const ull* __restrict__ act,
                                     const ulonglong2* __restrict__ w,
                                     float out[2][8], float b0, float b1)
{
    ull acc[2][8];
#pragma unroll
    for (int r = 0; r < 8; r++) { acc[0][r] = pack2(b0, 0.f); acc[1][r] = pack2(b1, 0.f); }
#pragma unroll 8
    for (int k4 = 0; k4 < NK4; k4++) {
        ulonglong2 ww = ldg128(w + k4 * 192);
        ull w0A, w0B, w1A, w1B;
        cvt4(ww.x, w0A, w0B);
        cvt4(ww.y, w1A, w1B);
        const ull* xa = act + 2 * k4 * SU;
#pragma unroll
        for (int p = 0; p < 4; p++) {
            ulonglong2 xv = *(const ulonglong2*)(xa + 2 * p);
            fma2(acc[0][2*p],   w0A, xv.x);
            fma2(acc[0][2*p+1], w0A, xv.y);
            fma2(acc[1][2*p],   w1A, xv.x);
            fma2(acc[1][2*p+1], w1A, xv.y);
        }
#pragma unroll
        for (int p = 0; p < 4; p++) {
            ulonglong2 xv = *(const ulonglong2*)(xa + SU + 2 * p);
            fma2(acc[0][2*p],   w0B, xv.x);
            fma2(acc[0][2*p+1], w0B, xv.y);
            fma2(acc[1][2*p],   w1B, xv.x);
            fma2(acc[1][2*p+1], w1B, xv.y);
        }
    }
#pragma unroll
    for (int jj = 0; jj < 2; jj++)
#pragma unroll
        for (int r = 0; r < 8; r++) {
            float2 s = unpack2(acc[jj][r]);
            out[jj][r] = s.x + s.y;
        }
}

// ===================== pre-kernel: gi0 + out4-low =====================
__global__ void __launch_bounds__(768)
pre_kernel(const int* __restrict__ il,
           const float* __restrict__ emb,
           const float* __restrict__ bih,
           float* __restrict__ out4)
{
    __shared__ __align__(16) ull xq[4 * NPBUF];
    const int tid = threadIdx.x;
    const int bt0 = blockIdx.x * 32;

    for (int i = tid; i < 1024; i += 768) {
        int row = i >> 5, k4 = i & 31;
        int tok = il[bt0 + row];
        float4 v = __ldg((const float4*)emb + (size_t)tok * 32 + k4);
        float* base = (float*)(xq + (row >> 3) * NPBUF);
        int r = row & 7;
        base[PIDX(4*k4 + 0, r)] = v.x;
        base[PIDX(4*k4 + 1, r)] = v.y;
        base[PIDX(4*k4 + 2, r)] = v.z;
        base[PIDX(4*k4 + 3, r)] = v.w;
        ((float4*)(out4 + (size_t)(bt0 + row) * 256))[k4] = v;
    }
    __syncthreads();

    const int rg = tid / 192, jp = tid - rg * 192;
    float out[2][8];
    mv2j<32>(xq + rg * NPBUF, g_Wp + jp, out, bih[jp], bih[jp + 192]);
#pragma unroll
    for (int jj = 0; jj < 2; jj++)
#pragma unroll
        for (int r = 0; r < 8; r++)
            g_gi0[(size_t)(bt0 + rg * 8 + r) * G_ + jp + jj * 192] = out[jj][r];
}

// ===================== post-kernel: h2o GEMM + tanh =====================
__global__ void __launch_bounds__(128)
post_kernel(const float* __restrict__ h2o_b,
            float* __restrict__ out1,
            float* __restrict__ out4)
{
    __shared__ __align__(16) ull xp[NPBUF];
    const int j   = threadIdx.x;
    const int bt0 = blockIdx.x * ROWS;
    float* xpf = (float*)xp;

#pragma unroll
    for (int r = 0; r < ROWS; r++)
        xpf[PIDX(j, r)] = g_h1[(size_t)(bt0 + r) * H_ + j];
    __syncthreads();

    const ull* w = g_Wo + j;
    float ob = h2o_b[j];
    ull acc[ROWS];
#pragma unroll
    for (int r = 0; r < ROWS; r++) acc[r] = pack2(ob, 0.0f);
#pragma unroll 4
    for (int k4 = 0; k4 < 32; k4++) {
        ull wA, wB; cvt4(__ldg(w + k4 * H_), wA, wB);
        const ull* xa = xp + (2 * k4) * SU;
#pragma unroll
        for (int p = 0; p < 4; p++) {
            ulonglong2 xv = *(const ulonglong2*)(xa + 2 * p);
            fma2(acc[2*p],   wA, xv.x);
            fma2(acc[2*p+1], wA, xv.y);
        }
#pragma unroll
        for (int p = 0; p < 4; p++) {
            ulonglong2 xv = *(const ulonglong2*)(xa + SU + 2 * p);
            fma2(acc[2*p],   wB, xv.x);
            fma2(acc[2*p+1], wB, xv.y);
        }
    }
#pragma unroll
    for (int r = 0; r < ROWS; r++) {
        float2 s = unpack2(acc[r]);
        float o  = tanh_fast(s.x + s.y);
        int bt = bt0 + r;
        int b  = bt / T_;
        int t  = bt - b * T_;
        out4[(size_t)bt * 256 + H_ + j] = o;
        if (t < T_ - 1)
            out1[((size_t)b * (T_ - 1) + t) * H_ + j] = o;
    }
}

// ===================== recurrence loop =====================
#define S4(buf, idx) ((buf)[idx] + (buf)[PSQ + (idx)] + (buf)[2*PSQ + (idx)] + (buf)[3*PSQ + (idx)])

__global__ void __launch_bounds__(NTHR, 1)
gru_loop(const float* __restrict__ mask,
         const float* __restrict__ bih,
         const float* __restrict__ bhh)
{
    extern __shared__ __align__(16) char dsm[];
    ull*   bp    = (ull*)dsm;                         // layer0 out pairs
    ull*   h0p   = bp  + NPBUF;
    ull*   h1p   = h0p + NPBUF;
    float* sgi   = (float*)(h1p + NPBUF);             // gi0 buffer [r][j]
    float* psA   = sgi + ROWS * G_;                   // 4*PSQ
    float* psB   = psA + 4 * PSQ;                     // 4*PSQ
    float* skeep = psB + 4 * PSQ;                     // 8

    const int tid = threadIdx.x;
    const int q   = tid / 192;       // k-quarter
    const int jp  = tid - q * 192;   // gate pair index
    const int b0  = blockIdx.x * ROWS;

    for (int i = tid; i < NPBUF; i += NTHR) { h0p[i] = 0ull; h1p[i] = 0ull; }

    const ulonglong2* wh0 = g_Wp + (1*32 + q*8) * 192 + jp;
    const ulonglong2* wi1 = g_Wp + (2*32 + q*8) * 192 + jp;
    const ulonglong2* wh1 = g_Wp + (3*32 + q*8) * 192 + jp;
    float bh0a = 0.f, bh0b = 0.f, bi1a = 0.f, bi1b = 0.f, bh1a = 0.f, bh1b = 0.f;
    if (q == 0) {
        bh0a = bhh[jp];        bh0b = bhh[jp + 192];
        bi1a = bih[G_ + jp];   bi1b = bih[G_ + jp + 192];
        bh1a = bhh[G_ + jp];   bh1b = bhh[G_ + jp + 192];
    }
    const ull* h0q = h0p + q * 16 * SU;
    const ull* h1q = h1p + q * 16 * SU;
    const ull* bpq = bp  + q * 16 * SU;

    float* h0pf = (float*)h0p;
    float* h1pf = (float*)h1p;
    float* bpf  = (float*)bp;

    // psum write bases for this thread: slice q, columns jp and jp+192
    float* psA0 = psA + q * PSQ + jp * 9;
    float* psA1 = psA + q * PSQ + (jp + 192) * 9;
    float* psB0 = psB + q * PSQ + jp * 9;
    float* psB1 = psB + q * PSQ + (jp + 192) * 9;

    // cp.async mapping: 768 thr = 8 rows x 96 float4 columns
    const int cr = tid / 96;
    const int cl = tid - cr * 96;
    uint32_t sgi_dst = (uint32_t)__cvta_generic_to_shared(sgi + cr * G_ + 4 * cl);
    const float* gi0src = g_gi0 + ((size_t)(b0 + cr) * T_) * G_ + 4 * cl;

    // fused phase mapping (512 threads): col, row pair
    const int col = tid & 127;
    const int rb  = (tid >> 7) * 2;

    __syncthreads();

    for (int t = 0; t < T_; t++) {
        // async-load gi0 row (bias included) into gate buffer
        cpasync16(sgi_dst, gi0src);
        asm volatile("cp.async.commit_group;" ::: "memory");
        gi0src += G_;
        if (tid >= 704 && tid < 712) {
            float m = mask[(b0 + tid - 704) * T_ + t];
            skeep[tid - 704] = (m != 0.0f) ? 1.0f : 0.0f;
        }

        // ---------- phase A: layer-0 gh partials ----------
        {
            float gh0[2][8];
            mv2j<8>(h0q, wh0, gh0, bh0a, bh0b);
#pragma unroll
            for (int r = 0; r < 8; r++) { psA0[r] = gh0[0][r]; psA1[r] = gh0[1][r]; }
        }
        asm volatile("cp.async.wait_group 0;" ::: "memory");
        __syncthreads();                                          // B1

        // ---------- phase B: fused reduce + gates + layer-0 update ----------
        if (tid < 512) {
#pragma unroll
            for (int rr = 0; rr < 2; rr++) {
                int r = rb + rr;
                int i_r = col * 9 + r, i_z = (128 + col) * 9 + r, i_n = (256 + col) * 9 + r;
                float rv  = sigmoid_fast(sgi[r * G_ + col]       + S4(psA, i_r));
                float zv  = sigmoid_fast(sgi[r * G_ + 128 + col] + S4(psA, i_z));
                float inn = sgi[r * G_ + 256 + col];
                float hn  = S4(psA, i_n);
                float nv  = tanh_fast(fmaf(rv, hn, inn));
                float ho  = h0pf[PIDX(col, r)];
                float hw  = fmaf(zv, ho - nv, nv);
                bpf [PIDX(col, r)] = hw;
                h0pf[PIDX(col, r)] = hw * skeep[r];
            }
        }
        __syncthreads();                                          // B2

        // ---------- phase C: layer-1 gi/gh partials ----------
        {
            float gi1[2][8];
            mv2j<8>(bpq, wi1, gi1, bi1a, bi1b);
#pragma unroll
            for (int r = 0; r < 8; r++) { psA0[r] = gi1[0][r]; psA1[r] = gi1[1][r]; }
        }
        {
            float gh1[2][8];
            mv2j<8>(h1q, wh1, gh1, bh1a, bh1b);
#pragma unroll
            for (int r = 0; r < 8; r++) { psB0[r] = gh1[0][r]; psB1[r] = gh1[1][r]; }
        }
        __syncthreads();                                          // B3

        // ---------- phase D: fused reduce + gates + layer-1 update ----------
        if (tid < 512) {
#pragma unroll
            for (int rr = 0; rr < 2; rr++) {
                int r = rb + rr;
                int i_r = col * 9 + r, i_z = (128 + col) * 9 + r, i_n = (256 + col) * 9 + r;
                float rv  = sigmoid_fast(S4(psA, i_r) + S4(psB, i_r));
                float zv  = sigmoid_fast(S4(psA, i_z) + S4(psB, i_z));
                float inn = S4(psA, i_n);
                float hn  = S4(psB, i_n);
                float nv  = tanh_fast(fmaf(rv, hn, inn));
                float ho  = h1pf[PIDX(col, r)];
                float hw  = fmaf(zv, ho - nv, nv);
                g_h1[((size_t)(b0 + r) * T_ + t) * H_ + col] = hw;
                h1pf[PIDX(col, r)] = hw * skeep[r];
            }
        }
        __syncthreads();                                          // B4
    }
}

// out2/out3 gathers
__global__ void gather_kernel(const int* __restrict__ il,
                              const int* __restrict__ neg,
                              const float4* __restrict__ emb4,
                              float4* __restrict__ out2,
                              float4* __restrict__ out3)
{
    int idx = blockIdx.x * blockDim.x + threadIdx.x;
    const int n4 = B_ * (T_ - 1) * (H_ / 4);
    if (idx >= n4) return;
    int k4 = idx & 31;
    int bt = idx >> 5;
    int b  = bt / (T_ - 1);
    int t  = bt - b * (T_ - 1);
    int p  = il [b * T_ + t + 1];
    int qd = neg[b * T_ + t];
    out2[idx] = __ldg(emb4 + (size_t)p  * 32 + k4);
    out3[idx] = __ldg(emb4 + (size_t)qd * 32 + k4);
}

#define LOOP_SMEM (3*NPBUF*8 + (ROWS*G_ + 8*PSQ + 8)*4 + 32)

extern "C" void kernel_launch(void* const* d_in, const int* in_sizes, int n_in,
                              void* d_out, int out_size)
{
    const int*   il    = (const int*)  d_in[0];
    const float* mask  = (const float*)d_in[1];
    const int*   neg   = (const int*)  d_in[2];
    const float* emb   = (const float*)d_in[3];
    const float* Wih   = (const float*)d_in[4];
    const float* Whh   = (const float*)d_in[5];
    const float* bih   = (const float*)d_in[6];
    const float* bhh   = (const float*)d_in[7];
    const float* h2o_w = (const float*)d_in[8];
    const float* h2o_b = (const float*)d_in[9];

    float* out  = (float*)d_out;
    float* out1 = out;
    float* out2 = out1 + (size_t)B_ * (T_ - 1) * H_;
    float* out3 = out2 + (size_t)B_ * (T_ - 1) * H_;
    float* out4 = out3 + (size_t)B_ * (T_ - 1) * H_;

    cudaFuncSetAttribute(gru_loop, cudaFuncAttributeMaxDynamicSharedMemorySize, LOOP_SMEM);

    const int nprep = NWP + 32 * 128;
    prep_kernel<<<(nprep + 255) / 256, 256>>>(Wih, Whh, h2o_w);

    const int n4 = B_ * (T_ - 1) * (H_ / 4);
    gather_kernel<<<(n4 + 255) / 256, 256>>>(il, neg, (const float4*)emb,
                                             (float4*)out2, (float4*)out3);

    pre_kernel<<<NBT / 32, 768>>>(il, emb, bih, out4);

    gru_loop<<<NCTA, NTHR, LOOP_SMEM>>>(mask, bih, bhh);

    post_kernel<<<NBT / ROWS, 128>>>(h2o_b, out1, out4);
}

// round 10
// speedup vs baseline: 1.4963x; 1.0010x over previous
#include <cuda_runtime.h>
#include <cuda_fp16.h>
#include <cstdint>

#define B_   1024
#define T_   200
#define H_   128
#define G_   384
#define ROWS 8
#define NCTA 128
#define NTHR 768
#define NBT  (B_*T_)

#define SU 10
#define NPBUF (64*SU)
#define PIDX(u,r) (((u)>>1)*(2*SU) + 2*(r) + ((u)&1))
#define PSQ (384*9)          // floats per k-quarter psum slice

typedef unsigned long long ull;

#define NWP (4*32*192)
__device__ ulonglong2 g_Wp[NWP];          // paired fp16 weights: [m][k4][jp] -> {j, j+192}
__device__ ull        g_Wo[32*128];       // h2o fp16 [k4][oi]
__device__ float g_gi0[(size_t)NBT * G_]; // precomputed layer-0 input gates (+bias)
__device__ float g_h1 [(size_t)NBT * H_]; // raw layer-1 hidden outputs

// ---- packed f32x2 helpers ----
__device__ __forceinline__ ull pack2(float a, float b) {
    ull r; asm("mov.b64 %0,{%1,%2};" : "=l"(r) : "f"(a), "f"(b)); return r;
}
__device__ __forceinline__ void fma2(ull& c, ull a, ull b) {
    asm("fma.rn.f32x2 %0,%1,%2,%0;" : "+l"(c) : "l"(a), "l"(b));
}
__device__ __forceinline__ float2 unpack2(ull v) {
    float lo, hi; asm("mov.b64 {%0,%1},%2;" : "=f"(lo), "=f"(hi) : "l"(v));
    return make_float2(lo, hi);
}
__device__ __forceinline__ void cvt4(ull w, ull& A, ull& B) {
    uint32_t lo = (uint32_t)w, hi = (uint32_t)(w >> 32);
    __half2 h0 = *reinterpret_cast<__half2*>(&lo);
    __half2 h1 = *reinterpret_cast<__half2*>(&hi);
    float2 f0 = __half22float2(h0);
    float2 f1 = __half22float2(h1);
    A = pack2(f0.x, f0.y);
    B = pack2(f1.x, f1.y);
}
__device__ __forceinline__ ulonglong2 ldg128(const ulonglong2* p) {
    ulonglong2 v;
    asm("ld.global.nc.v2.u64 {%0,%1},[%2];" : "=l"(v.x), "=l"(v.y) : "l"(p));
    return v;
}
__device__ __forceinline__ float sigmoid_fast(float x) {
    return 1.0f / (1.0f + __expf(-x));
}
__device__ __forceinline__ float tanh_fast(float x) {
    float ax = fabsf(x);
    float e  = __expf(-2.0f * ax);
    float t  = __fdividef(1.0f - e, 1.0f + e);
    return copysignf(t, x);
}
__device__ __forceinline__ ull pack4h(const float* row) {
    ull a = (ull)__half_as_ushort(__float2half_rn(row[0]));
    ull b = (ull)__half_as_ushort(__float2half_rn(row[1]));
    ull c = (ull)__half_as_ushort(__float2half_rn(row[2]));
    ull d = (ull)__half_as_ushort(__float2half_rn(row[3]));
    return a | (b << 16) | (c << 32) | (d << 48);
}
__device__ __forceinline__ void cpasync16(uint32_t dst, const void* src) {
    asm volatile("cp.async.ca.shared.global [%0],[%1],16;" :: "r"(dst), "l"(src));
}

// One-time weight re-layout (fp16 pairs).  m: 0=Wih0, 1=Whh0, 2=Wih1, 3=Whh1
__global__ void prep_kernel(const float* __restrict__ Wih,
                            const float* __restrict__ Whh,
                            const float* __restrict__ h2o_w)
{
    int idx = blockIdx.x * blockDim.x + threadIdx.x;
    if (idx < NWP) {
        int jp = idx % 192;
        int k4 = (idx / 192) % 32;
        int m  = idx / (192 * 32);
        int l  = m >> 1;
        const float* src = ((m & 1) == 0) ? Wih : Whh;
        ulonglong2 v;
        v.x = pack4h(src + ((size_t)l * G_ + jp      ) * H_ + 4 * k4);
        v.y = pack4h(src + ((size_t)l * G_ + jp + 192) * H_ + 4 * k4);
        g_Wp[idx] = v;
    } else if (idx < NWP + 32 * 128) {
        int i2 = idx - NWP;
        int oi = i2 % H_;
        int k4 = i2 / H_;
        g_Wo[i2] = pack4h(h2o_w + oi * H_ + 4 * k4);
    }
}

// 2j matvec partial
template<int NK4>
__device__ __forceinline__ void mv2j(const ull* __restrict__ act,
                                     const ulonglong2* __restrict__ w,
                                     float out[2][8], float b0, float b1)
{
    ull acc[2][8];
#pragma unroll
    for (int r = 0; r < 8; r++) { acc[0][r] = pack2(b0, 0.f); acc[1][r] = pack2(b1, 0.f); }
#pragma unroll 8
    for (int k4 = 0; k4 < NK4; k4++) {
        ulonglong2 ww = ldg128(w + k4 * 192);
        ull w0A, w0B, w1A, w1B;
        cvt4(ww.x, w0A, w0B);
        cvt4(ww.y, w1A, w1B);
        const ull* xa = act + 2 * k4 * SU;
#pragma unroll
        for (int p = 0; p < 4; p++) {
            ulonglong2 xv = *(const ulonglong2*)(xa + 2 * p);
            fma2(acc[0][2*p],   w0A, xv.x);
            fma2(acc[0][2*p+1], w0A, xv.y);
            fma2(acc[1][2*p],   w1A, xv.x);
            fma2(acc[1][2*p+1], w1A, xv.y);
        }
#pragma unroll
        for (int p = 0; p < 4; p++) {
            ulonglong2 xv = *(const ulonglong2*)(xa + SU + 2 * p);
            fma2(acc[0][2*p],   w0B, xv.x);
            fma2(acc[0][2*p+1], w0B, xv.y);
            fma2(acc[1][2*p],   w1B, xv.x);
            fma2(acc[1][2*p+1], w1B, xv.y);
        }
    }
#pragma unroll
    for (int jj = 0; jj < 2; jj++)
#pragma unroll
        for (int r = 0; r < 8; r++) {
            float2 s = unpack2(acc[jj][r]);
            out[jj][r] = s.x + s.y;
        }
}

// ===================== pre-kernel: gi0 + out4-low =====================
__global__ void __launch_bounds__(768)
pre_kernel(const int* __restrict__ il,
           const float* __restrict__ emb,
           const float* __restrict__ bih,
           float* __restrict__ out4)
{
    __shared__ __align__(16) ull xq[4 * NPBUF];
    const int tid = threadIdx.x;
    const int bt0 = blockIdx.x * 32;

    for (int i = tid; i < 1024; i += 768) {
        int row = i >> 5, k4 = i & 31;
        int tok = il[bt0 + row];
        float4 v = __ldg((const float4*)emb + (size_t)tok * 32 + k4);
        float* base = (float*)(xq + (row >> 3) * NPBUF);
        int r = row & 7;
        base[PIDX(4*k4 + 0, r)] = v.x;
        base[PIDX(4*k4 + 1, r)] = v.y;
        base[PIDX(4*k4 + 2, r)] = v.z;
        base[PIDX(4*k4 + 3, r)] = v.w;
        ((float4*)(out4 + (size_t)(bt0 + row) * 256))[k4] = v;
    }
    __syncthreads();

    const int rg = tid / 192, jp = tid - rg * 192;
    float out[2][8];
    mv2j<32>(xq + rg * NPBUF, g_Wp + jp, out, bih[jp], bih[jp + 192]);
#pragma unroll
    for (int jj = 0; jj < 2; jj++)
#pragma unroll
        for (int r = 0; r < 8; r++)
            g_gi0[(size_t)(bt0 + rg * 8 + r) * G_ + jp + jj * 192] = out[jj][r];
}

// ===================== post-kernel: h2o GEMM + tanh =====================
__global__ void __launch_bounds__(128)
post_kernel(const float* __restrict__ h2o_b,
            float* __restrict__ out1,
            float* __restrict__ out4)
{
    __shared__ __align__(16) ull xp[NPBUF];
    const int j   = threadIdx.x;
    const int bt0 = blockIdx.x * ROWS;
    float* xpf = (float*)xp;

#pragma unroll
    for (int r = 0; r < ROWS; r++)
        xpf[PIDX(j, r)] = g_h1[(size_t)(bt0 + r) * H_ + j];
    __syncthreads();

    const ull* w = g_Wo + j;
    float ob = h2o_b[j];
    ull acc[ROWS];
#pragma unroll
    for (int r = 0; r < ROWS; r++) acc[r] = pack2(ob, 0.0f);
#pragma unroll 4
    for (int k4 = 0; k4 < 32; k4++) {
        ull wA, wB; cvt4(__ldg(w + k4 * H_), wA, wB);
        const ull* xa = xp + (2 * k4) * SU;
#pragma unroll
        for (int p = 0; p < 4; p++) {
            ulonglong2 xv = *(const ulonglong2*)(xa + 2 * p);
            fma2(acc[2*p],   wA, xv.x);
            fma2(acc[2*p+1], wA, xv.y);
        }
#pragma unroll
        for (int p = 0; p < 4; p++) {
            ulonglong2 xv = *(const ulonglong2*)(xa + SU + 2 * p);
            fma2(acc[2*p],   wB, xv.x);
            fma2(acc[2*p+1], wB, xv.y);
        }
    }
#pragma unroll
    for (int r = 0; r < ROWS; r++) {
        float2 s = unpack2(acc[r]);
        float o  = tanh_fast(s.x + s.y);
        int bt = bt0 + r;
        int b  = bt / T_;
        int t  = bt - b * T_;
        out4[(size_t)bt * 256 + H_ + j] = o;
        if (t < T_ - 1)
            out1[((size_t)b * (T_ - 1) + t) * H_ + j] = o;
    }
}

// ===================== recurrence loop =====================
#define S4(buf, idx) ((buf)[idx] + (buf)[PSQ + (idx)] + (buf)[2*PSQ + (idx)] + (buf)[3*PSQ + (idx)])

__global__ void __launch_bounds__(NTHR, 1)
gru_loop(const float* __restrict__ mask,
         const float* __restrict__ bih,
         const float* __restrict__ bhh)
{
    extern __shared__ __align__(16) char dsm[];
    ull*   bp    = (ull*)dsm;                         // layer0 out pairs
    ull*   h0p   = bp  + NPBUF;
    ull*   h1p   = h0p + NPBUF;
    float* sgi   = (float*)(h1p + NPBUF);             // gi0 buffer [r][j]
    float* psA   = sgi + ROWS * G_;                   // 4*PSQ
    float* psB   = psA + 4 * PSQ;                     // 4*PSQ
    float* skeep = psB + 4 * PSQ;                     // 8

    const int tid = threadIdx.x;
    const int q   = tid / 192;       // k-quarter
    const int jp  = tid - q * 192;   // gate pair index
    const int b0  = blockIdx.x * ROWS;

    for (int i = tid; i < NPBUF; i += NTHR) { h0p[i] = 0ull; h1p[i] = 0ull; }

    const ulonglong2* wh0 = g_Wp + (1*32 + q*8) * 192 + jp;
    const ulonglong2* wi1 = g_Wp + (2*32 + q*8) * 192 + jp;
    const ulonglong2* wh1 = g_Wp + (3*32 + q*8) * 192 + jp;
    float bh0a = 0.f, bh0b = 0.f, bi1a = 0.f, bi1b = 0.f, bh1a = 0.f, bh1b = 0.f;
    if (q == 0) {
        bh0a = bhh[jp];        bh0b = bhh[jp + 192];
        bi1a = bih[G_ + jp];   bi1b = bih[G_ + jp + 192];
        bh1a = bhh[G_ + jp];   bh1b = bhh[G_ + jp + 192];
    }
    const ull* h0q = h0p + q * 16 * SU;
    const ull* h1q = h1p + q * 16 * SU;
    const ull* bpq = bp  + q * 16 * SU;

    float* h0pf = (float*)h0p;
    float* h1pf = (float*)h1p;
    float* bpf  = (float*)bp;

    // psum write bases for this thread: slice q, columns jp and jp+192
    float* psA0 = psA + q * PSQ + jp * 9;
    float* psA1 = psA + q * PSQ + (jp + 192) * 9;
    float* psB0 = psB + q * PSQ + jp * 9;
    float* psB1 = psB + q * PSQ + (jp + 192) * 9;

    // cp.async mapping: 768 thr = 8 rows x 96 float4 columns
    const int cr = tid / 96;
    const int cl = tid - cr * 96;
    uint32_t sgi_dst = (uint32_t)__cvta_generic_to_shared(sgi + cr * G_ + 4 * cl);
    const float* gi0src = g_gi0 + ((size_t)(b0 + cr) * T_) * G_ + 4 * cl;

    // fused phase mapping (512 threads): col, row pair
    const int col = tid & 127;
    const int rb  = (tid >> 7) * 2;

    __syncthreads();

    for (int t = 0; t < T_; t++) {
        // async-load gi0 row (bias included) into gate buffer
        cpasync16(sgi_dst, gi0src);
        asm volatile("cp.async.commit_group;" ::: "memory");
        gi0src += G_;
        if (tid >= 704 && tid < 712) {
            float m = mask[(b0 + tid - 704) * T_ + t];
            skeep[tid - 704] = (m != 0.0f) ? 1.0f : 0.0f;
        }

        // ---------- phase A: layer-0 gh partials ----------
        {
            float gh0[2][8];
            mv2j<8>(h0q, wh0, gh0, bh0a, bh0b);
#pragma unroll
            for (int r = 0; r < 8; r++) { psA0[r] = gh0[0][r]; psA1[r] = gh0[1][r]; }
        }
        asm volatile("cp.async.wait_group 0;" ::: "memory");
        __syncthreads();                                          // B1

        // ---------- phase B: fused reduce + gates + layer-0 update ----------
        if (tid < 512) {
#pragma unroll
            for (int rr = 0; rr < 2; rr++) {
                int r = rb + rr;
                int i_r = col * 9 + r, i_z = (128 + col) * 9 + r, i_n = (256 + col) * 9 + r;
                float rv  = sigmoid_fast(sgi[r * G_ + col]       + S4(psA, i_r));
                float zv  = sigmoid_fast(sgi[r * G_ + 128 + col] + S4(psA, i_z));
                float inn = sgi[r * G_ + 256 + col];
                float hn  = S4(psA, i_n);
                float nv  = tanh_fast(fmaf(rv, hn, inn));
                float ho  = h0pf[PIDX(col, r)];
                float hw  = fmaf(zv, ho - nv, nv);
                bpf [PIDX(col, r)] = hw;
                h0pf[PIDX(col, r)] = hw * skeep[r];
            }
        }
        __syncthreads();                                          // B2

        // ---------- phase C: layer-1 gi/gh partials ----------
        {
            float gi1[2][8];
            mv2j<8>(bpq, wi1, gi1, bi1a, bi1b);
#pragma unroll
            for (int r = 0; r < 8; r++) { psA0[r] = gi1[0][r]; psA1[r] = gi1[1][r]; }
        }
        {
            float gh1[2][8];
            mv2j<8>(h1q, wh1, gh1, bh1a, bh1b);
#pragma unroll
            for (int r = 0; r < 8; r++) { psB0[r] = gh1[0][r]; psB1[r] = gh1[1][r]; }
        }
        __syncthreads();                                          // B3

        // ---------- phase D: fused reduce + gates + layer-1 update ----------
        if (tid < 512) {
#pragma unroll
            for (int rr = 0; rr < 2; rr++) {
                int r = rb + rr;
                int i_r = col * 9 + r, i_z = (128 + col) * 9 + r, i_n = (256 + col) * 9 + r;
                float rv  = sigmoid_fast(S4(psA, i_r) + S4(psB, i_r));
                float zv  = sigmoid_fast(S4(psA, i_z) + S4(psB, i_z));
                float inn = S4(psA, i_n);
                float hn  = S4(psB, i_n);
                float nv  = tanh_fast(fmaf(rv, hn, inn));
                float ho  = h1pf[PIDX(col, r)];
                float hw  = fmaf(zv, ho - nv, nv);
                g_h1[((size_t)(b0 + r) * T_ + t) * H_ + col] = hw;
                h1pf[PIDX(col, r)] = hw * skeep[r];
            }
        }
        __syncthreads();                                          // B4
    }
}

// out2/out3 gathers
__global__ void gather_kernel(const int* __restrict__ il,
                              const int* __restrict__ neg,
                              const float4* __restrict__ emb4,
                              float4* __restrict__ out2,
                              float4* __restrict__ out3)
{
    int idx = blockIdx.x * blockDim.x + threadIdx.x;
    const int n4 = B_ * (T_ - 1) * (H_ / 4);
    if (idx >= n4) return;
    int k4 = idx & 31;
    int bt = idx >> 5;
    int b  = bt / (T_ - 1);
    int t  = bt - b * (T_ - 1);
    int p  = il [b * T_ + t + 1];
    int qd = neg[b * T_ + t];
    out2[idx] = __ldg(emb4 + (size_t)p  * 32 + k4);
    out3[idx] = __ldg(emb4 + (size_t)qd * 32 + k4);
}

#define LOOP_SMEM (3*NPBUF*8 + (ROWS*G_ + 8*PSQ + 8)*4 + 32)

extern "C" void kernel_launch(void* const* d_in, const int* in_sizes, int n_in,
                              void* d_out, int out_size)
{
    const int*   il    = (const int*)  d_in[0];
    const float* mask  = (const float*)d_in[1];
    const int*   neg   = (const int*)  d_in[2];
    const float* emb   = (const float*)d_in[3];
    const float* Wih   = (const float*)d_in[4];
    const float* Whh   = (const float*)d_in[5];
    const float* bih   = (const float*)d_in[6];
    const float* bhh   = (const float*)d_in[7];
    const float* h2o_w = (const float*)d_in[8];
    const float* h2o_b = (const float*)d_in[9];

    float* out  = (float*)d_out;
    float* out1 = out;
    float* out2 = out1 + (size_t)B_ * (T_ - 1) * H_;
    float* out3 = out2 + (size_t)B_ * (T_ - 1) * H_;
    float* out4 = out3 + (size_t)B_ * (T_ - 1) * H_;

    cudaFuncSetAttribute(gru_loop, cudaFuncAttributeMaxDynamicSharedMemorySize, LOOP_SMEM);

    const int nprep = NWP + 32 * 128;
    prep_kernel<<<(nprep + 255) / 256, 256>>>(Wih, Whh, h2o_w);

    const int n4 = B_ * (T_ - 1) * (H_ / 4);
    gather_kernel<<<(n4 + 255) / 256, 256>>>(il, neg, (const float4*)emb,
                                             (float4*)out2, (float4*)out3);

    pre_kernel<<<NBT / 32, 768>>>(il, emb, bih, out4);

    gru_loop<<<NCTA, NTHR, LOOP_SMEM>>>(mask, bih, bhh);

    post_kernel<<<NBT / ROWS, 128>>>(h2o_b, out1, out4);
}

// round 11
// speedup vs baseline: 2.4171x; 1.6154x over previous
#include <cuda_runtime.h>
#include <cuda_fp16.h>
#include <cstdint>

#define B_   1024
#define T_   200
#define H_   128
#define G_   384
#define ROWS 8
#define NCTA 128
#define NBT  (B_*T_)

#define SU 10
#define NPBUF (64*SU)
#define PIDX(u,r) (((u)>>1)*(2*SU) + 2*(r) + ((u)&1))
#define GST 516          // gates row stride (floats), conflict-free

typedef unsigned long long ull;

// pre_kernel scalar weights (Wih layer0, fp16 pairs)
__device__ ulonglong2 g_Wp[32*192];
__device__ ull        g_Wo[32*128];
// mma weights in A-fragment order: m=0 Whh0, 1 Wih1, 2 Whh1; [m][tile24][ks8][lane32]
__device__ uint4  g_Wf[3*24*8*32];
// biases in D-frag order: 40 slots x 32 lanes (slot: 0-7 L0hn, 8-23 L1rz, 24-31 L1inn, 32-39 L1hn)
__device__ float2 g_biasf[40*32];
// gi0 rz slice in D-frag order: [bgrp128][t200][tile16][lane32] float4
__device__ float4 g_gi0f[(size_t)128*200*16*32];
// gi0 inn slice: [bgrp][t][col128][r8] f32
__device__ float  g_gi0n[(size_t)128*200*128*8];
__device__ float  g_h1[(size_t)NBT*H_];

// ---- helpers ----
__device__ __forceinline__ ull pack2(float a, float b) {
    ull r; asm("mov.b64 %0,{%1,%2};" : "=l"(r) : "f"(a), "f"(b)); return r;
}
__device__ __forceinline__ void fma2(ull& c, ull a, ull b) {
    asm("fma.rn.f32x2 %0,%1,%2,%0;" : "+l"(c) : "l"(a), "l"(b));
}
__device__ __forceinline__ float2 unpack2(ull v) {
    float lo, hi; asm("mov.b64 {%0,%1},%2;" : "=f"(lo), "=f"(hi) : "l"(v));
    return make_float2(lo, hi);
}
__device__ __forceinline__ void cvt4(ull w, ull& A, ull& B) {
    uint32_t lo = (uint32_t)w, hi = (uint32_t)(w >> 32);
    __half2 h0 = *reinterpret_cast<__half2*>(&lo);
    __half2 h1 = *reinterpret_cast<__half2*>(&hi);
    float2 f0 = __half22float2(h0);
    float2 f1 = __half22float2(h1);
    A = pack2(f0.x, f0.y);
    B = pack2(f1.x, f1.y);
}
__device__ __forceinline__ float sigmoid_fast(float x) {
    return 1.0f / (1.0f + __expf(-x));
}
__device__ __forceinline__ float tanh_fast(float x) {
    float ax = fabsf(x);
    float e  = __expf(-2.0f * ax);
    float t  = __fdividef(1.0f - e, 1.0f + e);
    return copysignf(t, x);
}
__device__ __forceinline__ ull pack4h(const float* row) {
    ull a = (ull)__half_as_ushort(__float2half_rn(row[0]));
    ull b = (ull)__half_as_ushort(__float2half_rn(row[1]));
    ull c = (ull)__half_as_ushort(__float2half_rn(row[2]));
    ull d = (ull)__half_as_ushort(__float2half_rn(row[3]));
    return a | (b << 16) | (c << 32) | (d << 48);
}
__device__ __forceinline__ uint32_t h2pk(float a, float b) {
    __half2 h = __floats2half2_rn(a, b);
    return *reinterpret_cast<uint32_t*>(&h);
}

// m16n8k16 f16*f16+f32 mma with accumulate
__device__ __forceinline__ void mma16816(float& d0, float& d1, float& d2, float& d3,
                                         uint4 a, uint32_t b0, uint32_t b1)
{
    asm volatile(
        "mma.sync.aligned.m16n8k16.row.col.f32.f16.f16.f32 "
        "{%0,%1,%2,%3},{%4,%5,%6,%7},{%8,%9},{%0,%1,%2,%3};"
        : "+f"(d0), "+f"(d1), "+f"(d2), "+f"(d3)
        : "r"(a.x), "r"(a.y), "r"(a.z), "r"(a.w), "r"(b0), "r"(b1));
}

// 8 chained K-steps of one tile: D += W_tile(16x128) * act(128x8)
__device__ __forceinline__ void mma8(float& d0, float& d1, float& d2, float& d3,
                                     const uint4* __restrict__ wa,
                                     const uint32_t* __restrict__ act,
                                     int g, int tg)
{
#pragma unroll
    for (int ks = 0; ks < 8; ks++) {
        uint4 a = __ldg(wa + ks * 32);
        uint32_t b0 = act[(ks * 8 + tg) * 8 + g];
        uint32_t b1 = act[(ks * 8 + tg + 4) * 8 + g];
        mma16816(d0, d1, d2, d3, a, b0, b1);
    }
}

// ===================== prep: pack everything =====================
__global__ void prep_kernel(const float* __restrict__ Wih,
                            const float* __restrict__ Whh,
                            const float* __restrict__ bih,
                            const float* __restrict__ bhh,
                            const float* __restrict__ h2o_w)
{
    int idx = blockIdx.x * blockDim.x + threadIdx.x;
    if (idx < 6144) {                      // g_Wp: Wih layer0 pairs
        int jp = idx % 192;
        int k4 = idx / 192;
        ulonglong2 v;
        v.x = pack4h(Wih + (size_t)jp * H_ + 4 * k4);
        v.y = pack4h(Wih + (size_t)(jp + 192) * H_ + 4 * k4);
        g_Wp[k4 * 192 + jp] = v;
    } else if (idx < 6144 + 4096) {        // g_Wo
        int i2 = idx - 6144;
        int oi = i2 % H_;
        int k4 = i2 / H_;
        g_Wo[i2] = pack4h(h2o_w + oi * H_ + 4 * k4);
    } else if (idx < 6144 + 4096 + 18432) {  // g_Wf frag pack
        int i2   = idx - 6144 - 4096;
        int lane = i2 % 32;
        int ks   = (i2 / 32) % 8;
        int tile = (i2 / 256) % 24;
        int m    = i2 / 6144;
        const float* W = (m == 0) ? Whh : ((m == 1) ? (Wih + (size_t)G_ * H_) : (Whh + (size_t)G_ * H_));
        int g = lane >> 2, tg = lane & 3;
        int j0 = tile * 16, k0 = ks * 16;
        uint4 v;
        v.x = h2pk(W[(j0 + g)     * H_ + k0 + tg * 2], W[(j0 + g)     * H_ + k0 + tg * 2 + 1]);
        v.y = h2pk(W[(j0 + g + 8) * H_ + k0 + tg * 2], W[(j0 + g + 8) * H_ + k0 + tg * 2 + 1]);
        v.z = h2pk(W[(j0 + g)     * H_ + k0 + 8 + tg * 2], W[(j0 + g)     * H_ + k0 + 8 + tg * 2 + 1]);
        v.w = h2pk(W[(j0 + g + 8) * H_ + k0 + 8 + tg * 2], W[(j0 + g + 8) * H_ + k0 + 8 + tg * 2 + 1]);
        g_Wf[i2] = v;
    } else if (idx < 6144 + 4096 + 18432 + 1280) {   // g_biasf
        int i3 = idx - 6144 - 4096 - 18432;
        int s = i3 / 32, lane = i3 % 32, g = lane >> 2;
        float2 v;
        if (s < 8) {                       // L0 hn: bhh0 n-slice
            int j0 = 256 + s * 16;
            v = make_float2(bhh[j0 + g], bhh[j0 + g + 8]);
        } else if (s < 24) {               // L1 rz: bih1+bhh1
            int j0 = (s - 8) * 16;
            v = make_float2(bih[G_ + j0 + g] + bhh[G_ + j0 + g],
                            bih[G_ + j0 + g + 8] + bhh[G_ + j0 + g + 8]);
        } else if (s < 32) {               // L1 inn: bih1 n-slice
            int j0 = 256 + (s - 24) * 16;
            v = make_float2(bih[G_ + j0 + g], bih[G_ + j0 + g + 8]);
        } else {                           // L1 hn: bhh1 n-slice
            int j0 = 256 + (s - 32) * 16;
            v = make_float2(bhh[G_ + j0 + g], bhh[G_ + j0 + g + 8]);
        }
        g_biasf[i3] = v;
    }
}

// scalar 2j matvec (pre_kernel only)
__device__ __forceinline__ void mv2j32(const ull* __restrict__ act,
                                       const ulonglong2* __restrict__ w,
                                       float out[2][8], float b0, float b1)
{
    ull acc[2][8];
#pragma unroll
    for (int r = 0; r < 8; r++) { acc[0][r] = pack2(b0, 0.f); acc[1][r] = pack2(b1, 0.f); }
#pragma unroll 8
    for (int k4 = 0; k4 < 32; k4++) {
        ulonglong2 ww;
        asm("ld.global.nc.v2.u64 {%0,%1},[%2];" : "=l"(ww.x), "=l"(ww.y) : "l"(w + k4 * 192));
        ull w0A, w0B, w1A, w1B;
        cvt4(ww.x, w0A, w0B);
        cvt4(ww.y, w1A, w1B);
        const ull* xa = act + 2 * k4 * SU;
#pragma unroll
        for (int p = 0; p < 4; p++) {
            ulonglong2 xv = *(const ulonglong2*)(xa + 2 * p);
            fma2(acc[0][2*p],   w0A, xv.x); fma2(acc[0][2*p+1], w0A, xv.y);
            fma2(acc[1][2*p],   w1A, xv.x); fma2(acc[1][2*p+1], w1A, xv.y);
        }
#pragma unroll
        for (int p = 0; p < 4; p++) {
            ulonglong2 xv = *(const ulonglong2*)(xa + SU + 2 * p);
            fma2(acc[0][2*p],   w0B, xv.x); fma2(acc[0][2*p+1], w0B, xv.y);
            fma2(acc[1][2*p],   w1B, xv.x); fma2(acc[1][2*p+1], w1B, xv.y);
        }
    }
#pragma unroll
    for (int jj = 0; jj < 2; jj++)
#pragma unroll
        for (int r = 0; r < 8; r++) {
            float2 s = unpack2(acc[jj][r]);
            out[jj][r] = s.x + s.y;
        }
}

// ===================== pre-kernel: gi0 (frag order) + out4-low =====================
// block handles 8 batch rows x 4 timesteps
__global__ void __launch_bounds__(768)
pre_kernel(const int* __restrict__ il,
           const float* __restrict__ emb,
           const float* __restrict__ bih,
           const float* __restrict__ bhh,
           float* __restrict__ out4)
{
    __shared__ __align__(16) ull xq[4 * NPBUF];
    const int tid = threadIdx.x;
    const int bg  = blockIdx.x / 50;
    const int t0  = (blockIdx.x % 50) * 4;
    const int b0  = bg * 8;

    for (int i = tid; i < 1024; i += 768) {
        int row = i >> 5, k4 = i & 31;
        int ts = row >> 3, n = row & 7;
        int tok = il[(b0 + n) * T_ + t0 + ts];
        float4 v = __ldg((const float4*)emb + (size_t)tok * 32 + k4);
        float* base = (float*)(xq + ts * NPBUF);
        base[PIDX(4*k4 + 0, n)] = v.x;
        base[PIDX(4*k4 + 1, n)] = v.y;
        base[PIDX(4*k4 + 2, n)] = v.z;
        base[PIDX(4*k4 + 3, n)] = v.w;
        ((float4*)(out4 + ((size_t)(b0 + n) * T_ + t0 + ts) * 256))[k4] = v;
    }
    __syncthreads();

    const int rg = tid / 192, jp = tid - rg * 192;
    const int t  = t0 + rg;
    const int j2 = jp + 192;
    float bv0 = bih[jp] + bhh[jp];                       // j=jp < 256: rz, fold bhh0
    float bv1 = bih[j2] + ((j2 < 256) ? bhh[j2] : 0.f);  // mixed
    float out[2][8];
    mv2j32(xq + rg * NPBUF, g_Wp + jp, out, bv0, bv1);

#pragma unroll
    for (int jj = 0; jj < 2; jj++) {
        int j = jp + jj * 192;
        if (j < 256) {
            int tile = j >> 4, gg = j & 7;
            int sub0 = ((j & 15) >= 8) ? 2 : 0;
            float* basep = (float*)(g_gi0f + (((size_t)bg * 200 + t) * 16 + tile) * 32);
#pragma unroll
            for (int n = 0; n < 8; n++)
                basep[(gg * 4 + (n >> 1)) * 4 + sub0 + (n & 1)] = out[jj][n];
        } else {
            float* p = g_gi0n + (((size_t)bg * 200 + t) * 128 + (j - 256)) * 8;
            *(float4*)p       = make_float4(out[jj][0], out[jj][1], out[jj][2], out[jj][3]);
            *(float4*)(p + 4) = make_float4(out[jj][4], out[jj][5], out[jj][6], out[jj][7]);
        }
    }
}

// ===================== post-kernel: h2o GEMM + tanh =====================
__global__ void __launch_bounds__(128)
post_kernel(const float* __restrict__ h2o_b,
            float* __restrict__ out1,
            float* __restrict__ out4)
{
    __shared__ __align__(16) ull xp[NPBUF];
    const int j   = threadIdx.x;
    const int bt0 = blockIdx.x * ROWS;
    float* xpf = (float*)xp;
#pragma unroll
    for (int r = 0; r < ROWS; r++)
        xpf[PIDX(j, r)] = g_h1[(size_t)(bt0 + r) * H_ + j];
    __syncthreads();

    const ull* w = g_Wo + j;
    float ob = h2o_b[j];
    ull acc[ROWS];
#pragma unroll
    for (int r = 0; r < ROWS; r++) acc[r] = pack2(ob, 0.0f);
#pragma unroll 4
    for (int k4 = 0; k4 < 32; k4++) {
        ull wA, wB; cvt4(__ldg(w + k4 * H_), wA, wB);
        const ull* xa = xp + (2 * k4) * SU;
#pragma unroll
        for (int p = 0; p < 4; p++) {
            ulonglong2 xv = *(const ulonglong2*)(xa + 2 * p);
            fma2(acc[2*p], wA, xv.x); fma2(acc[2*p+1], wA, xv.y);
        }
#pragma unroll
        for (int p = 0; p < 4; p++) {
            ulonglong2 xv = *(const ulonglong2*)(xa + SU + 2 * p);
            fma2(acc[2*p], wB, xv.x); fma2(acc[2*p+1], wB, xv.y);
        }
    }
#pragma unroll
    for (int r = 0; r < ROWS; r++) {
        float2 s = unpack2(acc[r]);
        float o  = tanh_fast(s.x + s.y);
        int bt = bt0 + r;
        int b  = bt / T_;
        int t  = bt - b * T_;
        out4[(size_t)bt * 256 + H_ + j] = o;
        if (t < T_ - 1)
            out1[((size_t)b * (T_ - 1) + t) * H_ + j] = o;
    }
}

// ===================== recurrence loop (tensor-core) =====================
__global__ void __launch_bounds__(384, 1)
gru_loop(const float* __restrict__ mask)
{
    __shared__ uint32_t sh0[512], sh1[512], sbb[512];   // fp16 pair layout [k2*8+n]
    __shared__ float gates[8 * GST];                    // [r][j'] j':0-255 rz,256-383 inn,384-511 hn
    __shared__ float skeep[8];

    const int tid  = threadIdx.x;
    const int w    = tid >> 5;
    const int lane = tid & 31;
    const int g    = lane >> 2;
    const int tg   = lane & 3;
    const int bg   = blockIdx.x;
    const int b0   = bg * 8;

    for (int i = tid; i < 512; i += 384) { sh0[i] = 0u; sh1[i] = 0u; }
    __syncthreads();

    const float4* gi0f_b = g_gi0f + (size_t)bg * 200 * 16 * 32;
    const float*  gi0n_b = g_gi0n + (size_t)bg * 200 * 128 * 8;

    const int col = tid & 127;
    const int rg4 = (tid >> 7) & 1;

    __half* H0 = (__half*)sh0;
    __half* H1 = (__half*)sh1;
    __half* BB = (__half*)sbb;

    for (int t = 0; t < T_; t++) {
        if (tid < 8)
            skeep[tid] = (mask[(b0 + tid) * T_ + t] != 0.0f) ? 1.0f : 0.0f;

        // ---------- L0 MMA: D = gi0/bias + Whh0·h0 ----------
#pragma unroll
        for (int u = 0; u < 2; u++) {
            int tt = w * 2 + u;
            float d0, d1, d2, d3;
            if (tt < 16) {
                float4 v = __ldg(gi0f_b + ((size_t)t * 16 + tt) * 32 + lane);
                d0 = v.x; d1 = v.y; d2 = v.z; d3 = v.w;
            } else {
                float2 bv = g_biasf[(tt - 16) * 32 + lane];
                d0 = bv.x; d1 = bv.x; d2 = bv.y; d3 = bv.y;
            }
            mma8(d0, d1, d2, d3, g_Wf + (size_t)tt * 8 * 32 + lane, sh0, g, tg);
            int jd = (tt < 16) ? tt * 16 : 384 + (tt - 16) * 16;
            gates[(tg*2)   * GST + jd + g]     = d0;
            gates[(tg*2+1) * GST + jd + g]     = d1;
            gates[(tg*2)   * GST + jd + g + 8] = d2;
            gates[(tg*2+1) * GST + jd + g + 8] = d3;
        }
        __syncthreads();                                       // B1

        // ---------- pointwise L0 ----------
        if (tid < 256) {
            float4 inn4 = *(const float4*)(gi0n_b + ((size_t)t * 128 + col) * 8 + rg4 * 4);
            float inn[4] = {inn4.x, inn4.y, inn4.z, inn4.w};
#pragma unroll
            for (int rr = 0; rr < 4; rr++) {
                int r = rg4 * 4 + rr;
                float rv = sigmoid_fast(gates[r * GST + col]);
                float zv = sigmoid_fast(gates[r * GST + 128 + col]);
                float hn = gates[r * GST + 384 + col];
                float nv = tanh_fast(fmaf(rv, hn, inn[rr]));
                int hidx = (col >> 1) * 16 + r * 2 + (col & 1);
                float ho = __half2float(H0[hidx]);
                float hw = fmaf(zv, ho - nv, nv);
                BB[hidx] = __float2half_rn(hw);
                H0[hidx] = __float2half_rn(hw * skeep[r]);
            }
        }
        __syncthreads();                                       // B2

        // ---------- L1 MMA ----------
        if (w < 8) {
            // rz tiles: D = bias + Wih1·b + Whh1·h1 (two chains for ILP)
#pragma unroll
            for (int u = 0; u < 2; u++) {
                int tt = w * 2 + u;
                float2 bv = g_biasf[(8 + tt) * 32 + lane];
                float d0 = bv.x, d1 = bv.x, d2 = bv.y, d3 = bv.y;
                float e0 = 0.f, e1 = 0.f, e2 = 0.f, e3 = 0.f;
                mma8(d0, d1, d2, d3, g_Wf + (size_t)(24 + tt) * 8 * 32 + lane, sbb, g, tg);
                mma8(e0, e1, e2, e3, g_Wf + (size_t)(48 + tt) * 8 * 32 + lane, sh1, g, tg);
                d0 += e0; d1 += e1; d2 += e2; d3 += e3;
                int jd = tt * 16;
                gates[(tg*2)   * GST + jd + g]     = d0;
                gates[(tg*2+1) * GST + jd + g]     = d1;
                gates[(tg*2)   * GST + jd + g + 8] = d2;
                gates[(tg*2+1) * GST + jd + g + 8] = d3;
            }
        } else {
            int base = (w - 8) * 2;
#pragma unroll
            for (int u = 0; u < 2; u++) {
                int s  = base + u;
                int tl = 16 + s;
                // inn job: bih1_n + Wih1_n·b
                {
                    float2 bv = g_biasf[(24 + s) * 32 + lane];
                    float d0 = bv.x, d1 = bv.x, d2 = bv.y, d3 = bv.y;
                    mma8(d0, d1, d2, d3, g_Wf + (size_t)(24 + tl) * 8 * 32 + lane, sbb, g, tg);
                    int jd = 256 + s * 16;
                    gates[(tg*2)   * GST + jd + g]     = d0;
                    gates[(tg*2+1) * GST + jd + g]     = d1;
                    gates[(tg*2)   * GST + jd + g + 8] = d2;
                    gates[(tg*2+1) * GST + jd + g + 8] = d3;
                }
                // hn job: bhh1_n + Whh1_n·h1
                {
                    float2 bv = g_biasf[(32 + s) * 32 + lane];
                    float d0 = bv.x, d1 = bv.x, d2 = bv.y, d3 = bv.y;
                    mma8(d0, d1, d2, d3, g_Wf + (size_t)(48 + tl) * 8 * 32 + lane, sh1, g, tg);
                    int jd = 384 + s * 16;
                    gates[(tg*2)   * GST + jd + g]     = d0;
                    gates[(tg*2+1) * GST + jd + g]     = d1;
                    gates[(tg*2)   * GST + jd + g + 8] = d2;
                    gates[(tg*2+1) * GST + jd + g + 8] = d3;
                }
            }
        }
        __syncthreads();                                       // B3

        // ---------- pointwise L1 ----------
        if (tid < 256) {
#pragma unroll
            for (int rr = 0; rr < 4; rr++) {
                int r = rg4 * 4 + rr;
                float rv  = sigmoid_fast(gates[r * GST + col]);
                float zv  = sigmoid_fast(gates[r * GST + 128 + col]);
                float inn = gates[r * GST + 256 + col];
                float hn  = gates[r * GST + 384 + col];
                float nv  = tanh_fast(fmaf(rv, hn, inn));
                int hidx = (col >> 1) * 16 + r * 2 + (col & 1);
                float ho = __half2float(H1[hidx]);
                float hw = fmaf(zv, ho - nv, nv);
                g_h1[((size_t)(b0 + r) * T_ + t) * H_ + col] = hw;
                H1[hidx] = __float2half_rn(hw * skeep[r]);
            }
        }
        __syncthreads();                                       // B4
    }
}

// out2/out3 gathers
__global__ void gather_kernel(const int* __restrict__ il,
                              const int* __restrict__ neg,
                              const float4* __restrict__ emb4,
                              float4* __restrict__ out2,
                              float4* __restrict__ out3)
{
    int idx = blockIdx.x * blockDim.x + threadIdx.x;
    const int n4 = B_ * (T_ - 1) * (H_ / 4);
    if (idx >= n4) return;
    int k4 = idx & 31;
    int bt = idx >> 5;
    int b  = bt / (T_ - 1);
    int t  = bt - b * (T_ - 1);
    int p  = il [b * T_ + t + 1];
    int qd = neg[b * T_ + t];
    out2[idx] = __ldg(emb4 + (size_t)p  * 32 + k4);
    out3[idx] = __ldg(emb4 + (size_t)qd * 32 + k4);
}

extern "C" void kernel_launch(void* const* d_in, const int* in_sizes, int n_in,
                              void* d_out, int out_size)
{
    const int*   il    = (const int*)  d_in[0];
    const float* mask  = (const float*)d_in[1];
    const int*   neg   = (const int*)  d_in[2];
    const float* emb   = (const float*)d_in[3];
    const float* Wih   = (const float*)d_in[4];
    const float* Whh   = (const float*)d_in[5];
    const float* bih   = (const float*)d_in[6];
    const float* bhh   = (const float*)d_in[7];
    const float* h2o_w = (const float*)d_in[8];
    const float* h2o_b = (const float*)d_in[9];

    float* out  = (float*)d_out;
    float* out1 = out;
    float* out2 = out1 + (size_t)B_ * (T_ - 1) * H_;
    float* out3 = out2 + (size_t)B_ * (T_ - 1) * H_;
    float* out4 = out3 + (size_t)B_ * (T_ - 1) * H_;

    const int nprep = 6144 + 4096 + 18432 + 1280;
    prep_kernel<<<(nprep + 255) / 256, 256>>>(Wih, Whh, bih, bhh, h2o_w);

    const int n4 = B_ * (T_ - 1) * (H_ / 4);
    gather_kernel<<<(n4 + 255) / 256, 256>>>(il, neg, (const float4*)emb,
                                             (float4*)out2, (float4*)out3);

    pre_kernel<<<128 * 50, 768>>>(il, emb, bih, bhh, out4);

    gru_loop<<<NCTA, 384>>>(mask);

    post_kernel<<<NBT / ROWS, 128>>>(h2o_b, out1, out4);
}

// round 12
// speedup vs baseline: 2.4376x; 1.0085x over previous
#include <cuda_runtime.h>
#include <cuda_fp16.h>
#include <cstdint>

#define B_   1024
#define T_   200
#define H_   128
#define G_   384
#define ROWS 8
#define NCTA 128
#define NBT  (B_*T_)

#define SU 10
#define NPBUF (64*SU)
#define PIDX(u,r) (((u)>>1)*(2*SU) + 2*(r) + ((u)&1))
#define GST 516          // gates row stride (floats), conflict-free

typedef unsigned long long ull;

// pre_kernel scalar weights (Wih layer0, fp16 pairs)
__device__ ulonglong2 g_Wp[32*192];
__device__ ull        g_Wo[32*128];
// mma weights in A-fragment order: m=0 Whh0, 1 Wih1, 2 Whh1; [m][tile24][ks8][lane32]
__device__ uint4  g_Wf[3*24*8*32];
// biases in D-frag order: 40 slots x 32 lanes
__device__ float2 g_biasf[40*32];
// gi0 rz slice in D-frag order: [bgrp128][t200][tile16][lane32] float4
__device__ float4 g_gi0f[(size_t)128*200*16*32];
// gi0 inn slice: [bgrp][t][col128][r8] f32
__device__ float  g_gi0n[(size_t)128*200*128*8];
__device__ float  g_h1[(size_t)NBT*H_];

// ---- helpers ----
__device__ __forceinline__ ull pack2(float a, float b) {
    ull r; asm("mov.b64 %0,{%1,%2};" : "=l"(r) : "f"(a), "f"(b)); return r;
}
__device__ __forceinline__ void fma2(ull& c, ull a, ull b) {
    asm("fma.rn.f32x2 %0,%1,%2,%0;" : "+l"(c) : "l"(a), "l"(b));
}
__device__ __forceinline__ float2 unpack2(ull v) {
    float lo, hi; asm("mov.b64 {%0,%1},%2;" : "=f"(lo), "=f"(hi) : "l"(v));
    return make_float2(lo, hi);
}
__device__ __forceinline__ void cvt4(ull w, ull& A, ull& B) {
    uint32_t lo = (uint32_t)w, hi = (uint32_t)(w >> 32);
    __half2 h0 = *reinterpret_cast<__half2*>(&lo);
    __half2 h1 = *reinterpret_cast<__half2*>(&hi);
    float2 f0 = __half22float2(h0);
    float2 f1 = __half22float2(h1);
    A = pack2(f0.x, f0.y);
    B = pack2(f1.x, f1.y);
}
__device__ __forceinline__ float sigmoid_fast(float x) {
    return 1.0f / (1.0f + __expf(-x));
}
__device__ __forceinline__ float tanh_fast(float x) {
    float ax = fabsf(x);
    float e  = __expf(-2.0f * ax);
    float t  = __fdividef(1.0f - e, 1.0f + e);
    return copysignf(t, x);
}
__device__ __forceinline__ ull pack4h(const float* row) {
    ull a = (ull)__half_as_ushort(__float2half_rn(row[0]));
    ull b = (ull)__half_as_ushort(__float2half_rn(row[1]));
    ull c = (ull)__half_as_ushort(__float2half_rn(row[2]));
    ull d = (ull)__half_as_ushort(__float2half_rn(row[3]));
    return a | (b << 16) | (c << 32) | (d << 48);
}
__device__ __forceinline__ uint32_t h2pk(float a, float b) {
    __half2 h = __floats2half2_rn(a, b);
    return *reinterpret_cast<uint32_t*>(&h);
}

// m16n8k16 f16*f16+f32 mma with accumulate
__device__ __forceinline__ void mma16816(float& d0, float& d1, float& d2, float& d3,
                                         uint4 a, uint32_t b0, uint32_t b1)
{
    asm volatile(
        "mma.sync.aligned.m16n8k16.row.col.f32.f16.f16.f32 "
        "{%0,%1,%2,%3},{%4,%5,%6,%7},{%8,%9},{%0,%1,%2,%3};"
        : "+f"(d0), "+f"(d1), "+f"(d2), "+f"(d3)
        : "r"(a.x), "r"(a.y), "r"(a.z), "r"(a.w), "r"(b0), "r"(b1));
}

// 4 chained K-steps starting at ks0, weights from SMEM (LDS)
__device__ __forceinline__ void mma4s(float& d0, float& d1, float& d2, float& d3,
                                      const uint4* wa, const uint32_t* act,
                                      int g, int tg, int ks0)
{
#pragma unroll
    for (int k = 0; k < 4; k++) {
        int ks = ks0 + k;
        uint4 a = wa[ks * 32];
        uint32_t b0 = act[(ks * 8 + tg) * 8 + g];
        uint32_t b1 = act[(ks * 8 + tg + 4) * 8 + g];
        mma16816(d0, d1, d2, d3, a, b0, b1);
    }
}
// 4 chained K-steps, weights from global (LDG)
__device__ __forceinline__ void mma4g(float& d0, float& d1, float& d2, float& d3,
                                      const uint4* __restrict__ wa, const uint32_t* act,
                                      int g, int tg, int ks0)
{
#pragma unroll
    for (int k = 0; k < 4; k++) {
        int ks = ks0 + k;
        uint4 a = __ldg(wa + ks * 32);
        uint32_t b0 = act[(ks * 8 + tg) * 8 + g];
        uint32_t b1 = act[(ks * 8 + tg + 4) * 8 + g];
        mma16816(d0, d1, d2, d3, a, b0, b1);
    }
}

// ===================== prep: pack everything =====================
__global__ void prep_kernel(const float* __restrict__ Wih,
                            const float* __restrict__ Whh,
                            const float* __restrict__ bih,
                            const float* __restrict__ bhh,
                            const float* __restrict__ h2o_w)
{
    int idx = blockIdx.x * blockDim.x + threadIdx.x;
    if (idx < 6144) {
        int jp = idx % 192;
        int k4 = idx / 192;
        ulonglong2 v;
        v.x = pack4h(Wih + (size_t)jp * H_ + 4 * k4);
        v.y = pack4h(Wih + (size_t)(jp + 192) * H_ + 4 * k4);
        g_Wp[k4 * 192 + jp] = v;
    } else if (idx < 6144 + 4096) {
        int i2 = idx - 6144;
        int oi = i2 % H_;
        int k4 = i2 / H_;
        g_Wo[i2] = pack4h(h2o_w + oi * H_ + 4 * k4);
    } else if (idx < 6144 + 4096 + 18432) {
        int i2   = idx - 6144 - 4096;
        int lane = i2 % 32;
        int ks   = (i2 / 32) % 8;
        int tile = (i2 / 256) % 24;
        int m    = i2 / 6144;
        const float* W = (m == 0) ? Whh : ((m == 1) ? (Wih + (size_t)G_ * H_) : (Whh + (size_t)G_ * H_));
        int g = lane >> 2, tg = lane & 3;
        int j0 = tile * 16, k0 = ks * 16;
        uint4 v;
        v.x = h2pk(W[(j0 + g)     * H_ + k0 + tg * 2], W[(j0 + g)     * H_ + k0 + tg * 2 + 1]);
        v.y = h2pk(W[(j0 + g + 8) * H_ + k0 + tg * 2], W[(j0 + g + 8) * H_ + k0 + tg * 2 + 1]);
        v.z = h2pk(W[(j0 + g)     * H_ + k0 + 8 + tg * 2], W[(j0 + g)     * H_ + k0 + 8 + tg * 2 + 1]);
        v.w = h2pk(W[(j0 + g + 8) * H_ + k0 + 8 + tg * 2], W[(j0 + g + 8) * H_ + k0 + 8 + tg * 2 + 1]);
        g_Wf[i2] = v;
    } else if (idx < 6144 + 4096 + 18432 + 1280) {
        int i3 = idx - 6144 - 4096 - 18432;
        int s = i3 / 32, lane = i3 % 32, g = lane >> 2;
        float2 v;
        if (s < 8) {
            int j0 = 256 + s * 16;
            v = make_float2(bhh[j0 + g], bhh[j0 + g + 8]);
        } else if (s < 24) {
            int j0 = (s - 8) * 16;
            v = make_float2(bih[G_ + j0 + g] + bhh[G_ + j0 + g],
                            bih[G_ + j0 + g + 8] + bhh[G_ + j0 + g + 8]);
        } else if (s < 32) {
            int j0 = 256 + (s - 24) * 16;
            v = make_float2(bih[G_ + j0 + g], bih[G_ + j0 + g + 8]);
        } else {
            int j0 = 256 + (s - 32) * 16;
            v = make_float2(bhh[G_ + j0 + g], bhh[G_ + j0 + g + 8]);
        }
        g_biasf[i3] = v;
    }
}

// scalar 2j matvec (pre_kernel only)
__device__ __forceinline__ void mv2j32(const ull* __restrict__ act,
                                       const ulonglong2* __restrict__ w,
                                       float out[2][8], float b0, float b1)
{
    ull acc[2][8];
#pragma unroll
    for (int r = 0; r < 8; r++) { acc[0][r] = pack2(b0, 0.f); acc[1][r] = pack2(b1, 0.f); }
#pragma unroll 8
    for (int k4 = 0; k4 < 32; k4++) {
        ulonglong2 ww;
        asm("ld.global.nc.v2.u64 {%0,%1},[%2];" : "=l"(ww.x), "=l"(ww.y) : "l"(w + k4 * 192));
        ull w0A, w0B, w1A, w1B;
        cvt4(ww.x, w0A, w0B);
        cvt4(ww.y, w1A, w1B);
        const ull* xa = act + 2 * k4 * SU;
#pragma unroll
        for (int p = 0; p < 4; p++) {
            ulonglong2 xv = *(const ulonglong2*)(xa + 2 * p);
            fma2(acc[0][2*p],   w0A, xv.x); fma2(acc[0][2*p+1], w0A, xv.y);
            fma2(acc[1][2*p],   w1A, xv.x); fma2(acc[1][2*p+1], w1A, xv.y);
        }
#pragma unroll
        for (int p = 0; p < 4; p++) {
            ulonglong2 xv = *(const ulonglong2*)(xa + SU + 2 * p);
            fma2(acc[0][2*p],   w0B, xv.x); fma2(acc[0][2*p+1], w0B, xv.y);
            fma2(acc[1][2*p],   w1B, xv.x); fma2(acc[1][2*p+1], w1B, xv.y);
        }
    }
#pragma unroll
    for (int jj = 0; jj < 2; jj++)
#pragma unroll
        for (int r = 0; r < 8; r++) {
            float2 s = unpack2(acc[jj][r]);
            out[jj][r] = s.x + s.y;
        }
}

// ===================== pre-kernel =====================
__global__ void __launch_bounds__(768)
pre_kernel(const int* __restrict__ il,
           const float* __restrict__ emb,
           const float* __restrict__ bih,
           const float* __restrict__ bhh,
           float* __restrict__ out4)
{
    __shared__ __align__(16) ull xq[4 * NPBUF];
    const int tid = threadIdx.x;
    const int bg  = blockIdx.x / 50;
    const int t0  = (blockIdx.x % 50) * 4;
    const int b0  = bg * 8;

    for (int i = tid; i < 1024; i += 768) {
        int row = i >> 5, k4 = i & 31;
        int ts = row >> 3, n = row & 7;
        int tok = il[(b0 + n) * T_ + t0 + ts];
        float4 v = __ldg((const float4*)emb + (size_t)tok * 32 + k4);
        float* base = (float*)(xq + ts * NPBUF);
        base[PIDX(4*k4 + 0, n)] = v.x;
        base[PIDX(4*k4 + 1, n)] = v.y;
        base[PIDX(4*k4 + 2, n)] = v.z;
        base[PIDX(4*k4 + 3, n)] = v.w;
        ((float4*)(out4 + ((size_t)(b0 + n) * T_ + t0 + ts) * 256))[k4] = v;
    }
    __syncthreads();

    const int rg = tid / 192, jp = tid - rg * 192;
    const int t  = t0 + rg;
    const int j2 = jp + 192;
    float bv0 = bih[jp] + bhh[jp];
    float bv1 = bih[j2] + ((j2 < 256) ? bhh[j2] : 0.f);
    float out[2][8];
    mv2j32(xq + rg * NPBUF, g_Wp + jp, out, bv0, bv1);

#pragma unroll
    for (int jj = 0; jj < 2; jj++) {
        int j = jp + jj * 192;
        if (j < 256) {
            int tile = j >> 4, gg = j & 7;
            int sub0 = ((j & 15) >= 8) ? 2 : 0;
            float* basep = (float*)(g_gi0f + (((size_t)bg * 200 + t) * 16 + tile) * 32);
#pragma unroll
            for (int n = 0; n < 8; n++)
                basep[(gg * 4 + (n >> 1)) * 4 + sub0 + (n & 1)] = out[jj][n];
        } else {
            float* p = g_gi0n + (((size_t)bg * 200 + t) * 128 + (j - 256)) * 8;
            *(float4*)p       = make_float4(out[jj][0], out[jj][1], out[jj][2], out[jj][3]);
            *(float4*)(p + 4) = make_float4(out[jj][4], out[jj][5], out[jj][6], out[jj][7]);
        }
    }
}

// ===================== post-kernel =====================
__global__ void __launch_bounds__(128)
post_kernel(const float* __restrict__ h2o_b,
            float* __restrict__ out1,
            float* __restrict__ out4)
{
    __shared__ __align__(16) ull xp[NPBUF];
    const int j   = threadIdx.x;
    const int bt0 = blockIdx.x * ROWS;
    float* xpf = (float*)xp;
#pragma unroll
    for (int r = 0; r < ROWS; r++)
        xpf[PIDX(j, r)] = g_h1[(size_t)(bt0 + r) * H_ + j];
    __syncthreads();

    const ull* w = g_Wo + j;
    float ob = h2o_b[j];
    ull acc[ROWS];
#pragma unroll
    for (int r = 0; r < ROWS; r++) acc[r] = pack2(ob, 0.0f);
#pragma unroll 4
    for (int k4 = 0; k4 < 32; k4++) {
        ull wA, wB; cvt4(__ldg(w + k4 * H_), wA, wB);
        const ull* xa = xp + (2 * k4) * SU;
#pragma unroll
        for (int p = 0; p < 4; p++) {
            ulonglong2 xv = *(const ulonglong2*)(xa + 2 * p);
            fma2(acc[2*p], wA, xv.x); fma2(acc[2*p+1], wA, xv.y);
        }
#pragma unroll
        for (int p = 0; p < 4; p++) {
            ulonglong2 xv = *(const ulonglong2*)(xa + SU + 2 * p);
            fma2(acc[2*p], wB, xv.x); fma2(acc[2*p+1], wB, xv.y);
        }
    }
#pragma unroll
    for (int r = 0; r < ROWS; r++) {
        float2 s = unpack2(acc[r]);
        float o  = tanh_fast(s.x + s.y);
        int bt = bt0 + r;
        int b  = bt / T_;
        int t  = bt - b * T_;
        out4[(size_t)bt * 256 + H_ + j] = o;
        if (t < T_ - 1)
            out1[((size_t)b * (T_ - 1) + t) * H_ + j] = o;
    }
}

// ===================== recurrence loop (tensor-core, SMEM weights) =====================
__global__ void __launch_bounds__(384, 1)
gru_loop(const float* __restrict__ mask)
{
    extern __shared__ __align__(16) uint4 wsm[];   // [0:6144) Whh0, [6144:12288) Whh1
    __shared__ uint32_t sh0[512], sh1[512], sbb[512];
    __shared__ float gates[8 * GST];
    __shared__ float skeep[8];

    const int tid  = threadIdx.x;
    const int w    = tid >> 5;
    const int lane = tid & 31;
    const int g    = lane >> 2;
    const int tg   = lane & 3;
    const int bg   = blockIdx.x;
    const int b0   = bg * 8;

    // one-time: load Whh0 (m=0) and Whh1 (m=2) frags into SMEM
    for (int i = tid; i < 6144; i += 384) {
        wsm[i]        = g_Wf[i];
        wsm[6144 + i] = g_Wf[2 * 6144 + i];
    }
    for (int i = tid; i < 512; i += 384) { sh0[i] = 0u; sh1[i] = 0u; }
    __syncthreads();

    const uint4* ws0 = wsm;
    const uint4* ws1 = wsm + 6144;

    const float4* gi0f_b = g_gi0f + (size_t)bg * 200 * 16 * 32;
    const float*  gi0n_b = g_gi0n + (size_t)bg * 200 * 128 * 8;

    const int col = tid & 127;
    const int rg4 = (tid >> 7) & 1;

    __half* H0 = (__half*)sh0;
    __half* H1 = (__half*)sh1;
    __half* BB = (__half*)sbb;

    for (int t = 0; t < T_; t++) {
        if (tid < 8)
            skeep[tid] = (mask[(b0 + tid) * T_ + t] != 0.0f) ? 1.0f : 0.0f;

        // ---------- L0 MMA: D = gi0/bias + Whh0·h0 (SMEM weights, 2x4 chains) ----------
#pragma unroll
        for (int u = 0; u < 2; u++) {
            int tt = w * 2 + u;
            float d0, d1, d2, d3;
            if (tt < 16) {
                float4 v = __ldg(gi0f_b + ((size_t)t * 16 + tt) * 32 + lane);
                d0 = v.x; d1 = v.y; d2 = v.z; d3 = v.w;
            } else {
                float2 bv = g_biasf[(tt - 16) * 32 + lane];
                d0 = bv.x; d1 = bv.x; d2 = bv.y; d3 = bv.y;
            }
            float e0 = 0.f, e1 = 0.f, e2 = 0.f, e3 = 0.f;
            const uint4* wa = ws0 + tt * 256 + lane;
            mma4s(d0, d1, d2, d3, wa, sh0, g, tg, 0);
            mma4s(e0, e1, e2, e3, wa, sh0, g, tg, 4);
            d0 += e0; d1 += e1; d2 += e2; d3 += e3;
            int jd = (tt < 16) ? tt * 16 : 384 + (tt - 16) * 16;
            gates[(tg*2)   * GST + jd + g]     = d0;
            gates[(tg*2+1) * GST + jd + g]     = d1;
            gates[(tg*2)   * GST + jd + g + 8] = d2;
            gates[(tg*2+1) * GST + jd + g + 8] = d3;
        }
        __syncthreads();                                       // B1

        // ---------- pointwise L0 ----------
        if (tid < 256) {
            float4 inn4 = *(const float4*)(gi0n_b + ((size_t)t * 128 + col) * 8 + rg4 * 4);
            float inn[4] = {inn4.x, inn4.y, inn4.z, inn4.w};
#pragma unroll
            for (int rr = 0; rr < 4; rr++) {
                int r = rg4 * 4 + rr;
                float rv = sigmoid_fast(gates[r * GST + col]);
                float zv = sigmoid_fast(gates[r * GST + 128 + col]);
                float hn = gates[r * GST + 384 + col];
                float nv = tanh_fast(fmaf(rv, hn, inn[rr]));
                int hidx = (col >> 1) * 16 + r * 2 + (col & 1);
                float ho = __half2float(H0[hidx]);
                float hw = fmaf(zv, ho - nv, nv);
                BB[hidx] = __float2half_rn(hw);
                H0[hidx] = __float2half_rn(hw * skeep[r]);
            }
        }
        __syncthreads();                                       // B2

        // ---------- L1 MMA ----------
        if (w < 8) {
            // rz tiles: bias + Wih1·b (global) + Whh1·h1 (SMEM), 4 chains of 4
#pragma unroll
            for (int u = 0; u < 2; u++) {
                int tt = w * 2 + u;
                float2 bv = g_biasf[(8 + tt) * 32 + lane];
                float d0 = bv.x, d1 = bv.x, d2 = bv.y, d3 = bv.y;
                float e0 = 0.f, e1 = 0.f, e2 = 0.f, e3 = 0.f;
                float f0 = 0.f, f1 = 0.f, f2 = 0.f, f3 = 0.f;
                float h0a = 0.f, h1a = 0.f, h2a = 0.f, h3a = 0.f;
                const uint4* wg = g_Wf + (size_t)(24 + tt) * 256 + lane;
                const uint4* wsv = ws1 + tt * 256 + lane;
                mma4g(d0, d1, d2, d3, wg, sbb, g, tg, 0);
                mma4g(e0, e1, e2, e3, wg, sbb, g, tg, 4);
                mma4s(f0, f1, f2, f3, wsv, sh1, g, tg, 0);
                mma4s(h0a, h1a, h2a, h3a, wsv, sh1, g, tg, 4);
                d0 += e0 + f0 + h0a; d1 += e1 + f1 + h1a;
                d2 += e2 + f2 + h2a; d3 += e3 + f3 + h3a;
                int jd = tt * 16;
                gates[(tg*2)   * GST + jd + g]     = d0;
                gates[(tg*2+1) * GST + jd + g]     = d1;
                gates[(tg*2)   * GST + jd + g + 8] = d2;
                gates[(tg*2+1) * GST + jd + g + 8] = d3;
            }
        } else {
            int base = (w - 8) * 2;
#pragma unroll
            for (int u = 0; u < 2; u++) {
                int s  = base + u;
                int tl = 16 + s;
                // inn: bih1_n + Wih1_n·b (global)
                {
                    float2 bv = g_biasf[(24 + s) * 32 + lane];
                    float d0 = bv.x, d1 = bv.x, d2 = bv.y, d3 = bv.y;
                    float e0 = 0.f, e1 = 0.f, e2 = 0.f, e3 = 0.f;
                    const uint4* wg = g_Wf + (size_t)(24 + tl) * 256 + lane;
                    mma4g(d0, d1, d2, d3, wg, sbb, g, tg, 0);
                    mma4g(e0, e1, e2, e3, wg, sbb, g, tg, 4);
                    d0 += e0; d1 += e1; d2 += e2; d3 += e3;
                    int jd = 256 + s * 16;
                    gates[(tg*2)   * GST + jd + g]     = d0;
                    gates[(tg*2+1) * GST + jd + g]     = d1;
                    gates[(tg*2)   * GST + jd + g + 8] = d2;
                    gates[(tg*2+1) * GST + jd + g + 8] = d3;
                }
                // hn: bhh1_n + Whh1_n·h1 (SMEM)
                {
                    float2 bv = g_biasf[(32 + s) * 32 + lane];
                    float d0 = bv.x, d1 = bv.x, d2 = bv.y, d3 = bv.y;
                    float e0 = 0.f, e1 = 0.f, e2 = 0.f, e3 = 0.f;
                    const uint4* wsv = ws1 + tl * 256 + lane;
                    mma4s(d0, d1, d2, d3, wsv, sh1, g, tg, 0);
                    mma4s(e0, e1, e2, e3, wsv, sh1, g, tg, 4);
                    d0 += e0; d1 += e1; d2 += e2; d3 += e3;
                    int jd = 384 + s * 16;
                    gates[(tg*2)   * GST + jd + g]     = d0;
                    gates[(tg*2+1) * GST + jd + g]     = d1;
                    gates[(tg*2)   * GST + jd + g + 8] = d2;
                    gates[(tg*2+1) * GST + jd + g + 8] = d3;
                }
            }
        }
        __syncthreads();                                       // B3

        // ---------- pointwise L1 ----------
        if (tid < 256) {
#pragma unroll
            for (int rr = 0; rr < 4; rr++) {
                int r = rg4 * 4 + rr;
                float rv  = sigmoid_fast(gates[r * GST + col]);
                float zv  = sigmoid_fast(gates[r * GST + 128 + col]);
                float inn = gates[r * GST + 256 + col];
                float hn  = gates[r * GST + 384 + col];
                float nv  = tanh_fast(fmaf(rv, hn, inn));
                int hidx = (col >> 1) * 16 + r * 2 + (col & 1);
                float ho = __half2float(H1[hidx]);
                float hw = fmaf(zv, ho - nv, nv);
                g_h1[((size_t)(b0 + r) * T_ + t) * H_ + col] = hw;
                H1[hidx] = __float2half_rn(hw * skeep[r]);
            }
        }
        __syncthreads();                                       // B4
    }
}

// out2/out3 gathers
__global__ void gather_kernel(const int* __restrict__ il,
                              const int* __restrict__ neg,
                              const float4* __restrict__ emb4,
                              float4* __restrict__ out2,
                              float4* __restrict__ out3)
{
    int idx = blockIdx.x * blockDim.x + threadIdx.x;
    const int n4 = B_ * (T_ - 1) * (H_ / 4);
    if (idx >= n4) return;
    int k4 = idx & 31;
    int bt = idx >> 5;
    int b  = bt / (T_ - 1);
    int t  = bt - b * (T_ - 1);
    int p  = il [b * T_ + t + 1];
    int qd = neg[b * T_ + t];
    out2[idx] = __ldg(emb4 + (size_t)p  * 32 + k4);
    out3[idx] = __ldg(emb4 + (size_t)qd * 32 + k4);
}

#define WSMEM (2*6144*16)

extern "C" void kernel_launch(void* const* d_in, const int* in_sizes, int n_in,
                              void* d_out, int out_size)
{
    const int*   il    = (const int*)  d_in[0];
    const float* mask  = (const float*)d_in[1];
    const int*   neg   = (const int*)  d_in[2];
    const float* emb   = (const float*)d_in[3];
    const float* Wih   = (const float*)d_in[4];
    const float* Whh   = (const float*)d_in[5];
    const float* bih   = (const float*)d_in[6];
    const float* bhh   = (const float*)d_in[7];
    const float* h2o_w = (const float*)d_in[8];
    const float* h2o_b = (const float*)d_in[9];

    float* out  = (float*)d_out;
    float* out1 = out;
    float* out2 = out1 + (size_t)B_ * (T_ - 1) * H_;
    float* out3 = out2 + (size_t)B_ * (T_ - 1) * H_;
    float* out4 = out3 + (size_t)B_ * (T_ - 1) * H_;

    cudaFuncSetAttribute(gru_loop, cudaFuncAttributeMaxDynamicSharedMemorySize, WSMEM);

    const int nprep = 6144 + 4096 + 18432 + 1280;
    prep_kernel<<<(nprep + 255) / 256, 256>>>(Wih, Whh, bih, bhh, h2o_w);

    const int n4 = B_ * (T_ - 1) * (H_ / 4);
    gather_kernel<<<(n4 + 255) / 256, 256>>>(il, neg, (const float4*)emb,
                                             (float4*)out2, (float4*)out3);

    pre_kernel<<<128 * 50, 768>>>(il, emb, bih, bhh, out4);

    gru_loop<<<NCTA, 384, WSMEM>>>(mask);

    post_kernel<<<NBT / ROWS, 128>>>(h2o_b, out1, out4);
}

// round 13
// speedup vs baseline: 2.4561x; 1.0076x over previous
#include <cuda_runtime.h>
#include <cuda_fp16.h>
#include <cstdint>

#define B_   1024
#define T_   200
#define H_   128
#define G_   384
#define ROWS 8
#define NCTA 128
#define NBT  (B_*T_)

#define SU 10
#define NPBUF (64*SU)
#define PIDX(u,r) (((u)>>1)*(2*SU) + 2*(r) + ((u)&1))
#define GST 516          // gates row stride (floats), conflict-free

#define BAR_SYNC(id,cnt)   asm volatile("bar.sync %0,%1;"   :: "r"(id), "r"(cnt) : "memory")
#define BAR_ARRIVE(id,cnt) asm volatile("bar.arrive %0,%1;" :: "r"(id), "r"(cnt) : "memory")

typedef unsigned long long ull;

// pre_kernel scalar weights (Wih layer0, fp16 pairs)
__device__ ulonglong2 g_Wp[32*192];
__device__ ull        g_Wo[32*128];
// mma weights in A-fragment order: m=0 Whh0, 1 Wih1, 2 Whh1; [m][tile24][ks8][lane32]
__device__ uint4  g_Wf[3*24*8*32];
// biases in D-frag order: 40 slots x 32 lanes
__device__ float2 g_biasf[40*32];
// gi0 rz slice in D-frag order: [bgrp128][t200][tile16][lane32] float4
__device__ float4 g_gi0f[(size_t)128*200*16*32];
// gi0 inn slice: [bgrp][t][col128][r8] f32
__device__ float  g_gi0n[(size_t)128*200*128*8];
__device__ float  g_h1[(size_t)NBT*H_];

// ---- helpers ----
__device__ __forceinline__ ull pack2(float a, float b) {
    ull r; asm("mov.b64 %0,{%1,%2};" : "=l"(r) : "f"(a), "f"(b)); return r;
}
__device__ __forceinline__ void fma2(ull& c, ull a, ull b) {
    asm("fma.rn.f32x2 %0,%1,%2,%0;" : "+l"(c) : "l"(a), "l"(b));
}
__device__ __forceinline__ float2 unpack2(ull v) {
    float lo, hi; asm("mov.b64 {%0,%1},%2;" : "=f"(lo), "=f"(hi) : "l"(v));
    return make_float2(lo, hi);
}
__device__ __forceinline__ void cvt4(ull w, ull& A, ull& B) {
    uint32_t lo = (uint32_t)w, hi = (uint32_t)(w >> 32);
    __half2 h0 = *reinterpret_cast<__half2*>(&lo);
    __half2 h1 = *reinterpret_cast<__half2*>(&hi);
    float2 f0 = __half22float2(h0);
    float2 f1 = __half22float2(h1);
    A = pack2(f0.x, f0.y);
    B = pack2(f1.x, f1.y);
}
__device__ __forceinline__ float sigmoid_fast(float x) {
    return 1.0f / (1.0f + __expf(-x));
}
__device__ __forceinline__ float tanh_fast(float x) {
    float ax = fabsf(x);
    float e  = __expf(-2.0f * ax);
    float t  = __fdividef(1.0f - e, 1.0f + e);
    return copysignf(t, x);
}
__device__ __forceinline__ ull pack4h(const float* row) {
    ull a = (ull)__half_as_ushort(__float2half_rn(row[0]));
    ull b = (ull)__half_as_ushort(__float2half_rn(row[1]));
    ull c = (ull)__half_as_ushort(__float2half_rn(row[2]));
    ull d = (ull)__half_as_ushort(__float2half_rn(row[3]));
    return a | (b << 16) | (c << 32) | (d << 48);
}
__device__ __forceinline__ uint32_t h2pk(float a, float b) {
    __half2 h = __floats2half2_rn(a, b);
    return *reinterpret_cast<uint32_t*>(&h);
}

// m16n8k16 f16*f16+f32 mma with accumulate
__device__ __forceinline__ void mma16816(float& d0, float& d1, float& d2, float& d3,
                                         uint4 a, uint32_t b0, uint32_t b1)
{
    asm volatile(
        "mma.sync.aligned.m16n8k16.row.col.f32.f16.f16.f32 "
        "{%0,%1,%2,%3},{%4,%5,%6,%7},{%8,%9},{%0,%1,%2,%3};"
        : "+f"(d0), "+f"(d1), "+f"(d2), "+f"(d3)
        : "r"(a.x), "r"(a.y), "r"(a.z), "r"(a.w), "r"(b0), "r"(b1));
}

// 4 chained K-steps, weights from global (LDG)
__device__ __forceinline__ void mma4g(float& d0, float& d1, float& d2, float& d3,
                                      const uint4* __restrict__ wa, const uint32_t* act,
                                      int g, int tg, int ks0)
{
#pragma unroll
    for (int k = 0; k < 4; k++) {
        int ks = ks0 + k;
        uint4 a = __ldg(wa + ks * 32);
        uint32_t b0 = act[(ks * 8 + tg) * 8 + g];
        uint32_t b1 = act[(ks * 8 + tg + 4) * 8 + g];
        mma16816(d0, d1, d2, d3, a, b0, b1);
    }
}

// ===================== prep: pack everything =====================
__global__ void prep_kernel(const float* __restrict__ Wih,
                            const float* __restrict__ Whh,
                            const float* __restrict__ bih,
                            const float* __restrict__ bhh,
                            const float* __restrict__ h2o_w)
{
    int idx = blockIdx.x * blockDim.x + threadIdx.x;
    if (idx < 6144) {
        int jp = idx % 192;
        int k4 = idx / 192;
        ulonglong2 v;
        v.x = pack4h(Wih + (size_t)jp * H_ + 4 * k4);
        v.y = pack4h(Wih + (size_t)(jp + 192) * H_ + 4 * k4);
        g_Wp[k4 * 192 + jp] = v;
    } else if (idx < 6144 + 4096) {
        int i2 = idx - 6144;
        int oi = i2 % H_;
        int k4 = i2 / H_;
        g_Wo[i2] = pack4h(h2o_w + oi * H_ + 4 * k4);
    } else if (idx < 6144 + 4096 + 18432) {
        int i2   = idx - 6144 - 4096;
        int lane = i2 % 32;
        int ks   = (i2 / 32) % 8;
        int tile = (i2 / 256) % 24;
        int m    = i2 / 6144;
        const float* W = (m == 0) ? Whh : ((m == 1) ? (Wih + (size_t)G_ * H_) : (Whh + (size_t)G_ * H_));
        int g = lane >> 2, tg = lane & 3;
        int j0 = tile * 16, k0 = ks * 16;
        uint4 v;
        v.x = h2pk(W[(j0 + g)     * H_ + k0 + tg * 2], W[(j0 + g)     * H_ + k0 + tg * 2 + 1]);
        v.y = h2pk(W[(j0 + g + 8) * H_ + k0 + tg * 2], W[(j0 + g + 8) * H_ + k0 + tg * 2 + 1]);
        v.z = h2pk(W[(j0 + g)     * H_ + k0 + 8 + tg * 2], W[(j0 + g)     * H_ + k0 + 8 + tg * 2 + 1]);
        v.w = h2pk(W[(j0 + g + 8) * H_ + k0 + 8 + tg * 2], W[(j0 + g + 8) * H_ + k0 + 8 + tg * 2 + 1]);
        g_Wf[i2] = v;
    } else if (idx < 6144 + 4096 + 18432 + 1280) {
        int i3 = idx - 6144 - 4096 - 18432;
        int s = i3 / 32, lane = i3 % 32, g = lane >> 2;
        float2 v;
        if (s < 8) {
            int j0 = 256 + s * 16;
            v = make_float2(bhh[j0 + g], bhh[j0 + g + 8]);
        } else if (s < 24) {
            int j0 = (s - 8) * 16;
            v = make_float2(bih[G_ + j0 + g] + bhh[G_ + j0 + g],
                            bih[G_ + j0 + g + 8] + bhh[G_ + j0 + g + 8]);
        } else if (s < 32) {
            int j0 = 256 + (s - 24) * 16;
            v = make_float2(bih[G_ + j0 + g], bih[G_ + j0 + g + 8]);
        } else {
            int j0 = 256 + (s - 32) * 16;
            v = make_float2(bhh[G_ + j0 + g], bhh[G_ + j0 + g + 8]);
        }
        g_biasf[i3] = v;
    }
}

// scalar 2j matvec (pre_kernel only)
__device__ __forceinline__ void mv2j32(const ull* __restrict__ act,
                                       const ulonglong2* __restrict__ w,
                                       float out[2][8], float b0, float b1)
{
    ull acc[2][8];
#pragma unroll
    for (int r = 0; r < 8; r++) { acc[0][r] = pack2(b0, 0.f); acc[1][r] = pack2(b1, 0.f); }
#pragma unroll 8
    for (int k4 = 0; k4 < 32; k4++) {
        ulonglong2 ww;
        asm("ld.global.nc.v2.u64 {%0,%1},[%2];" : "=l"(ww.x), "=l"(ww.y) : "l"(w + k4 * 192));
        ull w0A, w0B, w1A, w1B;
        cvt4(ww.x, w0A, w0B);
        cvt4(ww.y, w1A, w1B);
        const ull* xa = act + 2 * k4 * SU;
#pragma unroll
        for (int p = 0; p < 4; p++) {
            ulonglong2 xv = *(const ulonglong2*)(xa + 2 * p);
            fma2(acc[0][2*p],   w0A, xv.x); fma2(acc[0][2*p+1], w0A, xv.y);
            fma2(acc[1][2*p],   w1A, xv.x); fma2(acc[1][2*p+1], w1A, xv.y);
        }
#pragma unroll
        for (int p = 0; p < 4; p++) {
            ulonglong2 xv = *(const ulonglong2*)(xa + SU + 2 * p);
            fma2(acc[0][2*p],   w0B, xv.x); fma2(acc[0][2*p+1], w0B, xv.y);
            fma2(acc[1][2*p],   w1B, xv.x); fma2(acc[1][2*p+1], w1B, xv.y);
        }
    }
#pragma unroll
    for (int jj = 0; jj < 2; jj++)
#pragma unroll
        for (int r = 0; r < 8; r++) {
            float2 s = unpack2(acc[jj][r]);
            out[jj][r] = s.x + s.y;
        }
}

// ===================== pre-kernel =====================
__global__ void __launch_bounds__(768)
pre_kernel(const int* __restrict__ il,
           const float* __restrict__ emb,
           const float* __restrict__ bih,
           const float* __restrict__ bhh,
           float* __restrict__ out4)
{
    __shared__ __align__(16) ull xq[4 * NPBUF];
    const int tid = threadIdx.x;
    const int bg  = blockIdx.x / 50;
    const int t0  = (blockIdx.x % 50) * 4;
    const int b0  = bg * 8;

    for (int i = tid; i < 1024; i += 768) {
        int row = i >> 5, k4 = i & 31;
        int ts = row >> 3, n = row & 7;
        int tok = il[(b0 + n) * T_ + t0 + ts];
        float4 v = __ldg((const float4*)emb + (size_t)tok * 32 + k4);
        float* base = (float*)(xq + ts * NPBUF);
        base[PIDX(4*k4 + 0, n)] = v.x;
        base[PIDX(4*k4 + 1, n)] = v.y;
        base[PIDX(4*k4 + 2, n)] = v.z;
        base[PIDX(4*k4 + 3, n)] = v.w;
        ((float4*)(out4 + ((size_t)(b0 + n) * T_ + t0 + ts) * 256))[k4] = v;
    }
    __syncthreads();

    const int rg = tid / 192, jp = tid - rg * 192;
    const int t  = t0 + rg;
    const int j2 = jp + 192;
    float bv0 = bih[jp] + bhh[jp];
    float bv1 = bih[j2] + ((j2 < 256) ? bhh[j2] : 0.f);
    float out[2][8];
    mv2j32(xq + rg * NPBUF, g_Wp + jp, out, bv0, bv1);

#pragma unroll
    for (int jj = 0; jj < 2; jj++) {
        int j = jp + jj * 192;
        if (j < 256) {
            int tile = j >> 4, gg = j & 7;
            int sub0 = ((j & 15) >= 8) ? 2 : 0;
            float* basep = (float*)(g_gi0f + (((size_t)bg * 200 + t) * 16 + tile) * 32);
#pragma unroll
            for (int n = 0; n < 8; n++)
                basep[(gg * 4 + (n >> 1)) * 4 + sub0 + (n & 1)] = out[jj][n];
        } else {
            float* p = g_gi0n + (((size_t)bg * 200 + t) * 128 + (j - 256)) * 8;
            *(float4*)p       = make_float4(out[jj][0], out[jj][1], out[jj][2], out[jj][3]);
            *(float4*)(p + 4) = make_float4(out[jj][4], out[jj][5], out[jj][6], out[jj][7]);
        }
    }
}

// ===================== post-kernel =====================
__global__ void __launch_bounds__(128)
post_kernel(const float* __restrict__ h2o_b,
            float* __restrict__ out1,
            float* __restrict__ out4)
{
    __shared__ __align__(16) ull xp[NPBUF];
    const int j   = threadIdx.x;
    const int bt0 = blockIdx.x * ROWS;
    float* xpf = (float*)xp;
#pragma unroll
    for (int r = 0; r < ROWS; r++)
        xpf[PIDX(j, r)] = g_h1[(size_t)(bt0 + r) * H_ + j];
    __syncthreads();

    const ull* w = g_Wo + j;
    float ob = h2o_b[j];
    ull acc[ROWS];
#pragma unroll
    for (int r = 0; r < ROWS; r++) acc[r] = pack2(ob, 0.0f);
#pragma unroll 4
    for (int k4 = 0; k4 < 32; k4++) {
        ull wA, wB; cvt4(__ldg(w + k4 * H_), wA, wB);
        const ull* xa = xp + (2 * k4) * SU;
#pragma unroll
        for (int p = 0; p < 4; p++) {
            ulonglong2 xv = *(const ulonglong2*)(xa + 2 * p);
            fma2(acc[2*p], wA, xv.x); fma2(acc[2*p+1], wA, xv.y);
        }
#pragma unroll
        for (int p = 0; p < 4; p++) {
            ulonglong2 xv = *(const ulonglong2*)(xa + SU + 2 * p);
            fma2(acc[2*p], wB, xv.x); fma2(acc[2*p+1], wB, xv.y);
        }
    }
#pragma unroll
    for (int r = 0; r < ROWS; r++) {
        float2 s = unpack2(acc[r]);
        float o  = tanh_fast(s.x + s.y);
        int bt = bt0 + r;
        int b  = bt / T_;
        int t  = bt - b * T_;
        out4[(size_t)bt * 256 + H_ + j] = o;
        if (t < T_ - 1)
            out1[((size_t)b * (T_ - 1) + t) * H_ + j] = o;
    }
}

// ===================== recurrence loop: warp-specialized 2-stage pipeline =====================
// Group A (warps 0-3, 128 thr): layer 0. Group B (warps 4-11, 256 thr): layer 1.
// A(t) runs concurrently with B(t-1). Handoff buffer sbb double-buffered.
// Named barriers: 1=A-internal, 2=B-internal, 3/4=full[parity], 5/6=empty[parity].
__global__ void __launch_bounds__(384, 1)
gru_loop(const float* __restrict__ mask)
{
    __shared__ uint32_t sh0[512], sh1[512], sbb[2][512];
    __shared__ float gatesA[8 * GST];
    __shared__ float gatesB[8 * GST];
    __shared__ float skA[8], skB[8];

    const int tid  = threadIdx.x;
    const int w    = tid >> 5;
    const int lane = tid & 31;
    const int g    = lane >> 2;
    const int tg   = lane & 3;
    const int bg   = blockIdx.x;
    const int b0   = bg * 8;
    const bool isA = (tid < 128);

    for (int i = tid; i < 512; i += 384) { sh0[i] = 0u; sh1[i] = 0u; }
    __syncthreads();

    const float4* gi0f_b = g_gi0f + (size_t)bg * 200 * 16 * 32;
    const float*  gi0n_b = g_gi0n + (size_t)bg * 200 * 128 * 8;

    __half* H0 = (__half*)sh0;
    __half* H1 = (__half*)sh1;

    for (int t = 0; t <= T_; t++) {
        if (isA) {
            if (t < T_) {
                if (t >= 2) BAR_SYNC(5 + (t & 1), 384);        // wait buffer empty
                if (tid < 8)
                    skA[tid] = (mask[(b0 + tid) * T_ + t] != 0.0f) ? 1.0f : 0.0f;

                // L0 MMA: 24 tiles over 4 warps
#pragma unroll
                for (int u = 0; u < 6; u++) {
                    int tt = u * 4 + w;
                    float d0, d1, d2, d3;
                    if (tt < 16) {
                        float4 v = __ldg(gi0f_b + ((size_t)t * 16 + tt) * 32 + lane);
                        d0 = v.x; d1 = v.y; d2 = v.z; d3 = v.w;
                    } else {
                        float2 bv = g_biasf[(tt - 16) * 32 + lane];
                        d0 = bv.x; d1 = bv.x; d2 = bv.y; d3 = bv.y;
                    }
                    float e0 = 0.f, e1 = 0.f, e2 = 0.f, e3 = 0.f;
                    const uint4* wg = g_Wf + (size_t)tt * 256 + lane;
                    mma4g(d0, d1, d2, d3, wg, sh0, g, tg, 0);
                    mma4g(e0, e1, e2, e3, wg, sh0, g, tg, 4);
                    d0 += e0; d1 += e1; d2 += e2; d3 += e3;
                    int jd = (tt < 16) ? tt * 16 : 384 + (tt - 16) * 16;
                    gatesA[(tg*2)   * GST + jd + g]     = d0;
                    gatesA[(tg*2+1) * GST + jd + g]     = d1;
                    gatesA[(tg*2)   * GST + jd + g + 8] = d2;
                    gatesA[(tg*2+1) * GST + jd + g + 8] = d3;
                }
                BAR_SYNC(1, 128);

                // pointwise L0: 128 threads, col = tid, all 8 rows
                {
                    const int col = tid;
                    const float* ip = gi0n_b + ((size_t)t * 128 + col) * 8;
                    float4 ia = *(const float4*)ip;
                    float4 ib = *(const float4*)(ip + 4);
                    float inn[8] = {ia.x, ia.y, ia.z, ia.w, ib.x, ib.y, ib.z, ib.w};
                    __half* BB = (__half*)sbb[t & 1];
#pragma unroll
                    for (int r = 0; r < 8; r++) {
                        float rv = sigmoid_fast(gatesA[r * GST + col]);
                        float zv = sigmoid_fast(gatesA[r * GST + 128 + col]);
                        float hn = gatesA[r * GST + 384 + col];
                        float nv = tanh_fast(fmaf(rv, hn, inn[r]));
                        int hidx = (col >> 1) * 16 + r * 2 + (col & 1);
                        float ho = __half2float(H0[hidx]);
                        float hw = fmaf(zv, ho - nv, nv);
                        BB[hidx] = __float2half_rn(hw);
                        H0[hidx] = __float2half_rn(hw * skA[r]);
                    }
                }
                BAR_ARRIVE(3 + (t & 1), 384);                  // buffer full
                BAR_SYNC(1, 128);                              // protect sh0 for next MMA
            }
        } else {
            if (t >= 1) {
                const int tb = t - 1;
                BAR_SYNC(3 + (tb & 1), 384);                   // wait buffer full (also B-internal)
                if (tid - 128 < 8)
                    skB[tid - 128] = (mask[(b0 + tid - 128) * T_ + tb] != 0.0f) ? 1.0f : 0.0f;

                const uint32_t* act = sbb[tb & 1];
                const int wb = w - 4;                          // 0..7

                // rz tiles: 2 per warp
#pragma unroll
                for (int u = 0; u < 2; u++) {
                    int tt = wb * 2 + u;
                    float2 bv = g_biasf[(8 + tt) * 32 + lane];
                    float d0 = bv.x, d1 = bv.x, d2 = bv.y, d3 = bv.y;
                    float e0 = 0.f, e1 = 0.f, e2 = 0.f, e3 = 0.f;
                    float f0 = 0.f, f1 = 0.f, f2 = 0.f, f3 = 0.f;
                    float h0a = 0.f, h1a = 0.f, h2a = 0.f, h3a = 0.f;
                    const uint4* wg1 = g_Wf + 6144  + (size_t)tt * 256 + lane;   // Wih1
                    const uint4* wg2 = g_Wf + 12288 + (size_t)tt * 256 + lane;   // Whh1
                    mma4g(d0, d1, d2, d3, wg1, act, g, tg, 0);
                    mma4g(e0, e1, e2, e3, wg1, act, g, tg, 4);
                    mma4g(f0, f1, f2, f3, wg2, sh1, g, tg, 0);
                    mma4g(h0a, h1a, h2a, h3a, wg2, sh1, g, tg, 4);
                    d0 += e0 + f0 + h0a; d1 += e1 + f1 + h1a;
                    d2 += e2 + f2 + h2a; d3 += e3 + f3 + h3a;
                    int jd = tt * 16;
                    gatesB[(tg*2)   * GST + jd + g]     = d0;
                    gatesB[(tg*2+1) * GST + jd + g]     = d1;
                    gatesB[(tg*2)   * GST + jd + g + 8] = d2;
                    gatesB[(tg*2+1) * GST + jd + g + 8] = d3;
                }
                // inn tile: 1 per warp (last reader of sbb)
                {
                    int s = wb;
                    float2 bv = g_biasf[(24 + s) * 32 + lane];
                    float d0 = bv.x, d1 = bv.x, d2 = bv.y, d3 = bv.y;
                    float e0 = 0.f, e1 = 0.f, e2 = 0.f, e3 = 0.f;
                    const uint4* wg = g_Wf + 6144 + (size_t)(16 + s) * 256 + lane;
                    mma4g(d0, d1, d2, d3, wg, act, g, tg, 0);
                    mma4g(e0, e1, e2, e3, wg, act, g, tg, 4);
                    d0 += e0; d1 += e1; d2 += e2; d3 += e3;
                    int jd = 256 + s * 16;
                    gatesB[(tg*2)   * GST + jd + g]     = d0;
                    gatesB[(tg*2+1) * GST + jd + g]     = d1;
                    gatesB[(tg*2)   * GST + jd + g + 8] = d2;
                    gatesB[(tg*2+1) * GST + jd + g + 8] = d3;
                }
                BAR_ARRIVE(5 + (tb & 1), 384);                 // buffer empty (sbb reads done)

                // hn tile: 1 per warp (reads sh1 only)
                {
                    int s = wb;
                    float2 bv = g_biasf[(32 + s) * 32 + lane];
                    float d0 = bv.x, d1 = bv.x, d2 = bv.y, d3 = bv.y;
                    float e0 = 0.f, e1 = 0.f, e2 = 0.f, e3 = 0.f;
                    const uint4* wg = g_Wf + 12288 + (size_t)(16 + s) * 256 + lane;
                    mma4g(d0, d1, d2, d3, wg, sh1, g, tg, 0);
                    mma4g(e0, e1, e2, e3, wg, sh1, g, tg, 4);
                    d0 += e0; d1 += e1; d2 += e2; d3 += e3;
                    int jd = 384 + s * 16;
                    gatesB[(tg*2)   * GST + jd + g]     = d0;
                    gatesB[(tg*2+1) * GST + jd + g]     = d1;
                    gatesB[(tg*2)   * GST + jd + g + 8] = d2;
                    gatesB[(tg*2+1) * GST + jd + g + 8] = d3;
                }
                BAR_SYNC(2, 256);

                // pointwise L1: 256 threads
                {
                    const int tidB = tid - 128;
                    const int col  = tidB & 127;
                    const int rg4  = tidB >> 7;
#pragma unroll
                    for (int rr = 0; rr < 4; rr++) {
                        int r = rg4 * 4 + rr;
                        float rv  = sigmoid_fast(gatesB[r * GST + col]);
                        float zv  = sigmoid_fast(gatesB[r * GST + 128 + col]);
                        float inn = gatesB[r * GST + 256 + col];
                        float hn  = gatesB[r * GST + 384 + col];
                        float nv  = tanh_fast(fmaf(rv, hn, inn));
                        int hidx = (col >> 1) * 16 + r * 2 + (col & 1);
                        float ho = __half2float(H1[hidx]);
                        float hw = fmaf(zv, ho - nv, nv);
                        g_h1[((size_t)(b0 + r) * T_ + tb) * H_ + col] = hw;
                        H1[hidx] = __float2half_rn(hw * skB[r]);
                    }
                }
            }
        }
    }
}

// out2/out3 gathers
__global__ void gather_kernel(const int* __restrict__ il,
                              const int* __restrict__ neg,
                              const float4* __restrict__ emb4,
                              float4* __restrict__ out2,
                              float4* __restrict__ out3)
{
    int idx = blockIdx.x * blockDim.x + threadIdx.x;
    const int n4 = B_ * (T_ - 1) * (H_ / 4);
    if (idx >= n4) return;
    int k4 = idx & 31;
    int bt = idx >> 5;
    int b  = bt / (T_ - 1);
    int t  = bt - b * (T_ - 1);
    int p  = il [b * T_ + t + 1];
    int qd = neg[b * T_ + t];
    out2[idx] = __ldg(emb4 + (size_t)p  * 32 + k4);
    out3[idx] = __ldg(emb4 + (size_t)qd * 32 + k4);
}

extern "C" void kernel_launch(void* const* d_in, const int* in_sizes, int n_in,
                              void* d_out, int out_size)
{
    const int*   il    = (const int*)  d_in[0];
    const float* mask  = (const float*)d_in[1];
    const int*   neg   = (const int*)  d_in[2];
    const float* emb   = (const float*)d_in[3];
    const float* Wih   = (const float*)d_in[4];
    const float* Whh   = (const float*)d_in[5];
    const float* bih   = (const float*)d_in[6];
    const float* bhh   = (const float*)d_in[7];
    const float* h2o_w = (const float*)d_in[8];
    const float* h2o_b = (const float*)d_in[9];

    float* out  = (float*)d_out;
    float* out1 = out;
    float* out2 = out1 + (size_t)B_ * (T_ - 1) * H_;
    float* out3 = out2 + (size_t)B_ * (T_ - 1) * H_;
    float* out4 = out3 + (size_t)B_ * (T_ - 1) * H_;

    const int nprep = 6144 + 4096 + 18432 + 1280;
    prep_kernel<<<(nprep + 255) / 256, 256>>>(Wih, Whh, bih, bhh, h2o_w);

    const int n4 = B_ * (T_ - 1) * (H_ / 4);
    gather_kernel<<<(n4 + 255) / 256, 256>>>(il, neg, (const float4*)emb,
                                             (float4*)out2, (float4*)out3);

    pre_kernel<<<128 * 50, 768>>>(il, emb, bih, bhh, out4);

    gru_loop<<<NCTA, 384>>>(mask);

    post_kernel<<<NBT / ROWS, 128>>>(h2o_b, out1, out4);
}

// round 14
// speedup vs baseline: 4.5474x; 1.8515x over previous
#include <cuda_runtime.h>
#include <cuda_fp16.h>
#include <cstdint>

#define B_   1024
#define T_   200
#define H_   128
#define G_   384
#define ROWS 8
#define NCTA 128
#define NBT  (B_*T_)

#define SU 10
#define NPBUF (64*SU)
#define PIDX(u,r) (((u)>>1)*(2*SU) + 2*(r) + ((u)&1))

typedef unsigned long long ull;

// mma weights in A-fragment order: m=0 Whh0, 1 Wih1, 2 Whh1, 3 Wih0; [m][tile24][ks8][lane32]
#define WFSZ 6144
__device__ uint4  g_Wf[4*WFSZ];
__device__ ull    g_Wo[32*128];             // h2o fp16 [k4][oi] (scalar post)
__device__ float2 g_biasf[40*32];           // loop biases, D-frag order
__device__ float2 g_biasP[24*32];           // pre biases, D-frag order
// gi0: all 24 tiles in D-frag order: [bg128][t200][tile24][lane32] float4
__device__ float4 g_gi0[(size_t)128*200*24*32];
__device__ float  g_h1[(size_t)NBT*H_];

// ---- helpers ----
__device__ __forceinline__ ull pack2(float a, float b) {
    ull r; asm("mov.b64 %0,{%1,%2};" : "=l"(r) : "f"(a), "f"(b)); return r;
}
__device__ __forceinline__ void fma2(ull& c, ull a, ull b) {
    asm("fma.rn.f32x2 %0,%1,%2,%0;" : "+l"(c) : "l"(a), "l"(b));
}
__device__ __forceinline__ float2 unpack2(ull v) {
    float lo, hi; asm("mov.b64 {%0,%1},%2;" : "=f"(lo), "=f"(hi) : "l"(v));
    return make_float2(lo, hi);
}
__device__ __forceinline__ void cvt4(ull w, ull& A, ull& B) {
    uint32_t lo = (uint32_t)w, hi = (uint32_t)(w >> 32);
    __half2 h0 = *reinterpret_cast<__half2*>(&lo);
    __half2 h1 = *reinterpret_cast<__half2*>(&hi);
    float2 f0 = __half22float2(h0);
    float2 f1 = __half22float2(h1);
    A = pack2(f0.x, f0.y);
    B = pack2(f1.x, f1.y);
}
__device__ __forceinline__ float sigmoid_fast(float x) {
    return __fdividef(1.0f, 1.0f + __expf(-x));
}
__device__ __forceinline__ float tanh_fast(float x) {
    float ax = fabsf(x);
    float e  = __expf(-2.0f * ax);
    float t  = __fdividef(1.0f - e, 1.0f + e);
    return copysignf(t, x);
}
__device__ __forceinline__ ull pack4h(const float* row) {
    ull a = (ull)__half_as_ushort(__float2half_rn(row[0]));
    ull b = (ull)__half_as_ushort(__float2half_rn(row[1]));
    ull c = (ull)__half_as_ushort(__float2half_rn(row[2]));
    ull d = (ull)__half_as_ushort(__float2half_rn(row[3]));
    return a | (b << 16) | (c << 32) | (d << 48);
}
__device__ __forceinline__ uint32_t h2pk(float a, float b) {
    __half2 h = __floats2half2_rn(a, b);
    return *reinterpret_cast<uint32_t*>(&h);
}

// m16n8k16 f16*f16+f32 mma, accumulate into d[4]
__device__ __forceinline__ void mma4(float d[4], uint4 a, uint32_t b0, uint32_t b1)
{
    asm volatile(
        "mma.sync.aligned.m16n8k16.row.col.f32.f16.f16.f32 "
        "{%0,%1,%2,%3},{%4,%5,%6,%7},{%8,%9},{%0,%1,%2,%3};"
        : "+f"(d[0]), "+f"(d[1]), "+f"(d[2]), "+f"(d[3])
        : "r"(a.x), "r"(a.y), "r"(a.z), "r"(a.w), "r"(b0), "r"(b1));
}

// 8-step chain over a tile, weights via LDG, B-frags from registers
__device__ __forceinline__ void chain8(float d[4], const uint4* __restrict__ wp,
                                       const uint32_t* bf)
{
#pragma unroll
    for (int ks = 0; ks < 8; ks++) {
        uint4 a = __ldg(wp + ks * 32);
        mma4(d, a, bf[2*ks], bf[2*ks+1]);
    }
}

// ===================== prep: pack everything =====================
__global__ void prep_kernel(const float* __restrict__ Wih,
                            const float* __restrict__ Whh,
                            const float* __restrict__ bih,
                            const float* __restrict__ bhh,
                            const float* __restrict__ h2o_w)
{
    int idx = blockIdx.x * blockDim.x + threadIdx.x;
    if (idx < 4*WFSZ) {
        int r    = idx % WFSZ;
        int m    = idx / WFSZ;
        int lane = r % 32;
        int ks   = (r / 32) % 8;
        int tile = r / 256;
        const float* W = (m == 0) ? Whh
                       : (m == 1) ? (Wih + (size_t)G_ * H_)
                       : (m == 2) ? (Whh + (size_t)G_ * H_)
                                  : Wih;
        int g = lane >> 2, tg = lane & 3;
        int j0 = tile * 16, k0 = ks * 16;
        uint4 v;
        v.x = h2pk(W[(j0 + g)     * H_ + k0 + tg * 2], W[(j0 + g)     * H_ + k0 + tg * 2 + 1]);
        v.y = h2pk(W[(j0 + g + 8) * H_ + k0 + tg * 2], W[(j0 + g + 8) * H_ + k0 + tg * 2 + 1]);
        v.z = h2pk(W[(j0 + g)     * H_ + k0 + 8 + tg * 2], W[(j0 + g)     * H_ + k0 + 8 + tg * 2 + 1]);
        v.w = h2pk(W[(j0 + g + 8) * H_ + k0 + 8 + tg * 2], W[(j0 + g + 8) * H_ + k0 + 8 + tg * 2 + 1]);
        g_Wf[idx] = v;
    } else if (idx < 4*WFSZ + 4096) {
        int i2 = idx - 4*WFSZ;
        int oi = i2 % H_;
        int k4 = i2 / H_;
        g_Wo[i2] = pack4h(h2o_w + oi * H_ + 4 * k4);
    } else if (idx < 4*WFSZ + 4096 + 1280) {
        int i3 = idx - 4*WFSZ - 4096;
        int s = i3 / 32, lane = i3 % 32, g = lane >> 2;
        float2 v;
        if (s < 8) {                     // L0 hn: bhh0 n
            int j0 = 256 + s * 16;
            v = make_float2(bhh[j0 + g], bhh[j0 + g + 8]);
        } else if (s < 24) {             // L1 rz: bih1+bhh1
            int j0 = (s - 8) * 16;
            v = make_float2(bih[G_ + j0 + g] + bhh[G_ + j0 + g],
                            bih[G_ + j0 + g + 8] + bhh[G_ + j0 + g + 8]);
        } else if (s < 32) {             // L1 inn: bih1 n
            int j0 = 256 + (s - 24) * 16;
            v = make_float2(bih[G_ + j0 + g], bih[G_ + j0 + g + 8]);
        } else {                         // L1 hn: bhh1 n
            int j0 = 256 + (s - 32) * 16;
            v = make_float2(bhh[G_ + j0 + g], bhh[G_ + j0 + g + 8]);
        }
        g_biasf[i3] = v;
    } else if (idx < 4*WFSZ + 4096 + 1280 + 768) {
        int i4 = idx - 4*WFSZ - 4096 - 1280;
        int s = i4 / 32, lane = i4 % 32, g = lane >> 2;
        float2 v;
        if (s < 16) {                    // L0 rz: bih0+bhh0
            int j0 = s * 16;
            v = make_float2(bih[j0 + g] + bhh[j0 + g],
                            bih[j0 + g + 8] + bhh[j0 + g + 8]);
        } else {                         // L0 inn: bih0 n
            int j0 = 256 + (s - 16) * 16;
            v = make_float2(bih[j0 + g], bih[j0 + g + 8]);
        }
        g_biasP[i4] = v;
    }
}

// ===================== pre-kernel: gi0 via tensor cores + out4-low =====================
// grid = 256: block = (bg, t-half). 8 warps, each owns its own act buffer and t-strides.
__global__ void __launch_bounds__(256)
pre_kernel(const int* __restrict__ il,
           const float* __restrict__ emb,
           float* __restrict__ out4)
{
    __shared__ uint32_t act[8][512];
    const int tid  = threadIdx.x;
    const int w    = tid >> 5;
    const int lane = tid & 31;
    const int g    = lane >> 2;
    const int tg   = lane & 3;
    const int bg   = blockIdx.x >> 1;
    const int th   = blockIdx.x & 1;
    const int b0   = bg * 8;

    const uint4* wbase = g_Wf + 3 * WFSZ;
    uint32_t* aw = act[w];
    const int n = lane >> 2;          // row for gather (4 lanes share)

    for (int t = th * 100 + w; t < th * 100 + 100; t += 8) {
        int tok = il[(b0 + n) * T_ + t];
        const float4* erow = (const float4*)emb + (size_t)tok * 32;
        float4* o4 = (float4*)(out4 + ((size_t)(b0 + n) * T_ + t) * 256);
#pragma unroll
        for (int i = 0; i < 8; i++) {
            int c = (lane & 3) + 4 * i;        // float4 chunk 0..31
            float4 v = __ldg(erow + c);
            o4[c] = v;
            aw[16 * c + n]     = h2pk(v.x, v.y);
            aw[16 * c + 8 + n] = h2pk(v.z, v.w);
        }
        __syncwarp();

        // B-frags once, reused across all 24 tiles
        uint32_t bf[16];
#pragma unroll
        for (int ks = 0; ks < 8; ks++) {
            bf[2*ks]   = aw[(ks * 8 + tg) * 8 + g];
            bf[2*ks+1] = aw[(ks * 8 + tg + 4) * 8 + g];
        }

        float4* gout = g_gi0 + ((size_t)bg * 200 + t) * 24 * 32 + lane;
#pragma unroll 2
        for (int tt = 0; tt < 24; tt++) {
            float2 bv = g_biasP[tt * 32 + lane];
            float d[4] = {bv.x, bv.x, bv.y, bv.y};
            chain8(d, wbase + tt * 256 + lane, bf);
            gout[tt * 32] = make_float4(d[0], d[1], d[2], d[3]);
        }
        __syncwarp();
    }
}

// ===================== post-kernel: h2o GEMM + tanh (scalar) =====================
__global__ void __launch_bounds__(128)
post_kernel(const float* __restrict__ h2o_b,
            float* __restrict__ out1,
            float* __restrict__ out4)
{
    __shared__ __align__(16) ull xp[NPBUF];
    const int j   = threadIdx.x;
    const int bt0 = blockIdx.x * ROWS;
    float* xpf = (float*)xp;
#pragma unroll
    for (int r = 0; r < ROWS; r++)
        xpf[PIDX(j, r)] = g_h1[(size_t)(bt0 + r) * H_ + j];
    __syncthreads();

    const ull* w = g_Wo + j;
    float ob = h2o_b[j];
    ull acc[ROWS];
#pragma unroll
    for (int r = 0; r < ROWS; r++) acc[r] = pack2(ob, 0.0f);
#pragma unroll 4
    for (int k4 = 0; k4 < 32; k4++) {
        ull wA, wB; cvt4(__ldg(w + k4 * H_), wA, wB);
        const ull* xa = xp + (2 * k4) * SU;
#pragma unroll
        for (int p = 0; p < 4; p++) {
            ulonglong2 xv = *(const ulonglong2*)(xa + 2 * p);
            fma2(acc[2*p], wA, xv.x); fma2(acc[2*p+1], wA, xv.y);
        }
#pragma unroll
        for (int p = 0; p < 4; p++) {
            ulonglong2 xv = *(const ulonglong2*)(xa + SU + 2 * p);
            fma2(acc[2*p], wB, xv.x); fma2(acc[2*p+1], wB, xv.y);
        }
    }
#pragma unroll
    for (int r = 0; r < ROWS; r++) {
        float2 s = unpack2(acc[r]);
        float o  = tanh_fast(s.x + s.y);
        int bt = bt0 + r;
        int b  = bt / T_;
        int t  = bt - b * T_;
        out4[(size_t)bt * 256 + H_ + j] = o;
        if (t < T_ - 1)
            out1[((size_t)b * (T_ - 1) + t) * H_ + j] = o;
    }
}

// ===================== recurrence loop: in-register pointwise, 2 barriers/step =====================
__global__ void __launch_bounds__(256, 1)
gru_loop(const float* __restrict__ mask)
{
    __shared__ uint32_t h0s[2][512], h1s[2][512], bbs[512];

    const int tid  = threadIdx.x;
    const int w    = tid >> 5;        // warp 0..7: owns hidden cols [16w,16w+16)
    const int lane = tid & 31;
    const int g    = lane >> 2;
    const int tg   = lane & 3;
    const int bg   = blockIdx.x;
    const int b0   = bg * 8;
    const int r0   = tg * 2;

    for (int i = tid; i < 512; i += 256) {
        h0s[0][i] = 0u; h0s[1][i] = 0u;
        h1s[0][i] = 0u; h1s[1][i] = 0u;
    }

    // weight tile pointers (frag-packed, LDG each step; L1/L2-hot)
    const uint4* W0r  = g_Wf + (0*24 +      w) * 256 + lane;
    const uint4* W0z  = g_Wf + (0*24 +  8 + w) * 256 + lane;
    const uint4* W0n  = g_Wf + (0*24 + 16 + w) * 256 + lane;
    const uint4* W1ir = g_Wf + (1*24 +      w) * 256 + lane;
    const uint4* W1iz = g_Wf + (1*24 +  8 + w) * 256 + lane;
    const uint4* W1in = g_Wf + (1*24 + 16 + w) * 256 + lane;
    const uint4* W1hr = g_Wf + (2*24 +      w) * 256 + lane;
    const uint4* W1hz = g_Wf + (2*24 +  8 + w) * 256 + lane;
    const uint4* W1hn = g_Wf + (2*24 + 16 + w) * 256 + lane;

    // biases hoisted for all 200 steps
    const float2 b0hn = g_biasf[( 0 + w) * 32 + lane];
    const float2 b1r  = g_biasf[( 8 + w) * 32 + lane];
    const float2 b1z  = g_biasf[(16 + w) * 32 + lane];
    const float2 b1n  = g_biasf[(24 + w) * 32 + lane];
    const float2 b1hn = g_biasf[(32 + w) * 32 + lane];

    const float4* gp = g_gi0 + (size_t)bg * 200 * 24 * 32 + lane;

    // prefetch t=0
    float4 gr = __ldg(gp + (0*24 +      w) * 32);
    float4 gz = __ldg(gp + (0*24 +  8 + w) * 32);
    float4 gn = __ldg(gp + (0*24 + 16 + w) * 32);
    float mk0 = (__ldg(mask + (b0 + r0)     * T_) != 0.0f) ? 1.0f : 0.0f;
    float mk1 = (__ldg(mask + (b0 + r0 + 1) * T_) != 0.0f) ? 1.0f : 0.0f;

    float h0reg[4] = {0.f, 0.f, 0.f, 0.f};
    float h1reg[4] = {0.f, 0.f, 0.f, 0.f};

    // precomputed store indices (halves) for (r0,c0),(r0+1,c0),(r0,c0+8),(r0+1,c0+8)
    const int c0 = 16 * w + g;
    const int hx0 = (c0 >> 1) * 16 + r0 * 2 + (c0 & 1);
    const int c1 = c0 + 8;
    const int hx2 = (c1 >> 1) * 16 + r0 * 2 + (c1 & 1);

    __syncthreads();

    for (int t = 0; t < T_; t++) {
        const int p = t & 1, q = p ^ 1;

        // ================= Phase 1: layer 0 =================
        uint32_t hb[16];
        {
            const uint32_t* a0 = h0s[p];
#pragma unroll
            for (int ks = 0; ks < 8; ks++) {
                hb[2*ks]   = a0[(ks * 8 + tg) * 8 + g];
                hb[2*ks+1] = a0[(ks * 8 + tg + 4) * 8 + g];
            }
        }
        float dr[4] = {gr.x, gr.y, gr.z, gr.w};
        float dz[4] = {gz.x, gz.y, gz.z, gz.w};
        float dn[4] = {gn.x, gn.y, gn.z, gn.w};
        float dhn[4] = {b0hn.x, b0hn.x, b0hn.y, b0hn.y};
        chain8(dr,  W0r, hb);
        chain8(dz,  W0z, hb);
        chain8(dhn, W0n, hb);

        // prefetch next step's gi0 + mask
        float4 gr2, gz2, gn2;
        float mkA = 0.f, mkB = 0.f;
        if (t + 1 < T_) {
            gr2 = __ldg(gp + ((t+1)*24 +      w) * 32);
            gz2 = __ldg(gp + ((t+1)*24 +  8 + w) * 32);
            gn2 = __ldg(gp + ((t+1)*24 + 16 + w) * 32);
            mkA = (__ldg(mask + (b0 + r0)     * T_ + t + 1) != 0.0f) ? 1.0f : 0.0f;
            mkB = (__ldg(mask + (b0 + r0 + 1) * T_ + t + 1) != 0.0f) ? 1.0f : 0.0f;
        }

        // pointwise L0 (in registers) + stores
        {
            __half* BB = (__half*)bbs;
            __half* HN = (__half*)h0s[q];
#pragma unroll
            for (int e = 0; e < 4; e++) {
                float rv = sigmoid_fast(dr[e]);
                float zv = sigmoid_fast(dz[e]);
                float nv = tanh_fast(fmaf(rv, dhn[e], dn[e]));
                float h  = fmaf(zv, h0reg[e] - nv, nv);
                float mk = (e & 1) ? mk1 : mk0;
                float hm = h * mk;
                h0reg[e] = hm;
                int hidx = ((e >> 1) ? hx2 : hx0) + (e & 1) * 2;
                BB[hidx] = __float2half_rn(h);
                HN[hidx] = __float2half_rn(hm);
            }
        }
        __syncthreads();                                   // B1

        // ================= Phase 2: layer 1 =================
        uint32_t bf[16], hf[16];
        {
            const uint32_t* ab = bbs;
            const uint32_t* a1 = h1s[p];
#pragma unroll
            for (int ks = 0; ks < 8; ks++) {
                bf[2*ks]   = ab[(ks * 8 + tg) * 8 + g];
                bf[2*ks+1] = ab[(ks * 8 + tg + 4) * 8 + g];
                hf[2*ks]   = a1[(ks * 8 + tg) * 8 + g];
                hf[2*ks+1] = a1[(ks * 8 + tg + 4) * 8 + g];
            }
        }
        float er[4]  = {b1r.x,  b1r.x,  b1r.y,  b1r.y};
        float ez[4]  = {b1z.x,  b1z.x,  b1z.y,  b1z.y};
        float en[4]  = {b1n.x,  b1n.x,  b1n.y,  b1n.y};
        float ehn[4] = {b1hn.x, b1hn.x, b1hn.y, b1hn.y};
        chain8(er,  W1ir, bf);
        chain8(er,  W1hr, hf);
        chain8(ez,  W1iz, bf);
        chain8(ez,  W1hz, hf);
        chain8(en,  W1in, bf);
        chain8(ehn, W1hn, hf);

        // pointwise L1 + stores
        {
            __half* HN = (__half*)h1s[q];
#pragma unroll
            for (int e = 0; e < 4; e++) {
                float rv = sigmoid_fast(er[e]);
                float zv = sigmoid_fast(ez[e]);
                float nv = tanh_fast(fmaf(rv, ehn[e], en[e]));
                float h  = fmaf(zv, h1reg[e] - nv, nv);
                float mk = (e & 1) ? mk1 : mk0;
                float hm = h * mk;
                h1reg[e] = hm;
                int row = r0 + (e & 1);
                int col = (e >> 1) ? c1 : c0;
                g_h1[((size_t)(b0 + row) * T_ + t) * H_ + col] = h;
                int hidx = ((e >> 1) ? hx2 : hx0) + (e & 1) * 2;
                HN[hidx] = __float2half_rn(hm);
            }
        }
        gr = gr2; gz = gz2; gn = gn2;
        mk0 = mkA; mk1 = mkB;
        __syncthreads();                                   // B2
    }
}

// out2/out3 gathers
__global__ void gather_kernel(const int* __restrict__ il,
                              const int* __restrict__ neg,
                              const float4* __restrict__ emb4,
                              float4* __restrict__ out2,
                              float4* __restrict__ out3)
{
    int idx = blockIdx.x * blockDim.x + threadIdx.x;
    const int n4 = B_ * (T_ - 1) * (H_ / 4);
    if (idx >= n4) return;
    int k4 = idx & 31;
    int bt = idx >> 5;
    int b  = bt / (T_ - 1);
    int t  = bt - b * (T_ - 1);
    int p  = il [b * T_ + t + 1];
    int qd = neg[b * T_ + t];
    out2[idx] = __ldg(emb4 + (size_t)p  * 32 + k4);
    out3[idx] = __ldg(emb4 + (size_t)qd * 32 + k4);
}

extern "C" void kernel_launch(void* const* d_in, const int* in_sizes, int n_in,
                              void* d_out, int out_size)
{
    const int*   il    = (const int*)  d_in[0];
    const float* mask  = (const float*)d_in[1];
    const int*   neg   = (const int*)  d_in[2];
    const float* emb   = (const float*)d_in[3];
    const float* Wih   = (const float*)d_in[4];
    const float* Whh   = (const float*)d_in[5];
    const float* bih   = (const float*)d_in[6];
    const float* bhh   = (const float*)d_in[7];
    const float* h2o_w = (const float*)d_in[8];
    const float* h2o_b = (const float*)d_in[9];

    float* out  = (float*)d_out;
    float* out1 = out;
    float* out2 = out1 + (size_t)B_ * (T_ - 1) * H_;
    float* out3 = out2 + (size_t)B_ * (T_ - 1) * H_;
    float* out4 = out3 + (size_t)B_ * (T_ - 1) * H_;

    const int nprep = 4*WFSZ + 4096 + 1280 + 768;
    prep_kernel<<<(nprep + 255) / 256, 256>>>(Wih, Whh, bih, bhh, h2o_w);

    const int n4 = B_ * (T_ - 1) * (H_ / 4);
    gather_kernel<<<(n4 + 255) / 256, 256>>>(il, neg, (const float4*)emb,
                                             (float4*)out2, (float4*)out3);

    pre_kernel<<<256, 256>>>(il, emb, out4);

    gru_loop<<<NCTA, 256>>>(mask);

    post_kernel<<<NBT / ROWS, 128>>>(h2o_b, out1, out4);
}

// round 15
// speedup vs baseline: 5.9597x; 1.3106x over previous
#include <cuda_runtime.h>
#include <cuda_fp16.h>
#include <cstdint>

#define B_   1024
#define T_   200
#define H_   128
#define G_   384
#define NCTA 128
#define NBT  (B_*T_)

typedef unsigned long long ull;

// mma weights in A-fragment order: m=0 Whh0, 1 Wih1, 2 Whh1, 3 Wih0; [m][tile24][ks8][lane32]
#define WFSZ 6144
__device__ uint4  g_Wf[4*WFSZ];
__device__ uint4  g_WoF[8*8*32];            // h2o frag-packed: [tile8][ks8][lane32]
__device__ float2 g_biasf[40*32];           // loop biases, D-frag order
__device__ float2 g_biasP[24*32];           // pre biases, D-frag order
__device__ float2 g_biasO[8*32];            // h2o biases, D-frag order
// gi0 fp16 D-frags: [bg128][t200][tile24][lane32] half4(ull)
__device__ ull    g_gi0h[(size_t)128*200*24*32];
// h1 fp16 B-frag-packed: [bg128][t200][1024 halves]
__device__ __half g_h1h[(size_t)128*200*1024];

// ---- helpers ----
__device__ __forceinline__ float sigmoid_fast(float x) {
    return __fdividef(1.0f, 1.0f + __expf(-x));
}
__device__ __forceinline__ float tanh_fast(float x) {
    float ax = fabsf(x);
    float e  = __expf(-2.0f * ax);
    float t  = __fdividef(1.0f - e, 1.0f + e);
    return copysignf(t, x);
}
__device__ __forceinline__ uint32_t h2pk(float a, float b) {
    __half2 h = __floats2half2_rn(a, b);
    return *reinterpret_cast<uint32_t*>(&h);
}
__device__ __forceinline__ float2 pk2f(uint32_t u) {
    __half2 h = *reinterpret_cast<__half2*>(&u);
    return __half22float2(h);
}

// m16n8k16 f16*f16+f32 mma, accumulate into d[4]
__device__ __forceinline__ void mma4(float d[4], uint4 a, uint32_t b0, uint32_t b1)
{
    asm volatile(
        "mma.sync.aligned.m16n8k16.row.col.f32.f16.f16.f32 "
        "{%0,%1,%2,%3},{%4,%5,%6,%7},{%8,%9},{%0,%1,%2,%3};"
        : "+f"(d[0]), "+f"(d[1]), "+f"(d[2]), "+f"(d[3])
        : "r"(a.x), "r"(a.y), "r"(a.z), "r"(a.w), "r"(b0), "r"(b1));
}

// 8-step chain over a tile, weights via LDG, B-frags from registers
__device__ __forceinline__ void chain8(float d[4], const uint4* __restrict__ wp,
                                       const uint32_t* bf)
{
#pragma unroll
    for (int ks = 0; ks < 8; ks++) {
        uint4 a = __ldg(wp + ks * 32);
        mma4(d, a, bf[2*ks], bf[2*ks+1]);
    }
}

// ===================== prep: pack everything =====================
__global__ void prep_kernel(const float* __restrict__ Wih,
                            const float* __restrict__ Whh,
                            const float* __restrict__ bih,
                            const float* __restrict__ bhh,
                            const float* __restrict__ h2o_w,
                            const float* __restrict__ h2o_b)
{
    int idx = blockIdx.x * blockDim.x + threadIdx.x;
    if (idx < 4*WFSZ) {
        int r    = idx % WFSZ;
        int m    = idx / WFSZ;
        int lane = r % 32;
        int ks   = (r / 32) % 8;
        int tile = r / 256;
        const float* W = (m == 0) ? Whh
                       : (m == 1) ? (Wih + (size_t)G_ * H_)
                       : (m == 2) ? (Whh + (size_t)G_ * H_)
                                  : Wih;
        int g = lane >> 2, tg = lane & 3;
        int j0 = tile * 16, k0 = ks * 16;
        uint4 v;
        v.x = h2pk(W[(j0 + g)     * H_ + k0 + tg * 2], W[(j0 + g)     * H_ + k0 + tg * 2 + 1]);
        v.y = h2pk(W[(j0 + g + 8) * H_ + k0 + tg * 2], W[(j0 + g + 8) * H_ + k0 + tg * 2 + 1]);
        v.z = h2pk(W[(j0 + g)     * H_ + k0 + 8 + tg * 2], W[(j0 + g)     * H_ + k0 + 8 + tg * 2 + 1]);
        v.w = h2pk(W[(j0 + g + 8) * H_ + k0 + 8 + tg * 2], W[(j0 + g + 8) * H_ + k0 + 8 + tg * 2 + 1]);
        g_Wf[idx] = v;
    } else if (idx < 4*WFSZ + 2048) {
        int i2   = idx - 4*WFSZ;
        int lane = i2 % 32;
        int ks   = (i2 / 32) % 8;
        int tile = i2 / 256;
        int g = lane >> 2, tg = lane & 3;
        int j0 = tile * 16, k0 = ks * 16;
        uint4 v;
        v.x = h2pk(h2o_w[(j0 + g)     * H_ + k0 + tg * 2], h2o_w[(j0 + g)     * H_ + k0 + tg * 2 + 1]);
        v.y = h2pk(h2o_w[(j0 + g + 8) * H_ + k0 + tg * 2], h2o_w[(j0 + g + 8) * H_ + k0 + tg * 2 + 1]);
        v.z = h2pk(h2o_w[(j0 + g)     * H_ + k0 + 8 + tg * 2], h2o_w[(j0 + g)     * H_ + k0 + 8 + tg * 2 + 1]);
        v.w = h2pk(h2o_w[(j0 + g + 8) * H_ + k0 + 8 + tg * 2], h2o_w[(j0 + g + 8) * H_ + k0 + 8 + tg * 2 + 1]);
        g_WoF[i2] = v;
    } else if (idx < 4*WFSZ + 2048 + 1280) {
        int i3 = idx - 4*WFSZ - 2048;
        int s = i3 / 32, lane = i3 % 32, g = lane >> 2;
        float2 v;
        if (s < 8) {                     // L0 hn: bhh0 n
            int j0 = 256 + s * 16;
            v = make_float2(bhh[j0 + g], bhh[j0 + g + 8]);
        } else if (s < 24) {             // L1 rz: bih1+bhh1
            int j0 = (s - 8) * 16;
            v = make_float2(bih[G_ + j0 + g] + bhh[G_ + j0 + g],
                            bih[G_ + j0 + g + 8] + bhh[G_ + j0 + g + 8]);
        } else if (s < 32) {             // L1 inn: bih1 n
            int j0 = 256 + (s - 24) * 16;
            v = make_float2(bih[G_ + j0 + g], bih[G_ + j0 + g + 8]);
        } else {                         // L1 hn: bhh1 n
            int j0 = 256 + (s - 32) * 16;
            v = make_float2(bhh[G_ + j0 + g], bhh[G_ + j0 + g + 8]);
        }
        g_biasf[i3] = v;
    } else if (idx < 4*WFSZ + 2048 + 1280 + 768) {
        int i4 = idx - 4*WFSZ - 2048 - 1280;
        int s = i4 / 32, lane = i4 % 32, g = lane >> 2;
        float2 v;
        if (s < 16) {                    // L0 rz: bih0+bhh0
            int j0 = s * 16;
            v = make_float2(bih[j0 + g] + bhh[j0 + g],
                            bih[j0 + g + 8] + bhh[j0 + g + 8]);
        } else {                         // L0 inn: bih0 n
            int j0 = 256 + (s - 16) * 16;
            v = make_float2(bih[j0 + g], bih[j0 + g + 8]);
        }
        g_biasP[i4] = v;
    } else if (idx < 4*WFSZ + 2048 + 1280 + 768 + 256) {
        int i5 = idx - 4*WFSZ - 2048 - 1280 - 768;
        int s = i5 / 32, lane = i5 % 32, g = lane >> 2;
        int j0 = s * 16;
        g_biasO[i5] = make_float2(h2o_b[j0 + g], h2o_b[j0 + g + 8]);
    }
}

// ===================== pre-kernel: gi0 via tensor cores + out4-low =====================
// grid = 512: (bg, t-quarter). 8 warps/block, each strides its own timesteps.
__global__ void __launch_bounds__(256)
pre_kernel(const int* __restrict__ il,
           const float* __restrict__ emb,
           float* __restrict__ out4)
{
    __shared__ uint32_t act[8][512];
    const int tid  = threadIdx.x;
    const int w    = tid >> 5;
    const int lane = tid & 31;
    const int g    = lane >> 2;
    const int tg   = lane & 3;
    const int bg   = blockIdx.x >> 2;
    const int tq   = blockIdx.x & 3;
    const int b0   = bg * 8;

    const uint4* wbase = g_Wf + 3 * WFSZ;
    uint32_t* aw = act[w];
    const int n = lane >> 2;          // row for gather (4 lanes share)

    for (int t = tq * 50 + w; t < tq * 50 + 50; t += 8) {
        int tok = il[(b0 + n) * T_ + t];
        const float4* erow = (const float4*)emb + (size_t)tok * 32;
        float4* o4 = (float4*)(out4 + ((size_t)(b0 + n) * T_ + t) * 256);
#pragma unroll
        for (int i = 0; i < 8; i++) {
            int c = (lane & 3) + 4 * i;        // float4 chunk 0..31
            float4 v = __ldg(erow + c);
            o4[c] = v;
            aw[16 * c + n]     = h2pk(v.x, v.y);
            aw[16 * c + 8 + n] = h2pk(v.z, v.w);
        }
        __syncwarp();

        uint32_t bf[16];
#pragma unroll
        for (int ks = 0; ks < 8; ks++) {
            bf[2*ks]   = aw[(ks * 8 + tg) * 8 + g];
            bf[2*ks+1] = aw[(ks * 8 + tg + 4) * 8 + g];
        }

        ull* gout = g_gi0h + ((size_t)bg * 200 + t) * 24 * 32 + lane;
#pragma unroll 2
        for (int tt = 0; tt < 24; tt++) {
            float2 bv = g_biasP[tt * 32 + lane];
            float d[4] = {bv.x, bv.x, bv.y, bv.y};
            chain8(d, wbase + tt * 256 + lane, bf);
            uint32_t lo = h2pk(d[0], d[1]);
            uint32_t hi = h2pk(d[2], d[3]);
            gout[tt * 32] = (ull)lo | ((ull)hi << 32);
        }
        __syncwarp();
    }
}

// ===================== post-kernel: h2o via tensor cores =====================
__global__ void __launch_bounds__(256)
post_kernel(float* __restrict__ out1,
            float* __restrict__ out4)
{
    const int tid  = threadIdx.x;
    const int w    = tid >> 5;
    const int lane = tid & 31;
    const int g    = lane >> 2;
    const int tg   = lane & 3;
    const int bg   = blockIdx.x >> 2;
    const int tq   = blockIdx.x & 3;
    const int b0   = bg * 8;
    const int r0   = tg * 2;

    for (int t = tq * 50 + w; t < tq * 50 + 50; t += 8) {
        const uint32_t* hp = (const uint32_t*)g_h1h + ((size_t)bg * 200 + t) * 512;
        uint32_t bf[16];
#pragma unroll
        for (int ks = 0; ks < 8; ks++) {
            bf[2*ks]   = __ldg(hp + (ks * 8 + tg) * 8 + g);
            bf[2*ks+1] = __ldg(hp + (ks * 8 + tg + 4) * 8 + g);
        }
#pragma unroll
        for (int tt = 0; tt < 8; tt++) {
            float2 bv = g_biasO[tt * 32 + lane];
            float d[4] = {bv.x, bv.x, bv.y, bv.y};
            chain8(d, g_WoF + tt * 256 + lane, bf);
#pragma unroll
            for (int e = 0; e < 4; e++) {
                float o = tanh_fast(d[e]);
                int row = r0 + (e & 1);
                int col = tt * 16 + g + ((e >> 1) ? 8 : 0);
                size_t gb = (size_t)(b0 + row);
                out4[(gb * T_ + t) * 256 + 128 + col] = o;
                if (t < T_ - 1)
                    out1[(gb * (T_ - 1) + t) * 128 + col] = o;
            }
        }
    }
}

// ===================== recurrence loop: in-register pointwise, 2 barriers/step =====================
__global__ void __launch_bounds__(256, 1)
gru_loop(const float* __restrict__ mask)
{
    __shared__ uint32_t h0s[2][512], h1s[2][512], bbs[512];

    const int tid  = threadIdx.x;
    const int w    = tid >> 5;        // warp 0..7: owns hidden cols [16w,16w+16)
    const int lane = tid & 31;
    const int g    = lane >> 2;
    const int tg   = lane & 3;
    const int bg   = blockIdx.x;
    const int b0   = bg * 8;
    const int r0   = tg * 2;

    for (int i = tid; i < 512; i += 256) {
        h0s[0][i] = 0u; h0s[1][i] = 0u;
        h1s[0][i] = 0u; h1s[1][i] = 0u;
    }

    const uint4* W0r  = g_Wf + (0*24 +      w) * 256 + lane;
    const uint4* W0z  = g_Wf + (0*24 +  8 + w) * 256 + lane;
    const uint4* W0n  = g_Wf + (0*24 + 16 + w) * 256 + lane;
    const uint4* W1ir = g_Wf + (1*24 +      w) * 256 + lane;
    const uint4* W1iz = g_Wf + (1*24 +  8 + w) * 256 + lane;
    const uint4* W1in = g_Wf + (1*24 + 16 + w) * 256 + lane;
    const uint4* W1hr = g_Wf + (2*24 +      w) * 256 + lane;
    const uint4* W1hz = g_Wf + (2*24 +  8 + w) * 256 + lane;
    const uint4* W1hn = g_Wf + (2*24 + 16 + w) * 256 + lane;

    const float2 b0hn = g_biasf[( 0 + w) * 32 + lane];
    const float2 b1r  = g_biasf[( 8 + w) * 32 + lane];
    const float2 b1z  = g_biasf[(16 + w) * 32 + lane];
    const float2 b1n  = g_biasf[(24 + w) * 32 + lane];
    const float2 b1hn = g_biasf[(32 + w) * 32 + lane];

    const ull* gp = g_gi0h + (size_t)bg * 200 * 24 * 32 + lane;

    // prefetch t=0
    ull grh = __ldg(gp + (0*24 +      w) * 32);
    ull gzh = __ldg(gp + (0*24 +  8 + w) * 32);
    ull gnh = __ldg(gp + (0*24 + 16 + w) * 32);
    float mk0 = (__ldg(mask + (b0 + r0)     * T_) != 0.0f) ? 1.0f : 0.0f;
    float mk1 = (__ldg(mask + (b0 + r0 + 1) * T_) != 0.0f) ? 1.0f : 0.0f;

    float h0reg[4] = {0.f, 0.f, 0.f, 0.f};
    float h1reg[4] = {0.f, 0.f, 0.f, 0.f};

    const int c0 = 16 * w + g;
    const int hx0 = (c0 >> 1) * 16 + r0 * 2 + (c0 & 1);
    const int c1 = c0 + 8;
    const int hx2 = (c1 >> 1) * 16 + r0 * 2 + (c1 & 1);

    __half* gh1 = g_h1h + (size_t)bg * 200 * 1024;

    __syncthreads();

    for (int t = 0; t < T_; t++) {
        const int p = t & 1, q = p ^ 1;

        // ================= Phase 1: layer 0 =================
        uint32_t hb[16];
        {
            const uint32_t* a0 = h0s[p];
#pragma unroll
            for (int ks = 0; ks < 8; ks++) {
                hb[2*ks]   = a0[(ks * 8 + tg) * 8 + g];
                hb[2*ks+1] = a0[(ks * 8 + tg + 4) * 8 + g];
            }
        }
        float2 fr0 = pk2f((uint32_t)grh), fr1 = pk2f((uint32_t)(grh >> 32));
        float2 fz0 = pk2f((uint32_t)gzh), fz1 = pk2f((uint32_t)(gzh >> 32));
        float2 fn0 = pk2f((uint32_t)gnh), fn1 = pk2f((uint32_t)(gnh >> 32));
        float dr[4] = {fr0.x, fr0.y, fr1.x, fr1.y};
        float dz[4] = {fz0.x, fz0.y, fz1.x, fz1.y};
        float dn[4] = {fn0.x, fn0.y, fn1.x, fn1.y};
        float dhn[4] = {b0hn.x, b0hn.x, b0hn.y, b0hn.y};
        chain8(dr,  W0r, hb);
        chain8(dz,  W0z, hb);
        chain8(dhn, W0n, hb);

        // prefetch next step's gi0 + mask
        ull gr2 = 0, gz2 = 0, gn2 = 0;
        float mkA = 0.f, mkB = 0.f;
        if (t + 1 < T_) {
            gr2 = __ldg(gp + ((t+1)*24 +      w) * 32);
            gz2 = __ldg(gp + ((t+1)*24 +  8 + w) * 32);
            gn2 = __ldg(gp + ((t+1)*24 + 16 + w) * 32);
            mkA = (__ldg(mask + (b0 + r0)     * T_ + t + 1) != 0.0f) ? 1.0f : 0.0f;
            mkB = (__ldg(mask + (b0 + r0 + 1) * T_ + t + 1) != 0.0f) ? 1.0f : 0.0f;
        }

        // pointwise L0 (in registers) + stores
        {
            __half* BB = (__half*)bbs;
            __half* HN = (__half*)h0s[q];
#pragma unroll
            for (int e = 0; e < 4; e++) {
                float rv = sigmoid_fast(dr[e]);
                float zv = sigmoid_fast(dz[e]);
                float nv = tanh_fast(fmaf(rv, dhn[e], dn[e]));
                float h  = fmaf(zv, h0reg[e] - nv, nv);
                float mk = (e & 1) ? mk1 : mk0;
                float hm = h * mk;
                h0reg[e] = hm;
                int hidx = ((e >> 1) ? hx2 : hx0) + (e & 1) * 2;
                BB[hidx] = __float2half_rn(h);
                HN[hidx] = __float2half_rn(hm);
            }
        }
        __syncthreads();                                   // B1

        // ================= Phase 2: layer 1 =================
        uint32_t bf[16], hf[16];
        {
            const uint32_t* ab = bbs;
            const uint32_t* a1 = h1s[p];
#pragma unroll
            for (int ks = 0; ks < 8; ks++) {
                bf[2*ks]   = ab[(ks * 8 + tg) * 8 + g];
                bf[2*ks+1] = ab[(ks * 8 + tg + 4) * 8 + g];
                hf[2*ks]   = a1[(ks * 8 + tg) * 8 + g];
                hf[2*ks+1] = a1[(ks * 8 + tg + 4) * 8 + g];
            }
        }
        float er[4]  = {b1r.x,  b1r.x,  b1r.y,  b1r.y};
        float ez[4]  = {b1z.x,  b1z.x,  b1z.y,  b1z.y};
        float en[4]  = {b1n.x,  b1n.x,  b1n.y,  b1n.y};
        float ehn[4] = {b1hn.x, b1hn.x, b1hn.y, b1hn.y};
        chain8(er,  W1ir, bf);
        chain8(er,  W1hr, hf);
        chain8(ez,  W1iz, bf);
        chain8(ez,  W1hz, hf);
        chain8(en,  W1in, bf);
        chain8(ehn, W1hn, hf);

        // pointwise L1 + stores (h1 emitted fp16 B-frag-packed)
        {
            __half* HN = (__half*)h1s[q];
            __half* GH = gh1 + (size_t)t * 1024;
#pragma unroll
            for (int e = 0; e < 4; e++) {
                float rv = sigmoid_fast(er[e]);
                float zv = sigmoid_fast(ez[e]);
                float nv = tanh_fast(fmaf(rv, ehn[e], en[e]));
                float h  = fmaf(zv, h1reg[e] - nv, nv);
                float mk = (e & 1) ? mk1 : mk0;
                float hm = h * mk;
                h1reg[e] = hm;
                int hidx = ((e >> 1) ? hx2 : hx0) + (e & 1) * 2;
                __half hh = __float2half_rn(h);
                GH[hidx] = hh;
                HN[hidx] = __float2half_rn(hm);
            }
        }
        grh = gr2; gzh = gz2; gnh = gn2;
        mk0 = mkA; mk1 = mkB;
        __syncthreads();                                   // B2
    }
}

// out2/out3 gathers
__global__ void gather_kernel(const int* __restrict__ il,
                              const int* __restrict__ neg,
                              const float4* __restrict__ emb4,
                              float4* __restrict__ out2,
                              float4* __restrict__ out3)
{
    int idx = blockIdx.x * blockDim.x + threadIdx.x;
    const int n4 = B_ * (T_ - 1) * (H_ / 4);
    if (idx >= n4) return;
    int k4 = idx & 31;
    int bt = idx >> 5;
    int b  = bt / (T_ - 1);
    int t  = bt - b * (T_ - 1);
    int p  = il [b * T_ + t + 1];
    int qd = neg[b * T_ + t];
    out2[idx] = __ldg(emb4 + (size_t)p  * 32 + k4);
    out3[idx] = __ldg(emb4 + (size_t)qd * 32 + k4);
}

extern "C" void kernel_launch(void* const* d_in, const int* in_sizes, int n_in,
                              void* d_out, int out_size)
{
    const int*   il    = (const int*)  d_in[0];
    const float* mask  = (const float*)d_in[1];
    const int*   neg   = (const int*)  d_in[2];
    const float* emb   = (const float*)d_in[3];
    const float* Wih   = (const float*)d_in[4];
    const float* Whh   = (const float*)d_in[5];
    const float* bih   = (const float*)d_in[6];
    const float* bhh   = (const float*)d_in[7];
    const float* h2o_w = (const float*)d_in[8];
    const float* h2o_b = (const float*)d_in[9];

    float* out  = (float*)d_out;
    float* out1 = out;
    float* out2 = out1 + (size_t)B_ * (T_ - 1) * H_;
    float* out3 = out2 + (size_t)B_ * (T_ - 1) * H_;
    float* out4 = out3 + (size_t)B_ * (T_ - 1) * H_;

    const int nprep = 4*WFSZ + 2048 + 1280 + 768 + 256;
    prep_kernel<<<(nprep + 255) / 256, 256>>>(Wih, Whh, bih, bhh, h2o_w, h2o_b);

    const int n4 = B_ * (T_ - 1) * (H_ / 4);
    gather_kernel<<<(n4 + 255) / 256, 256>>>(il, neg, (const float4*)emb,
                                             (float4*)out2, (float4*)out3);

    pre_kernel<<<512, 256>>>(il, emb, out4);

    gru_loop<<<NCTA, 256>>>(mask);

    post_kernel<<<512, 256>>>(out1, out4);
}